// round 1
// baseline (speedup 1.0000x reference)
#include <cuda_runtime.h>
#include <cuda_bf16.h>
#include <math_constants.h>

// ---------------------------------------------------------------------------
// DTransformerLayer: B=4, S=1024, D=1024, H=16, DK=64
// out = LayerNorm(query + (Attn(qWq, kWq, vWv) @ Wo + bo)) with strictly
// causal mask + additive state_weight[h, i, j], softmax over j, gamma/beta LN.
// Round 0: fp32 SIMT baseline. GEMMs 128x128x8 register-blocked; attention
// fused flash-style 64x64 tiles; residual+LN fused.
// ---------------------------------------------------------------------------

#define Bsz 4
#define Ssz 1024
#define Dsz 1024
#define Hsz 16
#define DKsz 64

// Scratch (device-global: no allocation allowed)
__device__ float g_Q[(size_t)Bsz * Ssz * Dsz];
__device__ float g_K[(size_t)Bsz * Ssz * Dsz];
__device__ float g_V[(size_t)Bsz * Ssz * Dsz];
__device__ float g_C[(size_t)Bsz * Ssz * Dsz];   // attention context
__device__ float g_O[(size_t)Bsz * Ssz * Dsz];   // output projection

// ---------------------------------------------------------------------------
// SGEMM with bias: C[M,N] = A[M,K] @ W[K,N] + bias[N]
// BM=BN=128, BK=8, 256 threads, 8x8 per-thread tile.
// ---------------------------------------------------------------------------
__global__ __launch_bounds__(256) void sgemm_bias(
    const float* __restrict__ A, const float* __restrict__ W,
    const float* __restrict__ bias, float* __restrict__ C,
    int M, int N, int K)
{
    __shared__ float As[8][128];
    __shared__ float Bs[8][128];

    const int bm = blockIdx.y * 128;
    const int bn = blockIdx.x * 128;
    const int tid = threadIdx.x;

    const int tr = (tid / 16) * 8;   // thread row within tile
    const int tc = (tid % 16) * 8;   // thread col within tile

    const int arow = tid >> 1;          // 0..127
    const int acol = (tid & 1) * 4;     // 0 or 4
    const int brow = tid >> 5;          // 0..7
    const int bcol = (tid & 31) * 4;    // 0..124

    float acc[8][8];
#pragma unroll
    for (int i = 0; i < 8; i++)
#pragma unroll
        for (int j = 0; j < 8; j++) acc[i][j] = 0.f;

    const float* Aptr = A + (size_t)(bm + arow) * K + acol;
    const float* Wptr = W + (size_t)brow * N + bn + bcol;

    for (int k0 = 0; k0 < K; k0 += 8) {
        float4 a4 = *(const float4*)(Aptr + k0);
        As[acol + 0][arow] = a4.x;
        As[acol + 1][arow] = a4.y;
        As[acol + 2][arow] = a4.z;
        As[acol + 3][arow] = a4.w;
        *(float4*)&Bs[brow][bcol] = *(const float4*)(Wptr + (size_t)k0 * N);
        __syncthreads();

#pragma unroll
        for (int kk = 0; kk < 8; kk++) {
            float a[8], b[8];
            *(float4*)&a[0] = *(float4*)&As[kk][tr];
            *(float4*)&a[4] = *(float4*)&As[kk][tr + 4];
            *(float4*)&b[0] = *(float4*)&Bs[kk][tc];
            *(float4*)&b[4] = *(float4*)&Bs[kk][tc + 4];
#pragma unroll
            for (int i = 0; i < 8; i++)
#pragma unroll
                for (int j = 0; j < 8; j++)
                    acc[i][j] += a[i] * b[j];
        }
        __syncthreads();
    }

#pragma unroll
    for (int i = 0; i < 8; i++) {
        float* crow = C + (size_t)(bm + tr + i) * N + bn + tc;
#pragma unroll
        for (int j = 0; j < 8; j += 4) {
            float4 o;
            o.x = acc[i][j + 0] + bias[bn + tc + j + 0];
            o.y = acc[i][j + 1] + bias[bn + tc + j + 1];
            o.z = acc[i][j + 2] + bias[bn + tc + j + 2];
            o.w = acc[i][j + 3] + bias[bn + tc + j + 3];
            *(float4*)(crow + j) = o;
        }
    }
}

// ---------------------------------------------------------------------------
// Fused causal attention with state_weight bias, flash-style online softmax.
// Tiles: 64 query rows x 64 key cols per block; 256 threads.
// Thread (i = tid/4, sub = tid%4) owns score cols [sub*16, sub*16+16) and
// output dims [sub*16, sub*16+16) of row i.
// ---------------------------------------------------------------------------
__global__ __launch_bounds__(256) void flash_attn(
    const float* __restrict__ Qg, const float* __restrict__ Kg,
    const float* __restrict__ Vg, const float* __restrict__ SW,
    float* __restrict__ ctx)
{
    __shared__ float Qts[64][64];   // Q transposed: [k][i]
    __shared__ float KPs[64][64];   // K transposed [k][j]; reused as P^T [j][i]
    __shared__ float Vs[64][64];    // V natural:   [j][d]

    const int qt = blockIdx.x;      // 0..15
    const int h  = blockIdx.y;      // 0..15
    const int b  = blockIdx.z;      // 0..3
    const int tid = threadIdx.x;
    const int i   = tid >> 2;       // row within tile 0..63
    const int sub = tid & 3;        // 0..3
    const int j0  = sub * 16;
    const int q0  = qt * 64;
    const int gi  = q0 + i;         // global query row
    const float scale = 0.125f;     // 1/sqrt(64)

    // Load Q tile transposed
    {
        const int r  = tid >> 2;
        const int c0 = (tid & 3) * 16;
        const float* src = Qg + ((size_t)b * Ssz + q0 + r) * Dsz + h * DKsz + c0;
#pragma unroll
        for (int u = 0; u < 16; u += 4) {
            float4 v = *(const float4*)(src + u);
            Qts[c0 + u + 0][r] = v.x;
            Qts[c0 + u + 1][r] = v.y;
            Qts[c0 + u + 2][r] = v.z;
            Qts[c0 + u + 3][r] = v.w;
        }
    }

    float m = -CUDART_INF_F, l = 0.f;
    float oacc[16];
#pragma unroll
    for (int u = 0; u < 16; u++) oacc[u] = 0.f;

    for (int kt = 0; kt <= qt; kt++) {
        const int k0 = kt * 64;
        __syncthreads();  // prior P^T consumption done before overwriting KPs

        // Load K tile transposed + V tile natural
        {
            const int r  = tid >> 2;
            const int c0 = (tid & 3) * 16;
            const float* ksrc = Kg + ((size_t)b * Ssz + k0 + r) * Dsz + h * DKsz + c0;
            const float* vsrc = Vg + ((size_t)b * Ssz + k0 + r) * Dsz + h * DKsz + c0;
#pragma unroll
            for (int u = 0; u < 16; u += 4) {
                float4 kv = *(const float4*)(ksrc + u);
                KPs[c0 + u + 0][r] = kv.x;
                KPs[c0 + u + 1][r] = kv.y;
                KPs[c0 + u + 2][r] = kv.z;
                KPs[c0 + u + 3][r] = kv.w;
                *(float4*)&Vs[r][c0 + u] = *(const float4*)(vsrc + u);
            }
        }
        __syncthreads();

        // S = Q K^T for (row i, cols j0..j0+15)
        float s[16];
#pragma unroll
        for (int u = 0; u < 16; u++) s[u] = 0.f;
#pragma unroll 8
        for (int kk = 0; kk < 64; kk++) {
            float qv = Qts[kk][i];
#pragma unroll
            for (int u = 0; u < 16; u++)
                s[u] += qv * KPs[kk][j0 + u];
        }

        // scale + state_weight + strict causal mask, local max
        const float* swrow = SW + ((size_t)h * Ssz + gi) * Ssz + k0 + j0;
        float tmax = -CUDART_INF_F;
#pragma unroll
        for (int u = 0; u < 16; u++) {
            int gj = k0 + j0 + u;
            if (gj < gi) {
                s[u] = s[u] * scale + swrow[u];
                tmax = fmaxf(tmax, s[u]);
            } else {
                s[u] = -CUDART_INF_F;
            }
        }

        // Row max across the 4 threads of this row
        tmax = fmaxf(tmax, __shfl_xor_sync(0xffffffffu, tmax, 1));
        tmax = fmaxf(tmax, __shfl_xor_sync(0xffffffffu, tmax, 2));
        float mnew = fmaxf(m, tmax);
        float corr = (mnew == -CUDART_INF_F) ? 0.f : __expf(m - mnew);

        float p[16];
        float psum = 0.f;
#pragma unroll
        for (int u = 0; u < 16; u++) {
            p[u] = (s[u] == -CUDART_INF_F) ? 0.f : __expf(s[u] - mnew);
            psum += p[u];
        }
        psum += __shfl_xor_sync(0xffffffffu, psum, 1);
        psum += __shfl_xor_sync(0xffffffffu, psum, 2);
        l = l * corr + psum;
        m = mnew;
#pragma unroll
        for (int u = 0; u < 16; u++) oacc[u] *= corr;

        __syncthreads();
        // Store P transposed: KPs[j][i]
#pragma unroll
        for (int u = 0; u < 16; u++)
            KPs[j0 + u][i] = p[u];
        __syncthreads();

        // O += P V  (dims d0..d0+15 of row i)
        const int d0 = sub * 16;
#pragma unroll 8
        for (int j = 0; j < 64; j++) {
            float pv = KPs[j][i];
#pragma unroll
            for (int u = 0; u < 16; u++)
                oacc[u] += pv * Vs[j][d0 + u];
        }
    }

    const float inv = (l > 0.f) ? (1.f / l) : 0.f;
    float* dst = ctx + ((size_t)b * Ssz + gi) * Dsz + h * DKsz + sub * 16;
#pragma unroll
    for (int u = 0; u < 16; u += 4) {
        float4 o;
        o.x = oacc[u + 0] * inv;
        o.y = oacc[u + 1] * inv;
        o.z = oacc[u + 2] * inv;
        o.w = oacc[u + 3] * inv;
        *(float4*)(dst + u) = o;
    }
}

// ---------------------------------------------------------------------------
// Residual + LayerNorm: out = LN(query + proj) * gamma + beta, per row of D.
// One block (256 threads) per row; each thread holds 4 elements.
// ---------------------------------------------------------------------------
__global__ __launch_bounds__(256) void residual_ln(
    const float* __restrict__ x0, const float* __restrict__ y,
    const float* __restrict__ gamma, const float* __restrict__ beta,
    float* __restrict__ out)
{
    const int row = blockIdx.x;
    const float* a = x0 + (size_t)row * Dsz;
    const float* c = y  + (size_t)row * Dsz;
    const int tid = threadIdx.x;

    float v[4];
    float sum = 0.f, sumsq = 0.f;
#pragma unroll
    for (int u = 0; u < 4; u++) {
        int idx = tid + u * 256;
        float t = a[idx] + c[idx];
        v[u] = t;
        sum += t;
        sumsq += t * t;
    }
#pragma unroll
    for (int o = 16; o; o >>= 1) {
        sum   += __shfl_xor_sync(0xffffffffu, sum, o);
        sumsq += __shfl_xor_sync(0xffffffffu, sumsq, o);
    }
    __shared__ float s1[8], s2[8];
    if ((tid & 31) == 0) { s1[tid >> 5] = sum; s2[tid >> 5] = sumsq; }
    __syncthreads();
    if (tid < 32) {
        sum   = (tid < 8) ? s1[tid] : 0.f;
        sumsq = (tid < 8) ? s2[tid] : 0.f;
#pragma unroll
        for (int o = 4; o; o >>= 1) {
            sum   += __shfl_xor_sync(0xffffffffu, sum, o);
            sumsq += __shfl_xor_sync(0xffffffffu, sumsq, o);
        }
        if (tid == 0) { s1[0] = sum; s2[0] = sumsq; }
    }
    __syncthreads();
    const float mu   = s1[0] * (1.f / Dsz);
    const float var  = s2[0] * (1.f / Dsz) - mu * mu;
    const float rstd = rsqrtf(var + 1e-5f);

    float* o = out + (size_t)row * Dsz;
#pragma unroll
    for (int u = 0; u < 4; u++) {
        int idx = tid + u * 256;
        o[idx] = (v[u] - mu) * rstd * gamma[idx] + beta[idx];
    }
}

// ---------------------------------------------------------------------------
extern "C" void kernel_launch(void* const* d_in, const int* in_sizes, int n_in,
                              void* d_out, int out_size)
{
    const float* query  = (const float*)d_in[0];
    const float* key    = (const float*)d_in[1];
    const float* values = (const float*)d_in[2];
    // d_in[3] = lens (unused by reference)
    const float* sw     = (const float*)d_in[4];
    const float* Wq     = (const float*)d_in[5];
    const float* bq     = (const float*)d_in[6];
    const float* Wv     = (const float*)d_in[7];
    const float* bv     = (const float*)d_in[8];
    const float* Wo     = (const float*)d_in[9];
    const float* bo     = (const float*)d_in[10];
    const float* gamma  = (const float*)d_in[11];
    const float* beta   = (const float*)d_in[12];
    float* out = (float*)d_out;

    float *Qp, *Kp, *Vp, *Cp, *Op;
    cudaGetSymbolAddress((void**)&Qp, g_Q);
    cudaGetSymbolAddress((void**)&Kp, g_K);
    cudaGetSymbolAddress((void**)&Vp, g_V);
    cudaGetSymbolAddress((void**)&Cp, g_C);
    cudaGetSymbolAddress((void**)&Op, g_O);

    const int M = Bsz * Ssz;  // 4096
    dim3 gg(Dsz / 128, M / 128);

    sgemm_bias<<<gg, 256>>>(query,  Wq, bq, Qp, M, Dsz, Dsz);
    sgemm_bias<<<gg, 256>>>(key,    Wq, bq, Kp, M, Dsz, Dsz);
    sgemm_bias<<<gg, 256>>>(values, Wv, bv, Vp, M, Dsz, Dsz);

    flash_attn<<<dim3(Ssz / 64, Hsz, Bsz), 256>>>(Qp, Kp, Vp, sw, Cp);

    sgemm_bias<<<gg, 256>>>(Cp, Wo, bo, Op, M, Dsz, Dsz);

    residual_ln<<<M, 256>>>(query, Op, gamma, beta, out);
}

// round 3
// speedup vs baseline: 2.6884x; 2.6884x over previous
#include <cuda_runtime.h>
#include <cuda_bf16.h>
#include <math_constants.h>
#include <cstdint>

// ---------------------------------------------------------------------------
// DTransformerLayer: B=4, S=1024, D=1024, H=16, DK=64
// R2: tensor-core GEMMs (bf16x3 split), fp32 SIMT flash attention with
// 48KB static smem (no cudaFuncSetAttribute, no dynamic smem), fused
// residual+LN. Attention epilogue writes bf16 hi/lo ctx directly.
// ---------------------------------------------------------------------------

#define Bsz 4
#define Ssz 1024
#define Dsz 1024
#define Hsz 16
#define DKsz 64
#define Msz (Bsz * Ssz)            // 4096
#define NELEM ((size_t)Msz * Dsz)  // 4M
#define WELEM ((size_t)Dsz * Dsz)  // 1M

// fp32 scratch
__device__ float g_Q[NELEM];
__device__ float g_K[NELEM];
__device__ float g_V[NELEM];
__device__ float g_O[NELEM];

// bf16 hi/lo split scratch (activations)
__device__ __nv_bfloat16 g_qh[NELEM], g_ql[NELEM];
__device__ __nv_bfloat16 g_kh[NELEM], g_kl[NELEM];
__device__ __nv_bfloat16 g_vh[NELEM], g_vl[NELEM];
__device__ __nv_bfloat16 g_ch[NELEM], g_cl[NELEM];
// weights, transposed to [N][K]
__device__ __nv_bfloat16 g_wqh[WELEM], g_wql[WELEM];
__device__ __nv_bfloat16 g_wvh[WELEM], g_wvl[WELEM];
__device__ __nv_bfloat16 g_woh[WELEM], g_wol[WELEM];

// ---------------------------------------------------------------------------
// fp32 -> (hi, lo) bf16 split, elementwise.
// ---------------------------------------------------------------------------
__global__ __launch_bounds__(256) void split_f32(
    const float* __restrict__ x, __nv_bfloat16* __restrict__ hi,
    __nv_bfloat16* __restrict__ lo)
{
    const size_t i = ((size_t)blockIdx.x * 256 + threadIdx.x) * 4;
    float4 v = *(const float4*)(x + i);
    float vv[4] = {v.x, v.y, v.z, v.w};
    __nv_bfloat16 h[4], l[4];
#pragma unroll
    for (int u = 0; u < 4; u++) {
        h[u] = __float2bfloat16_rn(vv[u]);
        l[u] = __float2bfloat16_rn(vv[u] - __bfloat162float(h[u]));
    }
    *(uint2*)(hi + i) = *(uint2*)h;
    *(uint2*)(lo + i) = *(uint2*)l;
}

// fp32 [K][N] -> transposed bf16 hi/lo [N][K] (weights; K = N = 1024)
__global__ __launch_bounds__(256) void split_t_f32(
    const float* __restrict__ w, __nv_bfloat16* __restrict__ hi,
    __nv_bfloat16* __restrict__ lo)
{
    const int idx = blockIdx.x * 256 + threadIdx.x;
    const int k = idx >> 10, n = idx & 1023;
    float v = w[idx];
    __nv_bfloat16 h = __float2bfloat16_rn(v);
    __nv_bfloat16 l = __float2bfloat16_rn(v - __bfloat162float(h));
    hi[n * 1024 + k] = h;
    lo[n * 1024 + k] = l;
}

// ---------------------------------------------------------------------------
// bf16x3 tensor-core GEMM: C[M,N] = Ahl[M,K] @ Bhl[N,K]^T + bias[N]
// BM=BN=128, BK=32; 8 warps as 4(m) x 2(n); warp tile 32x64 via m16n8k16.
// ---------------------------------------------------------------------------
#define LDSTR 40   // smem row stride in bf16

#define MMA16816(d, a, b0, b1)                                              \
    asm volatile(                                                           \
        "mma.sync.aligned.m16n8k16.row.col.f32.bf16.bf16.f32 "              \
        "{%0,%1,%2,%3},{%4,%5,%6,%7},{%8,%9},{%0,%1,%2,%3};"                \
        : "+f"(d[0]), "+f"(d[1]), "+f"(d[2]), "+f"(d[3])                    \
        : "r"(a[0]), "r"(a[1]), "r"(a[2]), "r"(a[3]), "r"(b0), "r"(b1))

__global__ __launch_bounds__(256, 2) void gemm_bf16x3(
    const __nv_bfloat16* __restrict__ Ah, const __nv_bfloat16* __restrict__ Al,
    const __nv_bfloat16* __restrict__ Bh, const __nv_bfloat16* __restrict__ Bl,
    const float* __restrict__ bias, float* __restrict__ C,
    int M, int N, int K)
{
    __shared__ __nv_bfloat16 sA[2][128 * LDSTR];
    __shared__ __nv_bfloat16 sB[2][128 * LDSTR];

    const int tid = threadIdx.x;
    const int bm = blockIdx.y * 128, bn = blockIdx.x * 128;
    const int w = tid >> 5, lane = tid & 31;
    const int g = lane >> 2, tg = lane & 3;
    const int wm = w >> 1, wn = w & 1;

    float fa[2][8][4];
#pragma unroll
    for (int i = 0; i < 2; i++)
#pragma unroll
        for (int j = 0; j < 8; j++)
#pragma unroll
            for (int u = 0; u < 4; u++) fa[i][j][u] = 0.f;

    for (int k0 = 0; k0 < K; k0 += 32) {
        __syncthreads();
#pragma unroll
        for (int s = 0; s < 4; s++) {
            const int seg = tid + s * 256;
            const int row = seg >> 3, col = (seg & 7) * 4;
            *(uint2*)&sA[0][row * LDSTR + col] =
                *(const uint2*)(Ah + (size_t)(bm + row) * K + k0 + col);
            *(uint2*)&sA[1][row * LDSTR + col] =
                *(const uint2*)(Al + (size_t)(bm + row) * K + k0 + col);
            *(uint2*)&sB[0][row * LDSTR + col] =
                *(const uint2*)(Bh + (size_t)(bn + row) * K + k0 + col);
            *(uint2*)&sB[1][row * LDSTR + col] =
                *(const uint2*)(Bl + (size_t)(bn + row) * K + k0 + col);
        }
        __syncthreads();

#pragma unroll
        for (int ks = 0; ks < 2; ks++) {
            const int kb = ks * 16 + tg * 2;
            uint32_t a[2][2][4];  // [hi/lo][mtile][frag]
#pragma unroll
            for (int i = 0; i < 2; i++) {
                const int r0 = wm * 32 + i * 16 + g;
#pragma unroll
                for (int hl = 0; hl < 2; hl++) {
                    a[hl][i][0] = *(const uint32_t*)&sA[hl][r0 * LDSTR + kb];
                    a[hl][i][1] = *(const uint32_t*)&sA[hl][(r0 + 8) * LDSTR + kb];
                    a[hl][i][2] = *(const uint32_t*)&sA[hl][r0 * LDSTR + kb + 8];
                    a[hl][i][3] = *(const uint32_t*)&sA[hl][(r0 + 8) * LDSTR + kb + 8];
                }
            }
#pragma unroll
            for (int j = 0; j < 8; j++) {
                const int n0 = wn * 64 + j * 8 + g;
                const uint32_t bh0 = *(const uint32_t*)&sB[0][n0 * LDSTR + kb];
                const uint32_t bh1 = *(const uint32_t*)&sB[0][n0 * LDSTR + kb + 8];
                const uint32_t bl0 = *(const uint32_t*)&sB[1][n0 * LDSTR + kb];
                const uint32_t bl1 = *(const uint32_t*)&sB[1][n0 * LDSTR + kb + 8];
#pragma unroll
                for (int i = 0; i < 2; i++) {
                    MMA16816(fa[i][j], a[0][i], bh0, bh1);
                    MMA16816(fa[i][j], a[1][i], bh0, bh1);
                    MMA16816(fa[i][j], a[0][i], bl0, bl1);
                }
            }
        }
    }

#pragma unroll
    for (int i = 0; i < 2; i++) {
        const int row = bm + wm * 32 + i * 16 + g;
#pragma unroll
        for (int j = 0; j < 8; j++) {
            const int col = bn + wn * 64 + j * 8 + tg * 2;
            const float b0 = bias[col], b1 = bias[col + 1];
            float2 v0 = {fa[i][j][0] + b0, fa[i][j][1] + b1};
            float2 v1 = {fa[i][j][2] + b0, fa[i][j][3] + b1};
            *(float2*)&C[(size_t)row * N + col] = v0;
            *(float2*)&C[(size_t)(row + 8) * N + col] = v1;
        }
    }
}

// ---------------------------------------------------------------------------
// Fused causal attention, fp32, flash-style. 64x64 tiles, 256 threads as
// 16(col threads) x 16(row groups); 4x4 register tile per thread.
// 48KB static smem exactly: Q^T, K^T (reused for P), V.
// Epilogue writes bf16 hi/lo context directly.
// ---------------------------------------------------------------------------
__global__ __launch_bounds__(256) void flash_attn2(
    const float* __restrict__ Qg, const float* __restrict__ Kg,
    const float* __restrict__ Vg, const float* __restrict__ SW,
    __nv_bfloat16* __restrict__ ctx_h, __nv_bfloat16* __restrict__ ctx_l)
{
    __shared__ float Qts[64 * 64];   // Q^T [k][i]
    __shared__ float KPs[64 * 64];   // K^T [k][j]; reused as P [i][j]
    __shared__ float Vss[64 * 64];   // V   [j][d]

    const int qt = blockIdx.x, h = blockIdx.y, b = blockIdx.z;
    const int tid = threadIdx.x;
    const int ct = tid & 15, rt = tid >> 4;
    const int r0 = rt * 4, c0 = ct * 4;
    const int q0 = qt * 64;
    const float scale = 0.125f;

    // Load Q tile transposed
    {
        const int r = tid >> 2, cc = (tid & 3) * 16;
        const float* src = Qg + ((size_t)b * Ssz + q0 + r) * Dsz + h * DKsz + cc;
#pragma unroll
        for (int u = 0; u < 16; u += 4) {
            float4 v = *(const float4*)(src + u);
            Qts[(cc + u + 0) * 64 + r] = v.x;
            Qts[(cc + u + 1) * 64 + r] = v.y;
            Qts[(cc + u + 2) * 64 + r] = v.z;
            Qts[(cc + u + 3) * 64 + r] = v.w;
        }
    }

    float m[4], l[4], o[4][4];
#pragma unroll
    for (int r = 0; r < 4; r++) {
        m[r] = -CUDART_INF_F;
        l[r] = 0.f;
#pragma unroll
        for (int c = 0; c < 4; c++) o[r][c] = 0.f;
    }

    for (int kt = 0; kt <= qt; kt++) {
        const int k0 = kt * 64;
        __syncthreads();  // previous PV reads done; Q store visible (1st iter)
        // Load K^T and V
        {
            const int r = tid >> 2, cc = (tid & 3) * 16;
            const float* ks = Kg + ((size_t)b * Ssz + k0 + r) * Dsz + h * DKsz + cc;
            const float* vs = Vg + ((size_t)b * Ssz + k0 + r) * Dsz + h * DKsz + cc;
#pragma unroll
            for (int u = 0; u < 16; u += 4) {
                float4 kv = *(const float4*)(ks + u);
                KPs[(cc + u + 0) * 64 + r] = kv.x;
                KPs[(cc + u + 1) * 64 + r] = kv.y;
                KPs[(cc + u + 2) * 64 + r] = kv.z;
                KPs[(cc + u + 3) * 64 + r] = kv.w;
                *(float4*)&Vss[r * 64 + cc + u] = *(const float4*)(vs + u);
            }
        }
        __syncthreads();

        // S = Q K^T (4x4 per thread)
        float s[4][4];
#pragma unroll
        for (int r = 0; r < 4; r++)
#pragma unroll
            for (int c = 0; c < 4; c++) s[r][c] = 0.f;
#pragma unroll 8
        for (int kk = 0; kk < 64; kk++) {
            float a[4], bb[4];
            *(float4*)a  = *(const float4*)&Qts[kk * 64 + r0];
            *(float4*)bb = *(const float4*)&KPs[kk * 64 + c0];
#pragma unroll
            for (int r = 0; r < 4; r++)
#pragma unroll
                for (int c = 0; c < 4; c++) s[r][c] += a[r] * bb[c];
        }

        // scale + state_weight (+ strict causal mask on diagonal tile)
        if (kt == qt) {
#pragma unroll
            for (int r = 0; r < 4; r++) {
                const int gi = q0 + r0 + r;
                const float* swp = SW + ((size_t)h * Ssz + gi) * Ssz + k0 + c0;
                float4 wv = *(const float4*)swp;
                float wa[4] = {wv.x, wv.y, wv.z, wv.w};
#pragma unroll
                for (int c = 0; c < 4; c++) {
                    const int gj = k0 + c0 + c;
                    s[r][c] = (gj < gi) ? s[r][c] * scale + wa[c] : -CUDART_INF_F;
                }
            }
        } else {
#pragma unroll
            for (int r = 0; r < 4; r++) {
                const int gi = q0 + r0 + r;
                const float* swp = SW + ((size_t)h * Ssz + gi) * Ssz + k0 + c0;
                float4 wv = *(const float4*)swp;
                s[r][0] = s[r][0] * scale + wv.x;
                s[r][1] = s[r][1] * scale + wv.y;
                s[r][2] = s[r][2] * scale + wv.z;
                s[r][3] = s[r][3] * scale + wv.w;
            }
        }

        // Row max across 16 col-threads (lanes of same row group)
        float rm[4];
#pragma unroll
        for (int r = 0; r < 4; r++)
            rm[r] = fmaxf(fmaxf(s[r][0], s[r][1]), fmaxf(s[r][2], s[r][3]));
#pragma unroll
        for (int msk = 1; msk < 16; msk <<= 1)
#pragma unroll
            for (int r = 0; r < 4; r++)
                rm[r] = fmaxf(rm[r], __shfl_xor_sync(0xffffffffu, rm[r], msk));

        float corr[4];
#pragma unroll
        for (int r = 0; r < 4; r++) {
            const float mn = fmaxf(m[r], rm[r]);
            corr[r] = (mn == -CUDART_INF_F) ? 0.f : __expf(m[r] - mn);
            m[r] = mn;
        }

        // P = exp(S - m), row sums
        float rs[4];
#pragma unroll
        for (int r = 0; r < 4; r++) {
            rs[r] = 0.f;
#pragma unroll
            for (int c = 0; c < 4; c++) {
                float p = (s[r][c] == -CUDART_INF_F) ? 0.f : __expf(s[r][c] - m[r]);
                s[r][c] = p;
                rs[r] += p;
            }
        }
#pragma unroll
        for (int msk = 1; msk < 16; msk <<= 1)
#pragma unroll
            for (int r = 0; r < 4; r++)
                rs[r] += __shfl_xor_sync(0xffffffffu, rs[r], msk);
#pragma unroll
        for (int r = 0; r < 4; r++) {
            l[r] = l[r] * corr[r] + rs[r];
#pragma unroll
            for (int c = 0; c < 4; c++) o[r][c] *= corr[r];
        }

        // All warps done reading K^T -> safe to overwrite with P
        __syncthreads();
#pragma unroll
        for (int r = 0; r < 4; r++) {
            float4 pv = {s[r][0], s[r][1], s[r][2], s[r][3]};
            *(float4*)&KPs[(r0 + r) * 64 + c0] = pv;
        }
        __syncwarp();   // P rows of this row-group are warp-local

        // O += P V
#pragma unroll 8
        for (int j = 0; j < 64; j++) {
            float bb[4];
            *(float4*)bb = *(const float4*)&Vss[j * 64 + c0];
#pragma unroll
            for (int r = 0; r < 4; r++) {
                const float p = KPs[(r0 + r) * 64 + j];
#pragma unroll
                for (int c = 0; c < 4; c++) o[r][c] += p * bb[c];
            }
        }
    }

    // Epilogue: normalize + bf16 hi/lo split write
#pragma unroll
    for (int r = 0; r < 4; r++) {
        const float inv = (l[r] > 0.f) ? (1.f / l[r]) : 0.f;
        __nv_bfloat16 hh[4], ll[4];
#pragma unroll
        for (int c = 0; c < 4; c++) {
            float val = o[r][c] * inv;
            hh[c] = __float2bfloat16_rn(val);
            ll[c] = __float2bfloat16_rn(val - __bfloat162float(hh[c]));
        }
        const size_t idx = ((size_t)b * Ssz + q0 + r0 + r) * Dsz + h * DKsz + c0;
        *(uint2*)(ctx_h + idx) = *(uint2*)hh;
        *(uint2*)(ctx_l + idx) = *(uint2*)ll;
    }
}

// ---------------------------------------------------------------------------
// Residual + LayerNorm
// ---------------------------------------------------------------------------
__global__ __launch_bounds__(256) void residual_ln(
    const float* __restrict__ x0, const float* __restrict__ y,
    const float* __restrict__ gamma, const float* __restrict__ beta,
    float* __restrict__ out)
{
    const int row = blockIdx.x;
    const float* a = x0 + (size_t)row * Dsz;
    const float* c = y  + (size_t)row * Dsz;
    const int tid = threadIdx.x;

    float v[4];
    float sum = 0.f, sumsq = 0.f;
#pragma unroll
    for (int u = 0; u < 4; u++) {
        int idx = tid + u * 256;
        float t = a[idx] + c[idx];
        v[u] = t;
        sum += t;
        sumsq += t * t;
    }
#pragma unroll
    for (int off = 16; off; off >>= 1) {
        sum   += __shfl_xor_sync(0xffffffffu, sum, off);
        sumsq += __shfl_xor_sync(0xffffffffu, sumsq, off);
    }
    __shared__ float s1[8], s2[8];
    if ((tid & 31) == 0) { s1[tid >> 5] = sum; s2[tid >> 5] = sumsq; }
    __syncthreads();
    if (tid < 32) {
        sum   = (tid < 8) ? s1[tid] : 0.f;
        sumsq = (tid < 8) ? s2[tid] : 0.f;
#pragma unroll
        for (int off = 4; off; off >>= 1) {
            sum   += __shfl_xor_sync(0xffffffffu, sum, off);
            sumsq += __shfl_xor_sync(0xffffffffu, sumsq, off);
        }
        if (tid == 0) { s1[0] = sum; s2[0] = sumsq; }
    }
    __syncthreads();
    const float mu   = s1[0] * (1.f / Dsz);
    const float var  = s2[0] * (1.f / Dsz) - mu * mu;
    const float rstd = rsqrtf(var + 1e-5f);

    float* op = out + (size_t)row * Dsz;
#pragma unroll
    for (int u = 0; u < 4; u++) {
        int idx = tid + u * 256;
        op[idx] = (v[u] - mu) * rstd * gamma[idx] + beta[idx];
    }
}

// ---------------------------------------------------------------------------
extern "C" void kernel_launch(void* const* d_in, const int* in_sizes, int n_in,
                              void* d_out, int out_size)
{
    const float* query  = (const float*)d_in[0];
    const float* key    = (const float*)d_in[1];
    const float* values = (const float*)d_in[2];
    // d_in[3] = lens (unused by reference)
    const float* sw     = (const float*)d_in[4];
    const float* Wq     = (const float*)d_in[5];
    const float* bq     = (const float*)d_in[6];
    const float* Wv     = (const float*)d_in[7];
    const float* bv     = (const float*)d_in[8];
    const float* Wo     = (const float*)d_in[9];
    const float* bo     = (const float*)d_in[10];
    const float* gamma  = (const float*)d_in[11];
    const float* beta   = (const float*)d_in[12];
    float* out = (float*)d_out;

    float *Qp, *Kp, *Vp, *Op;
    cudaGetSymbolAddress((void**)&Qp, g_Q);
    cudaGetSymbolAddress((void**)&Kp, g_K);
    cudaGetSymbolAddress((void**)&Vp, g_V);
    cudaGetSymbolAddress((void**)&Op, g_O);

    __nv_bfloat16 *qh, *ql, *kh, *kl, *vh, *vl, *ch, *cl;
    __nv_bfloat16 *wqh, *wql, *wvh, *wvl, *woh, *wol;
    cudaGetSymbolAddress((void**)&qh, g_qh);  cudaGetSymbolAddress((void**)&ql, g_ql);
    cudaGetSymbolAddress((void**)&kh, g_kh);  cudaGetSymbolAddress((void**)&kl, g_kl);
    cudaGetSymbolAddress((void**)&vh, g_vh);  cudaGetSymbolAddress((void**)&vl, g_vl);
    cudaGetSymbolAddress((void**)&ch, g_ch);  cudaGetSymbolAddress((void**)&cl, g_cl);
    cudaGetSymbolAddress((void**)&wqh, g_wqh); cudaGetSymbolAddress((void**)&wql, g_wql);
    cudaGetSymbolAddress((void**)&wvh, g_wvh); cudaGetSymbolAddress((void**)&wvl, g_wvl);
    cudaGetSymbolAddress((void**)&woh, g_woh); cudaGetSymbolAddress((void**)&wol, g_wol);

    const int nblk = (int)(NELEM / 1024);  // 4096 blocks, 4 elems/thread
    split_f32<<<nblk, 256>>>(query,  qh, ql);
    split_f32<<<nblk, 256>>>(key,    kh, kl);
    split_f32<<<nblk, 256>>>(values, vh, vl);
    const int wblk = (int)(WELEM / 256);
    split_t_f32<<<wblk, 256>>>(Wq, wqh, wql);
    split_t_f32<<<wblk, 256>>>(Wv, wvh, wvl);
    split_t_f32<<<wblk, 256>>>(Wo, woh, wol);

    dim3 gg(Dsz / 128, Msz / 128);  // (8, 32)
    gemm_bf16x3<<<gg, 256>>>(qh, ql, wqh, wql, bq, Qp, Msz, Dsz, Dsz);
    gemm_bf16x3<<<gg, 256>>>(kh, kl, wqh, wql, bq, Kp, Msz, Dsz, Dsz);
    gemm_bf16x3<<<gg, 256>>>(vh, vl, wvh, wvl, bv, Vp, Msz, Dsz, Dsz);

    flash_attn2<<<dim3(Ssz / 64, Hsz, Bsz), 256>>>(Qp, Kp, Vp, sw, ch, cl);

    gemm_bf16x3<<<gg, 256>>>(ch, cl, woh, wol, bo, Op, Msz, Dsz, Dsz);

    residual_ln<<<Msz, 256>>>(query, Op, gamma, beta, out);
}

// round 4
// speedup vs baseline: 3.7335x; 1.3888x over previous
#include <cuda_runtime.h>
#include <cuda_bf16.h>
#include <math_constants.h>
#include <cstdint>

// ---------------------------------------------------------------------------
// DTransformerLayer: B=4, S=1024, D=1024, H=16, DK=64
// R4: everything heavy on tensor cores via bf16 hi/lo 3-pass (Markidis):
//  - Q/K/V GEMMs emit bf16 hi/lo directly
//  - flash attention: S and P*V on mma.m16n8k16, register softmax
//  - tiled transposes for weights and V^T
// ---------------------------------------------------------------------------

#define Bsz 4
#define Ssz 1024
#define Dsz 1024
#define Hsz 16
#define DKsz 64
#define Msz (Bsz * Ssz)            // 4096
#define NELEM ((size_t)Msz * Dsz)  // 4M
#define WELEM ((size_t)Dsz * Dsz)  // 1M

// input activation splits
__device__ __nv_bfloat16 g_xqh[NELEM], g_xql[NELEM];
__device__ __nv_bfloat16 g_xkh[NELEM], g_xkl[NELEM];
__device__ __nv_bfloat16 g_xvh[NELEM], g_xvl[NELEM];
// projection outputs (bf16 hi/lo)
__device__ __nv_bfloat16 g_Qh[NELEM], g_Ql[NELEM];
__device__ __nv_bfloat16 g_Kh[NELEM], g_Kl[NELEM];
__device__ __nv_bfloat16 g_Vh[NELEM], g_Vl[NELEM];
// V transposed per (b,h): [ (b*H+h)*DK + d ][ s ]
__device__ __nv_bfloat16 g_vth[NELEM], g_vtl[NELEM];
// attention context (bf16 hi/lo)
__device__ __nv_bfloat16 g_ch[NELEM], g_cl[NELEM];
// weights transposed [N][K]
__device__ __nv_bfloat16 g_wqh[WELEM], g_wql[WELEM];
__device__ __nv_bfloat16 g_wvh[WELEM], g_wvl[WELEM];
__device__ __nv_bfloat16 g_woh[WELEM], g_wol[WELEM];
// O projection fp32
__device__ float g_O[NELEM];

__device__ __forceinline__ uint32_t pack2bf(float a, float b) {
    __nv_bfloat162 t = __floats2bfloat162_rn(a, b);  // .x = a (low), .y = b (high)
    return *(uint32_t*)&t;
}

// ---------------------------------------------------------------------------
// fp32 -> (hi, lo) bf16 split, elementwise.
// ---------------------------------------------------------------------------
__global__ __launch_bounds__(256) void split_f32(
    const float* __restrict__ x, __nv_bfloat16* __restrict__ hi,
    __nv_bfloat16* __restrict__ lo)
{
    const size_t i = ((size_t)blockIdx.x * 256 + threadIdx.x) * 4;
    float4 v = *(const float4*)(x + i);
    float vv[4] = {v.x, v.y, v.z, v.w};
    __nv_bfloat16 h[4], l[4];
#pragma unroll
    for (int u = 0; u < 4; u++) {
        h[u] = __float2bfloat16_rn(vv[u]);
        l[u] = __float2bfloat16_rn(vv[u] - __bfloat162float(h[u]));
    }
    *(uint2*)(hi + i) = *(uint2*)h;
    *(uint2*)(lo + i) = *(uint2*)l;
}

// ---------------------------------------------------------------------------
// Tiled weight transpose + split: w[k][n] fp32 -> hi/lo [n][k] bf16.
// grid(32,32), block(32,8)
// ---------------------------------------------------------------------------
__global__ __launch_bounds__(256) void transpose_split_w(
    const float* __restrict__ w, __nv_bfloat16* __restrict__ hi,
    __nv_bfloat16* __restrict__ lo)
{
    __shared__ float t[32][33];
    const int bx = blockIdx.x * 32;  // n tile
    const int by = blockIdx.y * 32;  // k tile
    const int tx = threadIdx.x, ty = threadIdx.y;
#pragma unroll
    for (int i = 0; i < 4; i++)
        t[ty + 8 * i][tx] = w[(size_t)(by + ty + 8 * i) * Dsz + bx + tx];
    __syncthreads();
#pragma unroll
    for (int i = 0; i < 4; i++) {
        float v = t[tx][ty + 8 * i];
        __nv_bfloat16 h = __float2bfloat16_rn(v);
        __nv_bfloat16 l = __float2bfloat16_rn(v - __bfloat162float(h));
        const size_t o = (size_t)(bx + ty + 8 * i) * Dsz + by + tx;
        hi[o] = h;
        lo[o] = l;
    }
}

// ---------------------------------------------------------------------------
// V transpose (bf16 x2): vh/vl [b*S+s][h*64+d] -> vth/vtl [(b*H+h)*64+d][s]
// grid(S/32, DK/32, B*H), block(32,8)
// ---------------------------------------------------------------------------
__global__ __launch_bounds__(256) void transpose_v(
    const __nv_bfloat16* __restrict__ vh, const __nv_bfloat16* __restrict__ vl,
    __nv_bfloat16* __restrict__ vth, __nv_bfloat16* __restrict__ vtl)
{
    __shared__ __nv_bfloat16 th[32][33], tl[32][33];
    const int s0 = blockIdx.x * 32, d0 = blockIdx.y * 32;
    const int bh = blockIdx.z, b = bh >> 4, h = bh & 15;
    const int tx = threadIdx.x, ty = threadIdx.y;
#pragma unroll
    for (int i = 0; i < 4; i++) {
        const size_t src = ((size_t)b * Ssz + s0 + ty + 8 * i) * Dsz + h * DKsz + d0 + tx;
        th[ty + 8 * i][tx] = vh[src];
        tl[ty + 8 * i][tx] = vl[src];
    }
    __syncthreads();
#pragma unroll
    for (int i = 0; i < 4; i++) {
        const size_t dst = (((size_t)b * Hsz + h) * DKsz + d0 + ty + 8 * i) * Ssz + s0 + tx;
        vth[dst] = th[tx][ty + 8 * i];
        vtl[dst] = tl[tx][ty + 8 * i];
    }
}

// ---------------------------------------------------------------------------
// bf16x3 tensor-core GEMM: C = Ahl[M,K] @ Bhl[N,K]^T + bias[N]
// SPLIT=true: write bf16 hi/lo; else fp32.
// ---------------------------------------------------------------------------
#define LDSTR 40

#define MMA16816(d, a, b0, b1)                                              \
    asm volatile(                                                           \
        "mma.sync.aligned.m16n8k16.row.col.f32.bf16.bf16.f32 "              \
        "{%0,%1,%2,%3},{%4,%5,%6,%7},{%8,%9},{%0,%1,%2,%3};"                \
        : "+f"(d[0]), "+f"(d[1]), "+f"(d[2]), "+f"(d[3])                    \
        : "r"(a[0]), "r"(a[1]), "r"(a[2]), "r"(a[3]), "r"(b0), "r"(b1))

template <bool SPLIT>
__global__ __launch_bounds__(256, 2) void gemm_bf16x3(
    const __nv_bfloat16* __restrict__ Ah, const __nv_bfloat16* __restrict__ Al,
    const __nv_bfloat16* __restrict__ Bh, const __nv_bfloat16* __restrict__ Bl,
    const float* __restrict__ bias, float* __restrict__ C,
    __nv_bfloat16* __restrict__ Ch, __nv_bfloat16* __restrict__ Cl,
    int M, int N, int K)
{
    __shared__ __nv_bfloat16 sA[2][128 * LDSTR];
    __shared__ __nv_bfloat16 sB[2][128 * LDSTR];

    const int tid = threadIdx.x;
    const int bm = blockIdx.y * 128, bn = blockIdx.x * 128;
    const int w = tid >> 5, lane = tid & 31;
    const int g = lane >> 2, tg = lane & 3;
    const int wm = w >> 1, wn = w & 1;

    float fa[2][8][4];
#pragma unroll
    for (int i = 0; i < 2; i++)
#pragma unroll
        for (int j = 0; j < 8; j++)
#pragma unroll
            for (int u = 0; u < 4; u++) fa[i][j][u] = 0.f;

    for (int k0 = 0; k0 < K; k0 += 32) {
        __syncthreads();
#pragma unroll
        for (int s = 0; s < 4; s++) {
            const int seg = tid + s * 256;
            const int row = seg >> 3, col = (seg & 7) * 4;
            *(uint2*)&sA[0][row * LDSTR + col] =
                *(const uint2*)(Ah + (size_t)(bm + row) * K + k0 + col);
            *(uint2*)&sA[1][row * LDSTR + col] =
                *(const uint2*)(Al + (size_t)(bm + row) * K + k0 + col);
            *(uint2*)&sB[0][row * LDSTR + col] =
                *(const uint2*)(Bh + (size_t)(bn + row) * K + k0 + col);
            *(uint2*)&sB[1][row * LDSTR + col] =
                *(const uint2*)(Bl + (size_t)(bn + row) * K + k0 + col);
        }
        __syncthreads();

#pragma unroll
        for (int ks = 0; ks < 2; ks++) {
            const int kb = ks * 16 + tg * 2;
            uint32_t a[2][2][4];
#pragma unroll
            for (int i = 0; i < 2; i++) {
                const int r0 = wm * 32 + i * 16 + g;
#pragma unroll
                for (int hl = 0; hl < 2; hl++) {
                    a[hl][i][0] = *(const uint32_t*)&sA[hl][r0 * LDSTR + kb];
                    a[hl][i][1] = *(const uint32_t*)&sA[hl][(r0 + 8) * LDSTR + kb];
                    a[hl][i][2] = *(const uint32_t*)&sA[hl][r0 * LDSTR + kb + 8];
                    a[hl][i][3] = *(const uint32_t*)&sA[hl][(r0 + 8) * LDSTR + kb + 8];
                }
            }
#pragma unroll
            for (int j = 0; j < 8; j++) {
                const int n0 = wn * 64 + j * 8 + g;
                const uint32_t bh0 = *(const uint32_t*)&sB[0][n0 * LDSTR + kb];
                const uint32_t bh1 = *(const uint32_t*)&sB[0][n0 * LDSTR + kb + 8];
                const uint32_t bl0 = *(const uint32_t*)&sB[1][n0 * LDSTR + kb];
                const uint32_t bl1 = *(const uint32_t*)&sB[1][n0 * LDSTR + kb + 8];
#pragma unroll
                for (int i = 0; i < 2; i++) {
                    MMA16816(fa[i][j], a[0][i], bh0, bh1);
                    MMA16816(fa[i][j], a[1][i], bh0, bh1);
                    MMA16816(fa[i][j], a[0][i], bl0, bl1);
                }
            }
        }
    }

#pragma unroll
    for (int i = 0; i < 2; i++) {
        const int row = bm + wm * 32 + i * 16 + g;
#pragma unroll
        for (int j = 0; j < 8; j++) {
            const int col = bn + wn * 64 + j * 8 + tg * 2;
            const float b0 = bias[col], b1 = bias[col + 1];
            float v00 = fa[i][j][0] + b0, v01 = fa[i][j][1] + b1;
            float v10 = fa[i][j][2] + b0, v11 = fa[i][j][3] + b1;
            if (SPLIT) {
                __nv_bfloat16 h00 = __float2bfloat16_rn(v00);
                __nv_bfloat16 h01 = __float2bfloat16_rn(v01);
                __nv_bfloat16 h10 = __float2bfloat16_rn(v10);
                __nv_bfloat16 h11 = __float2bfloat16_rn(v11);
                const size_t o0 = (size_t)row * N + col;
                const size_t o1 = (size_t)(row + 8) * N + col;
                *(uint32_t*)(Ch + o0) =
                    (uint32_t)*(uint16_t*)&h00 | ((uint32_t)*(uint16_t*)&h01 << 16);
                *(uint32_t*)(Ch + o1) =
                    (uint32_t)*(uint16_t*)&h10 | ((uint32_t)*(uint16_t*)&h11 << 16);
                *(uint32_t*)(Cl + o0) = pack2bf(v00 - __bfloat162float(h00),
                                                v01 - __bfloat162float(h01));
                *(uint32_t*)(Cl + o1) = pack2bf(v10 - __bfloat162float(h10),
                                                v11 - __bfloat162float(h11));
            } else {
                float2 a2 = {v00, v01}, b2 = {v10, v11};
                *(float2*)&C[(size_t)row * N + col] = a2;
                *(float2*)&C[(size_t)(row + 8) * N + col] = b2;
            }
        }
    }
}

// ---------------------------------------------------------------------------
// mma flash attention. q-tile 128, k-tile 64, 8 warps (16 q-rows each).
// S = QK^T via 3-pass bf16 mma (Q frags in regs), register softmax with
// state_weight bias + strict causal, P hi/lo in regs -> 3-pass PV mma
// against V^T smem tile. Epilogue writes bf16 hi/lo ctx.
// ---------------------------------------------------------------------------
#define KSTR 72   // smem row stride (bf16): conflict-free frag loads

__global__ __launch_bounds__(256) void flash_attn_mma(
    const __nv_bfloat16* __restrict__ Qh, const __nv_bfloat16* __restrict__ Ql,
    const __nv_bfloat16* __restrict__ Kh, const __nv_bfloat16* __restrict__ Kl,
    const __nv_bfloat16* __restrict__ Vth, const __nv_bfloat16* __restrict__ Vtl,
    const float* __restrict__ SW,
    __nv_bfloat16* __restrict__ ctx_h, __nv_bfloat16* __restrict__ ctx_l)
{
    __shared__ __nv_bfloat16 sK[2][64 * KSTR];
    __shared__ __nv_bfloat16 sV[2][64 * KSTR];   // V^T: [d][j]

    const int qt = blockIdx.x, h = blockIdx.y, b = blockIdx.z;
    const int tid = threadIdx.x, w = tid >> 5, lane = tid & 31;
    const int g = lane >> 2, tg = lane & 3;
    const int q0 = qt * 128, rw = q0 + w * 16;
    const float scale = 0.125f;

    // Q fragments resident in registers: [hi/lo][kstep][reg]
    uint32_t aq[2][4][4];
    {
        const size_t base = ((size_t)b * Ssz) * Dsz + (size_t)h * DKsz;
#pragma unroll
        for (int t = 0; t < 4; t++) {
            const int col = t * 16 + tg * 2;
            const size_t r0 = base + (size_t)(rw + g) * Dsz + col;
            const size_t r1 = base + (size_t)(rw + g + 8) * Dsz + col;
            aq[0][t][0] = *(const uint32_t*)(Qh + r0);
            aq[0][t][1] = *(const uint32_t*)(Qh + r1);
            aq[0][t][2] = *(const uint32_t*)(Qh + r0 + 8);
            aq[0][t][3] = *(const uint32_t*)(Qh + r1 + 8);
            aq[1][t][0] = *(const uint32_t*)(Ql + r0);
            aq[1][t][1] = *(const uint32_t*)(Ql + r1);
            aq[1][t][2] = *(const uint32_t*)(Ql + r0 + 8);
            aq[1][t][3] = *(const uint32_t*)(Ql + r1 + 8);
        }
    }

    const int i0 = rw + g, i1 = rw + g + 8;
    float m0 = -CUDART_INF_F, m1 = -CUDART_INF_F, l0 = 0.f, l1 = 0.f;
    float o[8][4];
#pragma unroll
    for (int d = 0; d < 8; d++)
#pragma unroll
        for (int u = 0; u < 4; u++) o[d][u] = 0.f;

    const int nkt = 2 * qt + 2;
    for (int kt = 0; kt < nkt; kt++) {
        const int k0 = kt * 64;
        __syncthreads();
        // Load K tile (rows j, cols d) and V^T tile (rows d, cols j)
#pragma unroll
        for (int it = 0; it < 2; it++) {
            const int seg = tid + it * 256;
            const int row = seg >> 3, cc = (seg & 7) * 8;
            const size_t gk = ((size_t)b * Ssz + k0 + row) * Dsz + h * DKsz + cc;
            *(uint4*)&sK[0][row * KSTR + cc] = *(const uint4*)(Kh + gk);
            *(uint4*)&sK[1][row * KSTR + cc] = *(const uint4*)(Kl + gk);
            const size_t gv = (((size_t)b * Hsz + h) * DKsz + row) * Ssz + k0 + cc;
            *(uint4*)&sV[0][row * KSTR + cc] = *(const uint4*)(Vth + gv);
            *(uint4*)&sV[1][row * KSTR + cc] = *(const uint4*)(Vtl + gv);
        }
        __syncthreads();

        if (k0 > rw + 14) continue;  // fully masked for this warp

        // ---- S = Q K^T ----
        float sf[8][4];
#pragma unroll
        for (int j = 0; j < 8; j++)
#pragma unroll
            for (int u = 0; u < 4; u++) sf[j][u] = 0.f;
#pragma unroll
        for (int t = 0; t < 4; t++) {
            const int kb = t * 16 + tg * 2;
#pragma unroll
            for (int j = 0; j < 8; j++) {
                const int ba = (j * 8 + g) * KSTR + kb;
                const uint32_t bh0 = *(const uint32_t*)&sK[0][ba];
                const uint32_t bh1 = *(const uint32_t*)&sK[0][ba + 8];
                const uint32_t bl0 = *(const uint32_t*)&sK[1][ba];
                const uint32_t bl1 = *(const uint32_t*)&sK[1][ba + 8];
                MMA16816(sf[j], aq[0][t], bh0, bh1);
                MMA16816(sf[j], aq[1][t], bh0, bh1);
                MMA16816(sf[j], aq[0][t], bl0, bl1);
            }
        }

        // ---- scale + state_weight + causal mask ----
        const float* sw0 = SW + ((size_t)h * Ssz + i0) * Ssz + k0;
        const float* sw1 = SW + ((size_t)h * Ssz + i1) * Ssz + k0;
        const bool needmask = (k0 + 63 >= i0);
#pragma unroll
        for (int j = 0; j < 8; j++) {
            const int c = j * 8 + tg * 2;
            const float2 w0 = *(const float2*)(sw0 + c);
            const float2 w1 = *(const float2*)(sw1 + c);
            sf[j][0] = sf[j][0] * scale + w0.x;
            sf[j][1] = sf[j][1] * scale + w0.y;
            sf[j][2] = sf[j][2] * scale + w1.x;
            sf[j][3] = sf[j][3] * scale + w1.y;
            if (needmask) {
                const int gc = k0 + c;
                if (gc     >= i0) sf[j][0] = -CUDART_INF_F;
                if (gc + 1 >= i0) sf[j][1] = -CUDART_INF_F;
                if (gc     >= i1) sf[j][2] = -CUDART_INF_F;
                if (gc + 1 >= i1) sf[j][3] = -CUDART_INF_F;
            }
        }

        // ---- row max (across quad lanes) ----
        float r0m = -CUDART_INF_F, r1m = -CUDART_INF_F;
#pragma unroll
        for (int j = 0; j < 8; j++) {
            r0m = fmaxf(r0m, fmaxf(sf[j][0], sf[j][1]));
            r1m = fmaxf(r1m, fmaxf(sf[j][2], sf[j][3]));
        }
        r0m = fmaxf(r0m, __shfl_xor_sync(0xffffffffu, r0m, 1));
        r0m = fmaxf(r0m, __shfl_xor_sync(0xffffffffu, r0m, 2));
        r1m = fmaxf(r1m, __shfl_xor_sync(0xffffffffu, r1m, 1));
        r1m = fmaxf(r1m, __shfl_xor_sync(0xffffffffu, r1m, 2));

        const float mn0 = fmaxf(m0, r0m), mn1 = fmaxf(m1, r1m);
        const float corr0 = (mn0 == -CUDART_INF_F) ? 0.f : __expf(m0 - mn0);
        const float corr1 = (mn1 == -CUDART_INF_F) ? 0.f : __expf(m1 - mn1);

        // ---- P = exp(S-m), row sums, pack hi/lo A-frags ----
        float rs0 = 0.f, rs1 = 0.f;
        uint32_t ph[4][4], pl[4][4];
#pragma unroll
        for (int t = 0; t < 4; t++) {
            float pv[2][4];   // [frag 2t / 2t+1][reg]
#pragma unroll
            for (int u = 0; u < 2; u++) {
                const int j = 2 * t + u;
#pragma unroll
                for (int r = 0; r < 4; r++) {
                    const float e = sf[j][r];
                    const float mm = (r < 2) ? mn0 : mn1;
                    float p = (e == -CUDART_INF_F) ? 0.f : __expf(e - mm);
                    pv[u][r] = p;
                    if (r < 2) rs0 += p; else rs1 += p;
                }
            }
            // A-frag: a0=(row g, k=tg*2..)=frag2t c0c1; a1=frag2t c2c3;
            //         a2=frag2t+1 c0c1; a3=frag2t+1 c2c3
            float lo[2][4];
#pragma unroll
            for (int u = 0; u < 2; u++)
#pragma unroll
                for (int r = 0; r < 4; r++) {
                    __nv_bfloat16 hb = __float2bfloat16_rn(pv[u][r]);
                    lo[u][r] = pv[u][r] - __bfloat162float(hb);
                }
            ph[t][0] = pack2bf(pv[0][0], pv[0][1]);
            ph[t][1] = pack2bf(pv[0][2], pv[0][3]);
            ph[t][2] = pack2bf(pv[1][0], pv[1][1]);
            ph[t][3] = pack2bf(pv[1][2], pv[1][3]);
            pl[t][0] = pack2bf(lo[0][0], lo[0][1]);
            pl[t][1] = pack2bf(lo[0][2], lo[0][3]);
            pl[t][2] = pack2bf(lo[1][0], lo[1][1]);
            pl[t][3] = pack2bf(lo[1][2], lo[1][3]);
        }
        rs0 += __shfl_xor_sync(0xffffffffu, rs0, 1);
        rs0 += __shfl_xor_sync(0xffffffffu, rs0, 2);
        rs1 += __shfl_xor_sync(0xffffffffu, rs1, 1);
        rs1 += __shfl_xor_sync(0xffffffffu, rs1, 2);

        l0 = l0 * corr0 + rs0;
        l1 = l1 * corr1 + rs1;
        m0 = mn0; m1 = mn1;
#pragma unroll
        for (int d = 0; d < 8; d++) {
            o[d][0] *= corr0; o[d][1] *= corr0;
            o[d][2] *= corr1; o[d][3] *= corr1;
        }

        // ---- O += P V  (B-frags from V^T tile) ----
#pragma unroll
        for (int t = 0; t < 4; t++) {
            const int kb = t * 16 + tg * 2;
#pragma unroll
            for (int d = 0; d < 8; d++) {
                const int ba = (d * 8 + g) * KSTR + kb;
                const uint32_t vh0 = *(const uint32_t*)&sV[0][ba];
                const uint32_t vh1 = *(const uint32_t*)&sV[0][ba + 8];
                const uint32_t vl0 = *(const uint32_t*)&sV[1][ba];
                const uint32_t vl1 = *(const uint32_t*)&sV[1][ba + 8];
                MMA16816(o[d], ph[t], vh0, vh1);
                MMA16816(o[d], pl[t], vh0, vh1);
                MMA16816(o[d], ph[t], vl0, vl1);
            }
        }
    }

    // ---- epilogue: normalize, split bf16 hi/lo, store ----
    const float inv0 = (l0 > 0.f) ? (1.f / l0) : 0.f;
    const float inv1 = (l1 > 0.f) ? (1.f / l1) : 0.f;
    const size_t ob = ((size_t)b * Ssz) * Dsz + (size_t)h * DKsz;
#pragma unroll
    for (int d = 0; d < 8; d++) {
        const int col = d * 8 + tg * 2;
        float v00 = o[d][0] * inv0, v01 = o[d][1] * inv0;
        float v10 = o[d][2] * inv1, v11 = o[d][3] * inv1;
        __nv_bfloat16 h00 = __float2bfloat16_rn(v00);
        __nv_bfloat16 h01 = __float2bfloat16_rn(v01);
        __nv_bfloat16 h10 = __float2bfloat16_rn(v10);
        __nv_bfloat16 h11 = __float2bfloat16_rn(v11);
        const size_t o0 = ob + (size_t)i0 * Dsz + col;
        const size_t o1 = ob + (size_t)i1 * Dsz + col;
        *(uint32_t*)(ctx_h + o0) =
            (uint32_t)*(uint16_t*)&h00 | ((uint32_t)*(uint16_t*)&h01 << 16);
        *(uint32_t*)(ctx_h + o1) =
            (uint32_t)*(uint16_t*)&h10 | ((uint32_t)*(uint16_t*)&h11 << 16);
        *(uint32_t*)(ctx_l + o0) = pack2bf(v00 - __bfloat162float(h00),
                                           v01 - __bfloat162float(h01));
        *(uint32_t*)(ctx_l + o1) = pack2bf(v10 - __bfloat162float(h10),
                                           v11 - __bfloat162float(h11));
    }
}

// ---------------------------------------------------------------------------
// Residual + LayerNorm
// ---------------------------------------------------------------------------
__global__ __launch_bounds__(256) void residual_ln(
    const float* __restrict__ x0, const float* __restrict__ y,
    const float* __restrict__ gamma, const float* __restrict__ beta,
    float* __restrict__ out)
{
    const int row = blockIdx.x;
    const float* a = x0 + (size_t)row * Dsz;
    const float* c = y  + (size_t)row * Dsz;
    const int tid = threadIdx.x;

    float v[4];
    float sum = 0.f, sumsq = 0.f;
#pragma unroll
    for (int u = 0; u < 4; u++) {
        int idx = tid + u * 256;
        float t = a[idx] + c[idx];
        v[u] = t;
        sum += t;
        sumsq += t * t;
    }
#pragma unroll
    for (int off = 16; off; off >>= 1) {
        sum   += __shfl_xor_sync(0xffffffffu, sum, off);
        sumsq += __shfl_xor_sync(0xffffffffu, sumsq, off);
    }
    __shared__ float s1[8], s2[8];
    if ((tid & 31) == 0) { s1[tid >> 5] = sum; s2[tid >> 5] = sumsq; }
    __syncthreads();
    if (tid < 32) {
        sum   = (tid < 8) ? s1[tid] : 0.f;
        sumsq = (tid < 8) ? s2[tid] : 0.f;
#pragma unroll
        for (int off = 4; off; off >>= 1) {
            sum   += __shfl_xor_sync(0xffffffffu, sum, off);
            sumsq += __shfl_xor_sync(0xffffffffu, sumsq, off);
        }
        if (tid == 0) { s1[0] = sum; s2[0] = sumsq; }
    }
    __syncthreads();
    const float mu   = s1[0] * (1.f / Dsz);
    const float var  = s2[0] * (1.f / Dsz) - mu * mu;
    const float rstd = rsqrtf(var + 1e-5f);

    float* op = out + (size_t)row * Dsz;
#pragma unroll
    for (int u = 0; u < 4; u++) {
        int idx = tid + u * 256;
        op[idx] = (v[u] - mu) * rstd * gamma[idx] + beta[idx];
    }
}

// ---------------------------------------------------------------------------
extern "C" void kernel_launch(void* const* d_in, const int* in_sizes, int n_in,
                              void* d_out, int out_size)
{
    const float* query  = (const float*)d_in[0];
    const float* key    = (const float*)d_in[1];
    const float* values = (const float*)d_in[2];
    // d_in[3] = lens (unused by reference)
    const float* sw     = (const float*)d_in[4];
    const float* Wq     = (const float*)d_in[5];
    const float* bq     = (const float*)d_in[6];
    const float* Wv     = (const float*)d_in[7];
    const float* bv     = (const float*)d_in[8];
    const float* Wo     = (const float*)d_in[9];
    const float* bo     = (const float*)d_in[10];
    const float* gamma  = (const float*)d_in[11];
    const float* beta   = (const float*)d_in[12];
    float* out = (float*)d_out;

    __nv_bfloat16 *xqh, *xql, *xkh, *xkl, *xvh, *xvl;
    __nv_bfloat16 *Qh, *Ql, *Kh, *Kl, *Vh, *Vl, *vth, *vtl, *ch, *cl;
    __nv_bfloat16 *wqh, *wql, *wvh, *wvl, *woh, *wol;
    float* Op;
    cudaGetSymbolAddress((void**)&xqh, g_xqh); cudaGetSymbolAddress((void**)&xql, g_xql);
    cudaGetSymbolAddress((void**)&xkh, g_xkh); cudaGetSymbolAddress((void**)&xkl, g_xkl);
    cudaGetSymbolAddress((void**)&xvh, g_xvh); cudaGetSymbolAddress((void**)&xvl, g_xvl);
    cudaGetSymbolAddress((void**)&Qh, g_Qh);   cudaGetSymbolAddress((void**)&Ql, g_Ql);
    cudaGetSymbolAddress((void**)&Kh, g_Kh);   cudaGetSymbolAddress((void**)&Kl, g_Kl);
    cudaGetSymbolAddress((void**)&Vh, g_Vh);   cudaGetSymbolAddress((void**)&Vl, g_Vl);
    cudaGetSymbolAddress((void**)&vth, g_vth); cudaGetSymbolAddress((void**)&vtl, g_vtl);
    cudaGetSymbolAddress((void**)&ch, g_ch);   cudaGetSymbolAddress((void**)&cl, g_cl);
    cudaGetSymbolAddress((void**)&wqh, g_wqh); cudaGetSymbolAddress((void**)&wql, g_wql);
    cudaGetSymbolAddress((void**)&wvh, g_wvh); cudaGetSymbolAddress((void**)&wvl, g_wvl);
    cudaGetSymbolAddress((void**)&woh, g_woh); cudaGetSymbolAddress((void**)&wol, g_wol);
    cudaGetSymbolAddress((void**)&Op, g_O);

    const int nblk = (int)(NELEM / 1024);
    split_f32<<<nblk, 256>>>(query,  xqh, xql);
    split_f32<<<nblk, 256>>>(key,    xkh, xkl);
    split_f32<<<nblk, 256>>>(values, xvh, xvl);

    dim3 tb(32, 8);
    transpose_split_w<<<dim3(32, 32), tb>>>(Wq, wqh, wql);
    transpose_split_w<<<dim3(32, 32), tb>>>(Wv, wvh, wvl);
    transpose_split_w<<<dim3(32, 32), tb>>>(Wo, woh, wol);

    dim3 gg(Dsz / 128, Msz / 128);  // (8, 32)
    gemm_bf16x3<true><<<gg, 256>>>(xqh, xql, wqh, wql, bq, nullptr, Qh, Ql,
                                   Msz, Dsz, Dsz);
    gemm_bf16x3<true><<<gg, 256>>>(xkh, xkl, wqh, wql, bq, nullptr, Kh, Kl,
                                   Msz, Dsz, Dsz);
    gemm_bf16x3<true><<<gg, 256>>>(xvh, xvl, wvh, wvl, bv, nullptr, Vh, Vl,
                                   Msz, Dsz, Dsz);

    transpose_v<<<dim3(Ssz / 32, DKsz / 32, Bsz * Hsz), tb>>>(Vh, Vl, vth, vtl);

    flash_attn_mma<<<dim3(Ssz / 128, Hsz, Bsz), 256>>>(Qh, Ql, Kh, Kl, vth, vtl,
                                                       sw, ch, cl);

    gemm_bf16x3<false><<<gg, 256>>>(ch, cl, woh, wol, bo, Op, nullptr, nullptr,
                                    Msz, Dsz, Dsz);

    residual_ln<<<Msz, 256>>>(query, Op, gamma, beta, out);
}

// round 5
// speedup vs baseline: 4.2551x; 1.1397x over previous
#include <cuda_runtime.h>
#include <cuda_bf16.h>
#include <math_constants.h>
#include <cstdint>

// ---------------------------------------------------------------------------
// DTransformerLayer: B=4, S=1024, D=1024, H=16, DK=64
// R5: cp.async double-buffered bf16x3 tensor-core GEMMs (BK=16, XOR-swizzled
// smem, merged QKV launch), mma flash attention (unchanged from R4).
// ---------------------------------------------------------------------------

#define Bsz 4
#define Ssz 1024
#define Dsz 1024
#define Hsz 16
#define DKsz 64
#define Msz (Bsz * Ssz)            // 4096
#define NELEM ((size_t)Msz * Dsz)  // 4M
#define WELEM ((size_t)Dsz * Dsz)  // 1M

// input activation splits
__device__ __nv_bfloat16 g_xqh[NELEM], g_xql[NELEM];
__device__ __nv_bfloat16 g_xkh[NELEM], g_xkl[NELEM];
__device__ __nv_bfloat16 g_xvh[NELEM], g_xvl[NELEM];
// projection outputs (bf16 hi/lo)
__device__ __nv_bfloat16 g_Qh[NELEM], g_Ql[NELEM];
__device__ __nv_bfloat16 g_Kh[NELEM], g_Kl[NELEM];
__device__ __nv_bfloat16 g_Vh[NELEM], g_Vl[NELEM];
// V transposed per (b,h)
__device__ __nv_bfloat16 g_vth[NELEM], g_vtl[NELEM];
// attention context (bf16 hi/lo)
__device__ __nv_bfloat16 g_ch[NELEM], g_cl[NELEM];
// weights transposed [N][K]
__device__ __nv_bfloat16 g_wqh[WELEM], g_wql[WELEM];
__device__ __nv_bfloat16 g_wvh[WELEM], g_wvl[WELEM];
__device__ __nv_bfloat16 g_woh[WELEM], g_wol[WELEM];
// O projection fp32
__device__ float g_O[NELEM];

__device__ __forceinline__ uint32_t pack2bf(float a, float b) {
    __nv_bfloat162 t = __floats2bfloat162_rn(a, b);
    return *(uint32_t*)&t;
}

__device__ __forceinline__ void cp_async16(uint32_t dst_sm, const void* src) {
    asm volatile("cp.async.cg.shared.global [%0], [%1], 16;\n"
                 :: "r"(dst_sm), "l"(src));
}
#define CP_COMMIT() asm volatile("cp.async.commit_group;\n" ::: "memory")
#define CP_WAIT0()  asm volatile("cp.async.wait_group 0;\n" ::: "memory")

// ---------------------------------------------------------------------------
__global__ __launch_bounds__(256) void split_f32(
    const float* __restrict__ x, __nv_bfloat16* __restrict__ hi,
    __nv_bfloat16* __restrict__ lo)
{
    const size_t i = ((size_t)blockIdx.x * 256 + threadIdx.x) * 4;
    float4 v = *(const float4*)(x + i);
    float vv[4] = {v.x, v.y, v.z, v.w};
    __nv_bfloat16 h[4], l[4];
#pragma unroll
    for (int u = 0; u < 4; u++) {
        h[u] = __float2bfloat16_rn(vv[u]);
        l[u] = __float2bfloat16_rn(vv[u] - __bfloat162float(h[u]));
    }
    *(uint2*)(hi + i) = *(uint2*)h;
    *(uint2*)(lo + i) = *(uint2*)l;
}

// ---------------------------------------------------------------------------
__global__ __launch_bounds__(256) void transpose_split_w(
    const float* __restrict__ w, __nv_bfloat16* __restrict__ hi,
    __nv_bfloat16* __restrict__ lo)
{
    __shared__ float t[32][33];
    const int bx = blockIdx.x * 32;
    const int by = blockIdx.y * 32;
    const int tx = threadIdx.x, ty = threadIdx.y;
#pragma unroll
    for (int i = 0; i < 4; i++)
        t[ty + 8 * i][tx] = w[(size_t)(by + ty + 8 * i) * Dsz + bx + tx];
    __syncthreads();
#pragma unroll
    for (int i = 0; i < 4; i++) {
        float v = t[tx][ty + 8 * i];
        __nv_bfloat16 h = __float2bfloat16_rn(v);
        __nv_bfloat16 l = __float2bfloat16_rn(v - __bfloat162float(h));
        const size_t o = (size_t)(bx + ty + 8 * i) * Dsz + by + tx;
        hi[o] = h;
        lo[o] = l;
    }
}

// ---------------------------------------------------------------------------
__global__ __launch_bounds__(256) void transpose_v(
    const __nv_bfloat16* __restrict__ vh, const __nv_bfloat16* __restrict__ vl,
    __nv_bfloat16* __restrict__ vth, __nv_bfloat16* __restrict__ vtl)
{
    __shared__ __nv_bfloat16 th[32][33], tl[32][33];
    const int s0 = blockIdx.x * 32, d0 = blockIdx.y * 32;
    const int bh = blockIdx.z, b = bh >> 4, h = bh & 15;
    const int tx = threadIdx.x, ty = threadIdx.y;
#pragma unroll
    for (int i = 0; i < 4; i++) {
        const size_t src = ((size_t)b * Ssz + s0 + ty + 8 * i) * Dsz + h * DKsz + d0 + tx;
        th[ty + 8 * i][tx] = vh[src];
        tl[ty + 8 * i][tx] = vl[src];
    }
    __syncthreads();
#pragma unroll
    for (int i = 0; i < 4; i++) {
        const size_t dst = (((size_t)b * Hsz + h) * DKsz + d0 + ty + 8 * i) * Ssz + s0 + tx;
        vth[dst] = th[tx][ty + 8 * i];
        vtl[dst] = tl[tx][ty + 8 * i];
    }
}

// ---------------------------------------------------------------------------
// Pipelined bf16x3 GEMM. BM=BN=128, BK=16, 2-stage cp.async, XOR swizzle.
// C = Ahl[M,K] @ Bhl[N,K]^T + bias. Up to 3 batched problems via blockIdx.z.
// ---------------------------------------------------------------------------
#define MMA16816(d, a, b0, b1)                                              \
    asm volatile(                                                           \
        "mma.sync.aligned.m16n8k16.row.col.f32.bf16.bf16.f32 "              \
        "{%0,%1,%2,%3},{%4,%5,%6,%7},{%8,%9},{%0,%1,%2,%3};"                \
        : "+f"(d[0]), "+f"(d[1]), "+f"(d[2]), "+f"(d[3])                    \
        : "r"(a[0]), "r"(a[1]), "r"(a[2]), "r"(a[3]), "r"(b0), "r"(b1))

// word index within a 128-row x 8-word tile, chunk-XOR swizzled
__device__ __forceinline__ int swz(int row, int wc) {
    return row * 8 + (((wc >> 2) ^ ((row >> 2) & 1)) << 2) + (wc & 3);
}

struct GemmArgs {
    const __nv_bfloat16 *Ah[3], *Al[3], *Bh[3], *Bl[3];
    const float* bias[3];
    float* Cf[3];
    __nv_bfloat16 *Ch[3], *Cl[3];
};

template <bool SPLIT>
__global__ __launch_bounds__(256, 2) void gemm_pipe(GemmArgs args, int M, int N, int K)
{
    __shared__ uint32_t sA[2][2][128 * 8];  // [stage][hi/lo]
    __shared__ uint32_t sB[2][2][128 * 8];

    const int z = blockIdx.z;
    const __nv_bfloat16* __restrict__ Ah = args.Ah[z];
    const __nv_bfloat16* __restrict__ Al = args.Al[z];
    const __nv_bfloat16* __restrict__ Bh = args.Bh[z];
    const __nv_bfloat16* __restrict__ Bl = args.Bl[z];
    const float* __restrict__ bias = args.bias[z];

    const int tid = threadIdx.x;
    const int bm = blockIdx.y * 128, bn = blockIdx.x * 128;
    const int w = tid >> 5, lane = tid & 31;
    const int g = lane >> 2, tg = lane & 3;
    const int wm = w >> 1, wn = w & 1;

    // load mapping: row = tid>>1 (0..127), chunk = tid&1 (8 elems each)
    const int lrow = tid >> 1, lch = tid & 1;
    const int ldst = (lrow * 8 + (((lch) ^ ((lrow >> 2) & 1)) << 2)) * 4; // byte offset
    const size_t gA = (size_t)(bm + lrow) * K + lch * 8;
    const size_t gB = (size_t)(bn + lrow) * K + lch * 8;

    uint32_t baseA0 = (uint32_t)__cvta_generic_to_shared(&sA[0][0][0]);
    uint32_t baseA1 = (uint32_t)__cvta_generic_to_shared(&sA[0][1][0]);
    uint32_t baseB0 = (uint32_t)__cvta_generic_to_shared(&sB[0][0][0]);
    uint32_t baseB1 = (uint32_t)__cvta_generic_to_shared(&sB[0][1][0]);
    const uint32_t stgoff = 128 * 8 * 2 * 4;  // bytes per stage within sA / sB

    float fa[2][8][4];
#pragma unroll
    for (int i = 0; i < 2; i++)
#pragma unroll
        for (int j = 0; j < 8; j++)
#pragma unroll
            for (int u = 0; u < 4; u++) fa[i][j][u] = 0.f;

    // prologue: stage 0
    {
        cp_async16(baseA0 + ldst, Ah + gA);
        cp_async16(baseA1 + ldst, Al + gA);
        cp_async16(baseB0 + ldst, Bh + gB);
        cp_async16(baseB1 + ldst, Bl + gB);
        CP_COMMIT();
    }

    int s = 0;
    for (int k0 = 0; k0 < K; k0 += 16) {
        CP_WAIT0();
        __syncthreads();
        if (k0 + 16 < K) {
            const uint32_t so = (uint32_t)(s ^ 1) * stgoff;
            const size_t go = (size_t)(k0 + 16);
            cp_async16(baseA0 + so + ldst, Ah + gA + go);
            cp_async16(baseA1 + so + ldst, Al + gA + go);
            cp_async16(baseB0 + so + ldst, Bh + gB + go);
            cp_async16(baseB1 + so + ldst, Bl + gB + go);
            CP_COMMIT();
        }

        const uint32_t* A0 = sA[s][0];
        const uint32_t* A1 = sA[s][1];
        const uint32_t* B0 = sB[s][0];
        const uint32_t* B1 = sB[s][1];

        uint32_t a[2][2][4];
#pragma unroll
        for (int i = 0; i < 2; i++) {
            const int r0 = wm * 32 + i * 16 + g;
            a[0][i][0] = A0[swz(r0, tg)];
            a[0][i][1] = A0[swz(r0 + 8, tg)];
            a[0][i][2] = A0[swz(r0, tg + 4)];
            a[0][i][3] = A0[swz(r0 + 8, tg + 4)];
            a[1][i][0] = A1[swz(r0, tg)];
            a[1][i][1] = A1[swz(r0 + 8, tg)];
            a[1][i][2] = A1[swz(r0, tg + 4)];
            a[1][i][3] = A1[swz(r0 + 8, tg + 4)];
        }
#pragma unroll
        for (int j = 0; j < 8; j++) {
            const int n0 = wn * 64 + j * 8 + g;
            const uint32_t bh0 = B0[swz(n0, tg)];
            const uint32_t bh1 = B0[swz(n0, tg + 4)];
            const uint32_t bl0 = B1[swz(n0, tg)];
            const uint32_t bl1 = B1[swz(n0, tg + 4)];
#pragma unroll
            for (int i = 0; i < 2; i++) {
                MMA16816(fa[i][j], a[0][i], bh0, bh1);
                MMA16816(fa[i][j], a[1][i], bh0, bh1);
                MMA16816(fa[i][j], a[0][i], bl0, bl1);
            }
        }
        s ^= 1;
    }

#pragma unroll
    for (int i = 0; i < 2; i++) {
        const int row = bm + wm * 32 + i * 16 + g;
#pragma unroll
        for (int j = 0; j < 8; j++) {
            const int col = bn + wn * 64 + j * 8 + tg * 2;
            const float b0 = bias[col], b1 = bias[col + 1];
            float v00 = fa[i][j][0] + b0, v01 = fa[i][j][1] + b1;
            float v10 = fa[i][j][2] + b0, v11 = fa[i][j][3] + b1;
            if (SPLIT) {
                __nv_bfloat16 h00 = __float2bfloat16_rn(v00);
                __nv_bfloat16 h01 = __float2bfloat16_rn(v01);
                __nv_bfloat16 h10 = __float2bfloat16_rn(v10);
                __nv_bfloat16 h11 = __float2bfloat16_rn(v11);
                const size_t o0 = (size_t)row * N + col;
                const size_t o1 = (size_t)(row + 8) * N + col;
                *(uint32_t*)(args.Ch[z] + o0) =
                    (uint32_t)*(uint16_t*)&h00 | ((uint32_t)*(uint16_t*)&h01 << 16);
                *(uint32_t*)(args.Ch[z] + o1) =
                    (uint32_t)*(uint16_t*)&h10 | ((uint32_t)*(uint16_t*)&h11 << 16);
                *(uint32_t*)(args.Cl[z] + o0) = pack2bf(v00 - __bfloat162float(h00),
                                                        v01 - __bfloat162float(h01));
                *(uint32_t*)(args.Cl[z] + o1) = pack2bf(v10 - __bfloat162float(h10),
                                                        v11 - __bfloat162float(h11));
            } else {
                float2 a2 = {v00, v01}, b2 = {v10, v11};
                *(float2*)&args.Cf[z][(size_t)row * N + col] = a2;
                *(float2*)&args.Cf[z][(size_t)(row + 8) * N + col] = b2;
            }
        }
    }
}

// ---------------------------------------------------------------------------
// mma flash attention (unchanged from R4, passing).
// ---------------------------------------------------------------------------
#define KSTR 72

__global__ __launch_bounds__(256) void flash_attn_mma(
    const __nv_bfloat16* __restrict__ Qh, const __nv_bfloat16* __restrict__ Ql,
    const __nv_bfloat16* __restrict__ Kh, const __nv_bfloat16* __restrict__ Kl,
    const __nv_bfloat16* __restrict__ Vth, const __nv_bfloat16* __restrict__ Vtl,
    const float* __restrict__ SW,
    __nv_bfloat16* __restrict__ ctx_h, __nv_bfloat16* __restrict__ ctx_l)
{
    __shared__ __nv_bfloat16 sK[2][64 * KSTR];
    __shared__ __nv_bfloat16 sV[2][64 * KSTR];

    const int qt = blockIdx.x, h = blockIdx.y, b = blockIdx.z;
    const int tid = threadIdx.x, w = tid >> 5, lane = tid & 31;
    const int g = lane >> 2, tg = lane & 3;
    const int q0 = qt * 128, rw = q0 + w * 16;
    const float scale = 0.125f;

    uint32_t aq[2][4][4];
    {
        const size_t base = ((size_t)b * Ssz) * Dsz + (size_t)h * DKsz;
#pragma unroll
        for (int t = 0; t < 4; t++) {
            const int col = t * 16 + tg * 2;
            const size_t r0 = base + (size_t)(rw + g) * Dsz + col;
            const size_t r1 = base + (size_t)(rw + g + 8) * Dsz + col;
            aq[0][t][0] = *(const uint32_t*)(Qh + r0);
            aq[0][t][1] = *(const uint32_t*)(Qh + r1);
            aq[0][t][2] = *(const uint32_t*)(Qh + r0 + 8);
            aq[0][t][3] = *(const uint32_t*)(Qh + r1 + 8);
            aq[1][t][0] = *(const uint32_t*)(Ql + r0);
            aq[1][t][1] = *(const uint32_t*)(Ql + r1);
            aq[1][t][2] = *(const uint32_t*)(Ql + r0 + 8);
            aq[1][t][3] = *(const uint32_t*)(Ql + r1 + 8);
        }
    }

    const int i0 = rw + g, i1 = rw + g + 8;
    float m0 = -CUDART_INF_F, m1 = -CUDART_INF_F, l0 = 0.f, l1 = 0.f;
    float o[8][4];
#pragma unroll
    for (int d = 0; d < 8; d++)
#pragma unroll
        for (int u = 0; u < 4; u++) o[d][u] = 0.f;

    const int nkt = 2 * qt + 2;
    for (int kt = 0; kt < nkt; kt++) {
        const int k0 = kt * 64;
        __syncthreads();
#pragma unroll
        for (int it = 0; it < 2; it++) {
            const int seg = tid + it * 256;
            const int row = seg >> 3, cc = (seg & 7) * 8;
            const size_t gk = ((size_t)b * Ssz + k0 + row) * Dsz + h * DKsz + cc;
            *(uint4*)&sK[0][row * KSTR + cc] = *(const uint4*)(Kh + gk);
            *(uint4*)&sK[1][row * KSTR + cc] = *(const uint4*)(Kl + gk);
            const size_t gv = (((size_t)b * Hsz + h) * DKsz + row) * Ssz + k0 + cc;
            *(uint4*)&sV[0][row * KSTR + cc] = *(const uint4*)(Vth + gv);
            *(uint4*)&sV[1][row * KSTR + cc] = *(const uint4*)(Vtl + gv);
        }
        __syncthreads();

        if (k0 > rw + 14) continue;

        float sf[8][4];
#pragma unroll
        for (int j = 0; j < 8; j++)
#pragma unroll
            for (int u = 0; u < 4; u++) sf[j][u] = 0.f;
#pragma unroll
        for (int t = 0; t < 4; t++) {
            const int kb = t * 16 + tg * 2;
#pragma unroll
            for (int j = 0; j < 8; j++) {
                const int ba = (j * 8 + g) * KSTR + kb;
                const uint32_t bh0 = *(const uint32_t*)&sK[0][ba];
                const uint32_t bh1 = *(const uint32_t*)&sK[0][ba + 8];
                const uint32_t bl0 = *(const uint32_t*)&sK[1][ba];
                const uint32_t bl1 = *(const uint32_t*)&sK[1][ba + 8];
                MMA16816(sf[j], aq[0][t], bh0, bh1);
                MMA16816(sf[j], aq[1][t], bh0, bh1);
                MMA16816(sf[j], aq[0][t], bl0, bl1);
            }
        }

        const float* sw0 = SW + ((size_t)h * Ssz + i0) * Ssz + k0;
        const float* sw1 = SW + ((size_t)h * Ssz + i1) * Ssz + k0;
        const bool needmask = (k0 + 63 >= i0);
#pragma unroll
        for (int j = 0; j < 8; j++) {
            const int c = j * 8 + tg * 2;
            const float2 w0 = *(const float2*)(sw0 + c);
            const float2 w1 = *(const float2*)(sw1 + c);
            sf[j][0] = sf[j][0] * scale + w0.x;
            sf[j][1] = sf[j][1] * scale + w0.y;
            sf[j][2] = sf[j][2] * scale + w1.x;
            sf[j][3] = sf[j][3] * scale + w1.y;
            if (needmask) {
                const int gc = k0 + c;
                if (gc     >= i0) sf[j][0] = -CUDART_INF_F;
                if (gc + 1 >= i0) sf[j][1] = -CUDART_INF_F;
                if (gc     >= i1) sf[j][2] = -CUDART_INF_F;
                if (gc + 1 >= i1) sf[j][3] = -CUDART_INF_F;
            }
        }

        float r0m = -CUDART_INF_F, r1m = -CUDART_INF_F;
#pragma unroll
        for (int j = 0; j < 8; j++) {
            r0m = fmaxf(r0m, fmaxf(sf[j][0], sf[j][1]));
            r1m = fmaxf(r1m, fmaxf(sf[j][2], sf[j][3]));
        }
        r0m = fmaxf(r0m, __shfl_xor_sync(0xffffffffu, r0m, 1));
        r0m = fmaxf(r0m, __shfl_xor_sync(0xffffffffu, r0m, 2));
        r1m = fmaxf(r1m, __shfl_xor_sync(0xffffffffu, r1m, 1));
        r1m = fmaxf(r1m, __shfl_xor_sync(0xffffffffu, r1m, 2));

        const float mn0 = fmaxf(m0, r0m), mn1 = fmaxf(m1, r1m);
        const float corr0 = (mn0 == -CUDART_INF_F) ? 0.f : __expf(m0 - mn0);
        const float corr1 = (mn1 == -CUDART_INF_F) ? 0.f : __expf(m1 - mn1);

        float rs0 = 0.f, rs1 = 0.f;
        uint32_t ph[4][4], pl[4][4];
#pragma unroll
        for (int t = 0; t < 4; t++) {
            float pv[2][4];
#pragma unroll
            for (int u = 0; u < 2; u++) {
                const int j = 2 * t + u;
#pragma unroll
                for (int r = 0; r < 4; r++) {
                    const float e = sf[j][r];
                    const float mm = (r < 2) ? mn0 : mn1;
                    float p = (e == -CUDART_INF_F) ? 0.f : __expf(e - mm);
                    pv[u][r] = p;
                    if (r < 2) rs0 += p; else rs1 += p;
                }
            }
            float lo[2][4];
#pragma unroll
            for (int u = 0; u < 2; u++)
#pragma unroll
                for (int r = 0; r < 4; r++) {
                    __nv_bfloat16 hb = __float2bfloat16_rn(pv[u][r]);
                    lo[u][r] = pv[u][r] - __bfloat162float(hb);
                }
            ph[t][0] = pack2bf(pv[0][0], pv[0][1]);
            ph[t][1] = pack2bf(pv[0][2], pv[0][3]);
            ph[t][2] = pack2bf(pv[1][0], pv[1][1]);
            ph[t][3] = pack2bf(pv[1][2], pv[1][3]);
            pl[t][0] = pack2bf(lo[0][0], lo[0][1]);
            pl[t][1] = pack2bf(lo[0][2], lo[0][3]);
            pl[t][2] = pack2bf(lo[1][0], lo[1][1]);
            pl[t][3] = pack2bf(lo[1][2], lo[1][3]);
        }
        rs0 += __shfl_xor_sync(0xffffffffu, rs0, 1);
        rs0 += __shfl_xor_sync(0xffffffffu, rs0, 2);
        rs1 += __shfl_xor_sync(0xffffffffu, rs1, 1);
        rs1 += __shfl_xor_sync(0xffffffffu, rs1, 2);

        l0 = l0 * corr0 + rs0;
        l1 = l1 * corr1 + rs1;
        m0 = mn0; m1 = mn1;
#pragma unroll
        for (int d = 0; d < 8; d++) {
            o[d][0] *= corr0; o[d][1] *= corr0;
            o[d][2] *= corr1; o[d][3] *= corr1;
        }

#pragma unroll
        for (int t = 0; t < 4; t++) {
            const int kb = t * 16 + tg * 2;
#pragma unroll
            for (int d = 0; d < 8; d++) {
                const int ba = (d * 8 + g) * KSTR + kb;
                const uint32_t vh0 = *(const uint32_t*)&sV[0][ba];
                const uint32_t vh1 = *(const uint32_t*)&sV[0][ba + 8];
                const uint32_t vl0 = *(const uint32_t*)&sV[1][ba];
                const uint32_t vl1 = *(const uint32_t*)&sV[1][ba + 8];
                MMA16816(o[d], ph[t], vh0, vh1);
                MMA16816(o[d], pl[t], vh0, vh1);
                MMA16816(o[d], ph[t], vl0, vl1);
            }
        }
    }

    const float inv0 = (l0 > 0.f) ? (1.f / l0) : 0.f;
    const float inv1 = (l1 > 0.f) ? (1.f / l1) : 0.f;
    const size_t ob = ((size_t)b * Ssz) * Dsz + (size_t)h * DKsz;
#pragma unroll
    for (int d = 0; d < 8; d++) {
        const int col = d * 8 + tg * 2;
        float v00 = o[d][0] * inv0, v01 = o[d][1] * inv0;
        float v10 = o[d][2] * inv1, v11 = o[d][3] * inv1;
        __nv_bfloat16 h00 = __float2bfloat16_rn(v00);
        __nv_bfloat16 h01 = __float2bfloat16_rn(v01);
        __nv_bfloat16 h10 = __float2bfloat16_rn(v10);
        __nv_bfloat16 h11 = __float2bfloat16_rn(v11);
        const size_t o0 = ob + (size_t)i0 * Dsz + col;
        const size_t o1 = ob + (size_t)i1 * Dsz + col;
        *(uint32_t*)(ctx_h + o0) =
            (uint32_t)*(uint16_t*)&h00 | ((uint32_t)*(uint16_t*)&h01 << 16);
        *(uint32_t*)(ctx_h + o1) =
            (uint32_t)*(uint16_t*)&h10 | ((uint32_t)*(uint16_t*)&h11 << 16);
        *(uint32_t*)(ctx_l + o0) = pack2bf(v00 - __bfloat162float(h00),
                                           v01 - __bfloat162float(h01));
        *(uint32_t*)(ctx_l + o1) = pack2bf(v10 - __bfloat162float(h10),
                                           v11 - __bfloat162float(h11));
    }
}

// ---------------------------------------------------------------------------
__global__ __launch_bounds__(256) void residual_ln(
    const float* __restrict__ x0, const float* __restrict__ y,
    const float* __restrict__ gamma, const float* __restrict__ beta,
    float* __restrict__ out)
{
    const int row = blockIdx.x;
    const float* a = x0 + (size_t)row * Dsz;
    const float* c = y  + (size_t)row * Dsz;
    const int tid = threadIdx.x;

    float v[4];
    float sum = 0.f, sumsq = 0.f;
#pragma unroll
    for (int u = 0; u < 4; u++) {
        int idx = tid + u * 256;
        float t = a[idx] + c[idx];
        v[u] = t;
        sum += t;
        sumsq += t * t;
    }
#pragma unroll
    for (int off = 16; off; off >>= 1) {
        sum   += __shfl_xor_sync(0xffffffffu, sum, off);
        sumsq += __shfl_xor_sync(0xffffffffu, sumsq, off);
    }
    __shared__ float s1[8], s2[8];
    if ((tid & 31) == 0) { s1[tid >> 5] = sum; s2[tid >> 5] = sumsq; }
    __syncthreads();
    if (tid < 32) {
        sum   = (tid < 8) ? s1[tid] : 0.f;
        sumsq = (tid < 8) ? s2[tid] : 0.f;
#pragma unroll
        for (int off = 4; off; off >>= 1) {
            sum   += __shfl_xor_sync(0xffffffffu, sum, off);
            sumsq += __shfl_xor_sync(0xffffffffu, sumsq, off);
        }
        if (tid == 0) { s1[0] = sum; s2[0] = sumsq; }
    }
    __syncthreads();
    const float mu   = s1[0] * (1.f / Dsz);
    const float var  = s2[0] * (1.f / Dsz) - mu * mu;
    const float rstd = rsqrtf(var + 1e-5f);

    float* op = out + (size_t)row * Dsz;
#pragma unroll
    for (int u = 0; u < 4; u++) {
        int idx = tid + u * 256;
        op[idx] = (v[u] - mu) * rstd * gamma[idx] + beta[idx];
    }
}

// ---------------------------------------------------------------------------
extern "C" void kernel_launch(void* const* d_in, const int* in_sizes, int n_in,
                              void* d_out, int out_size)
{
    const float* query  = (const float*)d_in[0];
    const float* key    = (const float*)d_in[1];
    const float* values = (const float*)d_in[2];
    // d_in[3] = lens (unused by reference)
    const float* sw     = (const float*)d_in[4];
    const float* Wq     = (const float*)d_in[5];
    const float* bq     = (const float*)d_in[6];
    const float* Wv     = (const float*)d_in[7];
    const float* bv     = (const float*)d_in[8];
    const float* Wo     = (const float*)d_in[9];
    const float* bo     = (const float*)d_in[10];
    const float* gamma  = (const float*)d_in[11];
    const float* beta   = (const float*)d_in[12];
    float* out = (float*)d_out;

    __nv_bfloat16 *xqh, *xql, *xkh, *xkl, *xvh, *xvl;
    __nv_bfloat16 *Qh, *Ql, *Kh, *Kl, *Vh, *Vl, *vth, *vtl, *ch, *cl;
    __nv_bfloat16 *wqh, *wql, *wvh, *wvl, *woh, *wol;
    float* Op;
    cudaGetSymbolAddress((void**)&xqh, g_xqh); cudaGetSymbolAddress((void**)&xql, g_xql);
    cudaGetSymbolAddress((void**)&xkh, g_xkh); cudaGetSymbolAddress((void**)&xkl, g_xkl);
    cudaGetSymbolAddress((void**)&xvh, g_xvh); cudaGetSymbolAddress((void**)&xvl, g_xvl);
    cudaGetSymbolAddress((void**)&Qh, g_Qh);   cudaGetSymbolAddress((void**)&Ql, g_Ql);
    cudaGetSymbolAddress((void**)&Kh, g_Kh);   cudaGetSymbolAddress((void**)&Kl, g_Kl);
    cudaGetSymbolAddress((void**)&Vh, g_Vh);   cudaGetSymbolAddress((void**)&Vl, g_Vl);
    cudaGetSymbolAddress((void**)&vth, g_vth); cudaGetSymbolAddress((void**)&vtl, g_vtl);
    cudaGetSymbolAddress((void**)&ch, g_ch);   cudaGetSymbolAddress((void**)&cl, g_cl);
    cudaGetSymbolAddress((void**)&wqh, g_wqh); cudaGetSymbolAddress((void**)&wql, g_wql);
    cudaGetSymbolAddress((void**)&wvh, g_wvh); cudaGetSymbolAddress((void**)&wvl, g_wvl);
    cudaGetSymbolAddress((void**)&woh, g_woh); cudaGetSymbolAddress((void**)&wol, g_wol);
    cudaGetSymbolAddress((void**)&Op, g_O);

    const int nblk = (int)(NELEM / 1024);
    split_f32<<<nblk, 256>>>(query,  xqh, xql);
    split_f32<<<nblk, 256>>>(key,    xkh, xkl);
    split_f32<<<nblk, 256>>>(values, xvh, xvl);

    dim3 tb(32, 8);
    transpose_split_w<<<dim3(32, 32), tb>>>(Wq, wqh, wql);
    transpose_split_w<<<dim3(32, 32), tb>>>(Wv, wvh, wvl);
    transpose_split_w<<<dim3(32, 32), tb>>>(Wo, woh, wol);

    // merged Q/K/V projections
    GemmArgs qkv = {};
    qkv.Ah[0] = xqh; qkv.Al[0] = xql; qkv.Bh[0] = wqh; qkv.Bl[0] = wql;
    qkv.bias[0] = bq; qkv.Ch[0] = Qh; qkv.Cl[0] = Ql;
    qkv.Ah[1] = xkh; qkv.Al[1] = xkl; qkv.Bh[1] = wqh; qkv.Bl[1] = wql;
    qkv.bias[1] = bq; qkv.Ch[1] = Kh; qkv.Cl[1] = Kl;
    qkv.Ah[2] = xvh; qkv.Al[2] = xvl; qkv.Bh[2] = wvh; qkv.Bl[2] = wvl;
    qkv.bias[2] = bv; qkv.Ch[2] = Vh; qkv.Cl[2] = Vl;
    dim3 gq(Dsz / 128, Msz / 128, 3);
    gemm_pipe<true><<<gq, 256>>>(qkv, Msz, Dsz, Dsz);

    transpose_v<<<dim3(Ssz / 32, DKsz / 32, Bsz * Hsz), tb>>>(Vh, Vl, vth, vtl);

    flash_attn_mma<<<dim3(Ssz / 128, Hsz, Bsz), 256>>>(Qh, Ql, Kh, Kl, vth, vtl,
                                                       sw, ch, cl);

    GemmArgs og = {};
    og.Ah[0] = ch; og.Al[0] = cl; og.Bh[0] = woh; og.Bl[0] = wol;
    og.bias[0] = bo; og.Cf[0] = Op;
    dim3 go(Dsz / 128, Msz / 128, 1);
    gemm_pipe<false><<<go, 256>>>(og, Msz, Dsz, Dsz);

    residual_ln<<<Msz, 256>>>(query, Op, gamma, beta, out);
}

// round 7
// speedup vs baseline: 4.3389x; 1.0197x over previous
#include <cuda_runtime.h>
#include <cuda_bf16.h>
#include <math_constants.h>
#include <cstdint>

// ---------------------------------------------------------------------------
// DTransformerLayer: B=4, S=1024, D=1024, H=16, DK=64
// R7 (= R6 resubmit; R6 bench died with a container-level failure and the
// source audits clean): GEMMs with ldmatrix fragment loads + 3-stage
// cp.async pipeline; merged split/transpose launches; mma flash attention.
// ---------------------------------------------------------------------------

#define Bsz 4
#define Ssz 1024
#define Dsz 1024
#define Hsz 16
#define DKsz 64
#define Msz (Bsz * Ssz)            // 4096
#define NELEM ((size_t)Msz * Dsz)  // 4M
#define WELEM ((size_t)Dsz * Dsz)  // 1M

__device__ __nv_bfloat16 g_xqh[NELEM], g_xql[NELEM];
__device__ __nv_bfloat16 g_xkh[NELEM], g_xkl[NELEM];
__device__ __nv_bfloat16 g_xvh[NELEM], g_xvl[NELEM];
__device__ __nv_bfloat16 g_Qh[NELEM], g_Ql[NELEM];
__device__ __nv_bfloat16 g_Kh[NELEM], g_Kl[NELEM];
__device__ __nv_bfloat16 g_Vh[NELEM], g_Vl[NELEM];
__device__ __nv_bfloat16 g_vth[NELEM], g_vtl[NELEM];
__device__ __nv_bfloat16 g_ch[NELEM], g_cl[NELEM];
__device__ __nv_bfloat16 g_wqh[WELEM], g_wql[WELEM];
__device__ __nv_bfloat16 g_wvh[WELEM], g_wvl[WELEM];
__device__ __nv_bfloat16 g_woh[WELEM], g_wol[WELEM];
__device__ float g_O[NELEM];

__device__ __forceinline__ uint32_t pack2bf(float a, float b) {
    __nv_bfloat162 t = __floats2bfloat162_rn(a, b);
    return *(uint32_t*)&t;
}

__device__ __forceinline__ void cp_async16(uint32_t dst_sm, const void* src) {
    asm volatile("cp.async.cg.shared.global [%0], [%1], 16;\n"
                 :: "r"(dst_sm), "l"(src));
}
#define CP_COMMIT() asm volatile("cp.async.commit_group;\n" ::: "memory")
#define CP_WAIT1()  asm volatile("cp.async.wait_group 1;\n" ::: "memory")

__device__ __forceinline__ void ldsm_x4(uint32_t& r0, uint32_t& r1,
                                        uint32_t& r2, uint32_t& r3,
                                        uint32_t addr) {
    asm volatile("ldmatrix.sync.aligned.m8n8.x4.shared.b16 {%0,%1,%2,%3}, [%4];"
                 : "=r"(r0), "=r"(r1), "=r"(r2), "=r"(r3) : "r"(addr));
}

// ---------------------------------------------------------------------------
struct Split3Args {
    const float* x[3];
    __nv_bfloat16 *hi[3], *lo[3];
};

__global__ __launch_bounds__(256) void split3(Split3Args a)
{
    const int z = blockIdx.y;
    const size_t i = ((size_t)blockIdx.x * 256 + threadIdx.x) * 4;
    float4 v = *(const float4*)(a.x[z] + i);
    float vv[4] = {v.x, v.y, v.z, v.w};
    __nv_bfloat16 h[4], l[4];
#pragma unroll
    for (int u = 0; u < 4; u++) {
        h[u] = __float2bfloat16_rn(vv[u]);
        l[u] = __float2bfloat16_rn(vv[u] - __bfloat162float(h[u]));
    }
    *(uint2*)(a.hi[z] + i) = *(uint2*)h;
    *(uint2*)(a.lo[z] + i) = *(uint2*)l;
}

// ---------------------------------------------------------------------------
struct TW3Args {
    const float* w[3];
    __nv_bfloat16 *hi[3], *lo[3];
};

__global__ __launch_bounds__(256) void transpose_split_w3(TW3Args a)
{
    __shared__ float t[32][33];
    const int z = blockIdx.z;
    const float* __restrict__ w = a.w[z];
    const int bx = blockIdx.x * 32;
    const int by = blockIdx.y * 32;
    const int tx = threadIdx.x, ty = threadIdx.y;
#pragma unroll
    for (int i = 0; i < 4; i++)
        t[ty + 8 * i][tx] = w[(size_t)(by + ty + 8 * i) * Dsz + bx + tx];
    __syncthreads();
#pragma unroll
    for (int i = 0; i < 4; i++) {
        float v = t[tx][ty + 8 * i];
        __nv_bfloat16 h = __float2bfloat16_rn(v);
        __nv_bfloat16 l = __float2bfloat16_rn(v - __bfloat162float(h));
        const size_t o = (size_t)(bx + ty + 8 * i) * Dsz + by + tx;
        a.hi[z][o] = h;
        a.lo[z][o] = l;
    }
}

// ---------------------------------------------------------------------------
__global__ __launch_bounds__(256) void transpose_v(
    const __nv_bfloat16* __restrict__ vh, const __nv_bfloat16* __restrict__ vl,
    __nv_bfloat16* __restrict__ vth, __nv_bfloat16* __restrict__ vtl)
{
    __shared__ __nv_bfloat16 th[32][33], tl[32][33];
    const int s0 = blockIdx.x * 32, d0 = blockIdx.y * 32;
    const int bh = blockIdx.z, b = bh >> 4, h = bh & 15;
    const int tx = threadIdx.x, ty = threadIdx.y;
#pragma unroll
    for (int i = 0; i < 4; i++) {
        const size_t src = ((size_t)b * Ssz + s0 + ty + 8 * i) * Dsz + h * DKsz + d0 + tx;
        th[ty + 8 * i][tx] = vh[src];
        tl[ty + 8 * i][tx] = vl[src];
    }
    __syncthreads();
#pragma unroll
    for (int i = 0; i < 4; i++) {
        const size_t dst = (((size_t)b * Hsz + h) * DKsz + d0 + ty + 8 * i) * Ssz + s0 + tx;
        vth[dst] = th[tx][ty + 8 * i];
        vtl[dst] = tl[tx][ty + 8 * i];
    }
}

// ---------------------------------------------------------------------------
// Pipelined bf16x3 GEMM: BM=BN=128, BK=16, 3-stage cp.async, XOR swizzle,
// ldmatrix fragment loads. C = Ahl @ Bhl^T + bias. Batched via blockIdx.z.
// ---------------------------------------------------------------------------
#define MMA16816(d, a, b0, b1)                                              \
    asm volatile(                                                           \
        "mma.sync.aligned.m16n8k16.row.col.f32.bf16.bf16.f32 "              \
        "{%0,%1,%2,%3},{%4,%5,%6,%7},{%8,%9},{%0,%1,%2,%3};"                \
        : "+f"(d[0]), "+f"(d[1]), "+f"(d[2]), "+f"(d[3])                    \
        : "r"(a[0]), "r"(a[1]), "r"(a[2]), "r"(a[3]), "r"(b0), "r"(b1))

__device__ __forceinline__ uint32_t swz_byte(int row, int chunk) {
    return (uint32_t)(row * 32 + ((chunk ^ ((row >> 2) & 1)) << 4));
}

struct GemmArgs {
    const __nv_bfloat16 *Ah[3], *Al[3], *Bh[3], *Bl[3];
    const float* bias[3];
    float* Cf[3];
    __nv_bfloat16 *Ch[3], *Cl[3];
};

template <bool SPLIT>
__global__ __launch_bounds__(256, 2) void gemm_pipe(GemmArgs args, int M, int N, int K)
{
    __shared__ uint32_t sA[3][2][128 * 8];  // [stage][hi/lo]  24 KB
    __shared__ uint32_t sB[3][2][128 * 8];  //                 24 KB

    const int z = blockIdx.z;
    const __nv_bfloat16* __restrict__ Ah = args.Ah[z];
    const __nv_bfloat16* __restrict__ Al = args.Al[z];
    const __nv_bfloat16* __restrict__ Bh = args.Bh[z];
    const __nv_bfloat16* __restrict__ Bl = args.Bl[z];
    const float* __restrict__ bias = args.bias[z];

    const int tid = threadIdx.x;
    const int bm = blockIdx.y * 128, bn = blockIdx.x * 128;
    const int w = tid >> 5, lane = tid & 31;
    const int g = lane >> 2, tg = lane & 3;
    const int wm = w >> 1, wn = w & 1;
    const int l7 = lane & 7, sel = lane >> 3;

    const int lrow = tid >> 1, lch = tid & 1;
    const uint32_t ldst = swz_byte(lrow, lch);
    const size_t gA = (size_t)(bm + lrow) * K + lch * 8;
    const size_t gB = (size_t)(bn + lrow) * K + lch * 8;

    const uint32_t baseA = (uint32_t)__cvta_generic_to_shared(&sA[0][0][0]);
    const uint32_t baseB = (uint32_t)__cvta_generic_to_shared(&sB[0][0][0]);

    float fa[2][8][4];
#pragma unroll
    for (int i = 0; i < 2; i++)
#pragma unroll
        for (int j = 0; j < 8; j++)
#pragma unroll
            for (int u = 0; u < 4; u++) fa[i][j][u] = 0.f;

    const int arow_off = l7 + ((sel & 1) << 3);
    const int achk = sel >> 1;
    const int brow_off = ((sel >> 1) << 3) + l7;
    const int bchk = sel & 1;

    auto load_stage = [&](int st, int kk) {
        const uint32_t so = (uint32_t)st * 8192;
        cp_async16(baseA + so +        ldst, Ah + gA + kk);
        cp_async16(baseA + so + 4096 + ldst, Al + gA + kk);
        cp_async16(baseB + so +        ldst, Bh + gB + kk);
        cp_async16(baseB + so + 4096 + ldst, Bl + gB + kk);
    };

    load_stage(0, 0);  CP_COMMIT();
    load_stage(1, 16); CP_COMMIT();

    int s = 0;
    for (int k0 = 0; k0 < K; k0 += 16) {
        CP_WAIT1();
        __syncthreads();
        {
            const int ns = (s + 2) % 3;
            if (k0 + 32 < K) load_stage(ns, k0 + 32);
            CP_COMMIT();  // empty tail groups keep group accounting uniform
        }

        const uint32_t sAh = baseA + (uint32_t)s * 8192;
        const uint32_t sAl = sAh + 4096;
        const uint32_t sBh = baseB + (uint32_t)s * 8192;
        const uint32_t sBl = sBh + 4096;

        uint32_t a[2][2][4];
#pragma unroll
        for (int i = 0; i < 2; i++) {
            const int rb = wm * 32 + i * 16 + arow_off;
            const uint32_t off = swz_byte(rb, achk);
            ldsm_x4(a[0][i][0], a[0][i][1], a[0][i][2], a[0][i][3], sAh + off);
            ldsm_x4(a[1][i][0], a[1][i][1], a[1][i][2], a[1][i][3], sAl + off);
        }

#pragma unroll
        for (int jp = 0; jp < 4; jp++) {
            const int nb = wn * 64 + jp * 16 + brow_off;
            const uint32_t off = swz_byte(nb, bchk);
            uint32_t bh[4], bl[4];
            ldsm_x4(bh[0], bh[1], bh[2], bh[3], sBh + off);
            ldsm_x4(bl[0], bl[1], bl[2], bl[3], sBl + off);
#pragma unroll
            for (int i = 0; i < 2; i++) {
                MMA16816(fa[i][2 * jp],     a[0][i], bh[0], bh[1]);
                MMA16816(fa[i][2 * jp],     a[1][i], bh[0], bh[1]);
                MMA16816(fa[i][2 * jp],     a[0][i], bl[0], bl[1]);
                MMA16816(fa[i][2 * jp + 1], a[0][i], bh[2], bh[3]);
                MMA16816(fa[i][2 * jp + 1], a[1][i], bh[2], bh[3]);
                MMA16816(fa[i][2 * jp + 1], a[0][i], bl[2], bl[3]);
            }
        }
        s = (s + 1) % 3;
    }

#pragma unroll
    for (int i = 0; i < 2; i++) {
        const int row = bm + wm * 32 + i * 16 + g;
#pragma unroll
        for (int j = 0; j < 8; j++) {
            const int col = bn + wn * 64 + j * 8 + tg * 2;
            const float b0 = bias[col], b1 = bias[col + 1];
            float v00 = fa[i][j][0] + b0, v01 = fa[i][j][1] + b1;
            float v10 = fa[i][j][2] + b0, v11 = fa[i][j][3] + b1;
            if (SPLIT) {
                __nv_bfloat16 h00 = __float2bfloat16_rn(v00);
                __nv_bfloat16 h01 = __float2bfloat16_rn(v01);
                __nv_bfloat16 h10 = __float2bfloat16_rn(v10);
                __nv_bfloat16 h11 = __float2bfloat16_rn(v11);
                const size_t o0 = (size_t)row * N + col;
                const size_t o1 = (size_t)(row + 8) * N + col;
                *(uint32_t*)(args.Ch[z] + o0) =
                    (uint32_t)*(uint16_t*)&h00 | ((uint32_t)*(uint16_t*)&h01 << 16);
                *(uint32_t*)(args.Ch[z] + o1) =
                    (uint32_t)*(uint16_t*)&h10 | ((uint32_t)*(uint16_t*)&h11 << 16);
                *(uint32_t*)(args.Cl[z] + o0) = pack2bf(v00 - __bfloat162float(h00),
                                                        v01 - __bfloat162float(h01));
                *(uint32_t*)(args.Cl[z] + o1) = pack2bf(v10 - __bfloat162float(h10),
                                                        v11 - __bfloat162float(h11));
            } else {
                float2 a2 = {v00, v01}, b2 = {v10, v11};
                *(float2*)&args.Cf[z][(size_t)row * N + col] = a2;
                *(float2*)&args.Cf[z][(size_t)(row + 8) * N + col] = b2;
            }
        }
    }
}

// ---------------------------------------------------------------------------
// mma flash attention (unchanged, passing since R4).
// ---------------------------------------------------------------------------
#define KSTR 72

__global__ __launch_bounds__(256) void flash_attn_mma(
    const __nv_bfloat16* __restrict__ Qh, const __nv_bfloat16* __restrict__ Ql,
    const __nv_bfloat16* __restrict__ Kh, const __nv_bfloat16* __restrict__ Kl,
    const __nv_bfloat16* __restrict__ Vth, const __nv_bfloat16* __restrict__ Vtl,
    const float* __restrict__ SW,
    __nv_bfloat16* __restrict__ ctx_h, __nv_bfloat16* __restrict__ ctx_l)
{
    __shared__ __nv_bfloat16 sK[2][64 * KSTR];
    __shared__ __nv_bfloat16 sV[2][64 * KSTR];

    const int qt = blockIdx.x, h = blockIdx.y, b = blockIdx.z;
    const int tid = threadIdx.x, w = tid >> 5, lane = tid & 31;
    const int g = lane >> 2, tg = lane & 3;
    const int q0 = qt * 128, rw = q0 + w * 16;
    const float scale = 0.125f;

    uint32_t aq[2][4][4];
    {
        const size_t base = ((size_t)b * Ssz) * Dsz + (size_t)h * DKsz;
#pragma unroll
        for (int t = 0; t < 4; t++) {
            const int col = t * 16 + tg * 2;
            const size_t r0 = base + (size_t)(rw + g) * Dsz + col;
            const size_t r1 = base + (size_t)(rw + g + 8) * Dsz + col;
            aq[0][t][0] = *(const uint32_t*)(Qh + r0);
            aq[0][t][1] = *(const uint32_t*)(Qh + r1);
            aq[0][t][2] = *(const uint32_t*)(Qh + r0 + 8);
            aq[0][t][3] = *(const uint32_t*)(Qh + r1 + 8);
            aq[1][t][0] = *(const uint32_t*)(Ql + r0);
            aq[1][t][1] = *(const uint32_t*)(Ql + r1);
            aq[1][t][2] = *(const uint32_t*)(Ql + r0 + 8);
            aq[1][t][3] = *(const uint32_t*)(Ql + r1 + 8);
        }
    }

    const int i0 = rw + g, i1 = rw + g + 8;
    float m0 = -CUDART_INF_F, m1 = -CUDART_INF_F, l0 = 0.f, l1 = 0.f;
    float o[8][4];
#pragma unroll
    for (int d = 0; d < 8; d++)
#pragma unroll
        for (int u = 0; u < 4; u++) o[d][u] = 0.f;

    const int nkt = 2 * qt + 2;
    for (int kt = 0; kt < nkt; kt++) {
        const int k0 = kt * 64;
        __syncthreads();
#pragma unroll
        for (int it = 0; it < 2; it++) {
            const int seg = tid + it * 256;
            const int row = seg >> 3, cc = (seg & 7) * 8;
            const size_t gk = ((size_t)b * Ssz + k0 + row) * Dsz + h * DKsz + cc;
            *(uint4*)&sK[0][row * KSTR + cc] = *(const uint4*)(Kh + gk);
            *(uint4*)&sK[1][row * KSTR + cc] = *(const uint4*)(Kl + gk);
            const size_t gv = (((size_t)b * Hsz + h) * DKsz + row) * Ssz + k0 + cc;
            *(uint4*)&sV[0][row * KSTR + cc] = *(const uint4*)(Vth + gv);
            *(uint4*)&sV[1][row * KSTR + cc] = *(const uint4*)(Vtl + gv);
        }
        __syncthreads();

        if (k0 > rw + 14) continue;

        float sf[8][4];
#pragma unroll
        for (int j = 0; j < 8; j++)
#pragma unroll
            for (int u = 0; u < 4; u++) sf[j][u] = 0.f;
#pragma unroll
        for (int t = 0; t < 4; t++) {
            const int kb = t * 16 + tg * 2;
#pragma unroll
            for (int j = 0; j < 8; j++) {
                const int ba = (j * 8 + g) * KSTR + kb;
                const uint32_t bh0 = *(const uint32_t*)&sK[0][ba];
                const uint32_t bh1 = *(const uint32_t*)&sK[0][ba + 8];
                const uint32_t bl0 = *(const uint32_t*)&sK[1][ba];
                const uint32_t bl1 = *(const uint32_t*)&sK[1][ba + 8];
                MMA16816(sf[j], aq[0][t], bh0, bh1);
                MMA16816(sf[j], aq[1][t], bh0, bh1);
                MMA16816(sf[j], aq[0][t], bl0, bl1);
            }
        }

        const float* sw0 = SW + ((size_t)h * Ssz + i0) * Ssz + k0;
        const float* sw1 = SW + ((size_t)h * Ssz + i1) * Ssz + k0;
        const bool needmask = (k0 + 63 >= i0);
#pragma unroll
        for (int j = 0; j < 8; j++) {
            const int c = j * 8 + tg * 2;
            const float2 w0 = *(const float2*)(sw0 + c);
            const float2 w1 = *(const float2*)(sw1 + c);
            sf[j][0] = sf[j][0] * scale + w0.x;
            sf[j][1] = sf[j][1] * scale + w0.y;
            sf[j][2] = sf[j][2] * scale + w1.x;
            sf[j][3] = sf[j][3] * scale + w1.y;
            if (needmask) {
                const int gc = k0 + c;
                if (gc     >= i0) sf[j][0] = -CUDART_INF_F;
                if (gc + 1 >= i0) sf[j][1] = -CUDART_INF_F;
                if (gc     >= i1) sf[j][2] = -CUDART_INF_F;
                if (gc + 1 >= i1) sf[j][3] = -CUDART_INF_F;
            }
        }

        float r0m = -CUDART_INF_F, r1m = -CUDART_INF_F;
#pragma unroll
        for (int j = 0; j < 8; j++) {
            r0m = fmaxf(r0m, fmaxf(sf[j][0], sf[j][1]));
            r1m = fmaxf(r1m, fmaxf(sf[j][2], sf[j][3]));
        }
        r0m = fmaxf(r0m, __shfl_xor_sync(0xffffffffu, r0m, 1));
        r0m = fmaxf(r0m, __shfl_xor_sync(0xffffffffu, r0m, 2));
        r1m = fmaxf(r1m, __shfl_xor_sync(0xffffffffu, r1m, 1));
        r1m = fmaxf(r1m, __shfl_xor_sync(0xffffffffu, r1m, 2));

        const float mn0 = fmaxf(m0, r0m), mn1 = fmaxf(m1, r1m);
        const float corr0 = (mn0 == -CUDART_INF_F) ? 0.f : __expf(m0 - mn0);
        const float corr1 = (mn1 == -CUDART_INF_F) ? 0.f : __expf(m1 - mn1);

        float rs0 = 0.f, rs1 = 0.f;
        uint32_t ph[4][4], pl[4][4];
#pragma unroll
        for (int t = 0; t < 4; t++) {
            float pv[2][4];
#pragma unroll
            for (int u = 0; u < 2; u++) {
                const int j = 2 * t + u;
#pragma unroll
                for (int r = 0; r < 4; r++) {
                    const float e = sf[j][r];
                    const float mm = (r < 2) ? mn0 : mn1;
                    float p = (e == -CUDART_INF_F) ? 0.f : __expf(e - mm);
                    pv[u][r] = p;
                    if (r < 2) rs0 += p; else rs1 += p;
                }
            }
            float lo[2][4];
#pragma unroll
            for (int u = 0; u < 2; u++)
#pragma unroll
                for (int r = 0; r < 4; r++) {
                    __nv_bfloat16 hb = __float2bfloat16_rn(pv[u][r]);
                    lo[u][r] = pv[u][r] - __bfloat162float(hb);
                }
            ph[t][0] = pack2bf(pv[0][0], pv[0][1]);
            ph[t][1] = pack2bf(pv[0][2], pv[0][3]);
            ph[t][2] = pack2bf(pv[1][0], pv[1][1]);
            ph[t][3] = pack2bf(pv[1][2], pv[1][3]);
            pl[t][0] = pack2bf(lo[0][0], lo[0][1]);
            pl[t][1] = pack2bf(lo[0][2], lo[0][3]);
            pl[t][2] = pack2bf(lo[1][0], lo[1][1]);
            pl[t][3] = pack2bf(lo[1][2], lo[1][3]);
        }
        rs0 += __shfl_xor_sync(0xffffffffu, rs0, 1);
        rs0 += __shfl_xor_sync(0xffffffffu, rs0, 2);
        rs1 += __shfl_xor_sync(0xffffffffu, rs1, 1);
        rs1 += __shfl_xor_sync(0xffffffffu, rs1, 2);

        l0 = l0 * corr0 + rs0;
        l1 = l1 * corr1 + rs1;
        m0 = mn0; m1 = mn1;
#pragma unroll
        for (int d = 0; d < 8; d++) {
            o[d][0] *= corr0; o[d][1] *= corr0;
            o[d][2] *= corr1; o[d][3] *= corr1;
        }

#pragma unroll
        for (int t = 0; t < 4; t++) {
            const int kb = t * 16 + tg * 2;
#pragma unroll
            for (int d = 0; d < 8; d++) {
                const int ba = (d * 8 + g) * KSTR + kb;
                const uint32_t vh0 = *(const uint32_t*)&sV[0][ba];
                const uint32_t vh1 = *(const uint32_t*)&sV[0][ba + 8];
                const uint32_t vl0 = *(const uint32_t*)&sV[1][ba];
                const uint32_t vl1 = *(const uint32_t*)&sV[1][ba + 8];
                MMA16816(o[d], ph[t], vh0, vh1);
                MMA16816(o[d], pl[t], vh0, vh1);
                MMA16816(o[d], ph[t], vl0, vl1);
            }
        }
    }

    const float inv0 = (l0 > 0.f) ? (1.f / l0) : 0.f;
    const float inv1 = (l1 > 0.f) ? (1.f / l1) : 0.f;
    const size_t ob = ((size_t)b * Ssz) * Dsz + (size_t)h * DKsz;
#pragma unroll
    for (int d = 0; d < 8; d++) {
        const int col = d * 8 + tg * 2;
        float v00 = o[d][0] * inv0, v01 = o[d][1] * inv0;
        float v10 = o[d][2] * inv1, v11 = o[d][3] * inv1;
        __nv_bfloat16 h00 = __float2bfloat16_rn(v00);
        __nv_bfloat16 h01 = __float2bfloat16_rn(v01);
        __nv_bfloat16 h10 = __float2bfloat16_rn(v10);
        __nv_bfloat16 h11 = __float2bfloat16_rn(v11);
        const size_t o0 = ob + (size_t)i0 * Dsz + col;
        const size_t o1 = ob + (size_t)i1 * Dsz + col;
        *(uint32_t*)(ctx_h + o0) =
            (uint32_t)*(uint16_t*)&h00 | ((uint32_t)*(uint16_t*)&h01 << 16);
        *(uint32_t*)(ctx_h + o1) =
            (uint32_t)*(uint16_t*)&h10 | ((uint32_t)*(uint16_t*)&h11 << 16);
        *(uint32_t*)(ctx_l + o0) = pack2bf(v00 - __bfloat162float(h00),
                                           v01 - __bfloat162float(h01));
        *(uint32_t*)(ctx_l + o1) = pack2bf(v10 - __bfloat162float(h10),
                                           v11 - __bfloat162float(h11));
    }
}

// ---------------------------------------------------------------------------
__global__ __launch_bounds__(256) void residual_ln(
    const float* __restrict__ x0, const float* __restrict__ y,
    const float* __restrict__ gamma, const float* __restrict__ beta,
    float* __restrict__ out)
{
    const int row = blockIdx.x;
    const float* a = x0 + (size_t)row * Dsz;
    const float* c = y  + (size_t)row * Dsz;
    const int tid = threadIdx.x;

    float v[4];
    float sum = 0.f, sumsq = 0.f;
#pragma unroll
    for (int u = 0; u < 4; u++) {
        int idx = tid + u * 256;
        float t = a[idx] + c[idx];
        v[u] = t;
        sum += t;
        sumsq += t * t;
    }
#pragma unroll
    for (int off = 16; off; off >>= 1) {
        sum   += __shfl_xor_sync(0xffffffffu, sum, off);
        sumsq += __shfl_xor_sync(0xffffffffu, sumsq, off);
    }
    __shared__ float s1[8], s2[8];
    if ((tid & 31) == 0) { s1[tid >> 5] = sum; s2[tid >> 5] = sumsq; }
    __syncthreads();
    if (tid < 32) {
        sum   = (tid < 8) ? s1[tid] : 0.f;
        sumsq = (tid < 8) ? s2[tid] : 0.f;
#pragma unroll
        for (int off = 4; off; off >>= 1) {
            sum   += __shfl_xor_sync(0xffffffffu, sum, off);
            sumsq += __shfl_xor_sync(0xffffffffu, sumsq, off);
        }
        if (tid == 0) { s1[0] = sum; s2[0] = sumsq; }
    }
    __syncthreads();
    const float mu   = s1[0] * (1.f / Dsz);
    const float var  = s2[0] * (1.f / Dsz) - mu * mu;
    const float rstd = rsqrtf(var + 1e-5f);

    float* op = out + (size_t)row * Dsz;
#pragma unroll
    for (int u = 0; u < 4; u++) {
        int idx = tid + u * 256;
        op[idx] = (v[u] - mu) * rstd * gamma[idx] + beta[idx];
    }
}

// ---------------------------------------------------------------------------
extern "C" void kernel_launch(void* const* d_in, const int* in_sizes, int n_in,
                              void* d_out, int out_size)
{
    const float* query  = (const float*)d_in[0];
    const float* key    = (const float*)d_in[1];
    const float* values = (const float*)d_in[2];
    // d_in[3] = lens (unused by reference)
    const float* sw     = (const float*)d_in[4];
    const float* Wq     = (const float*)d_in[5];
    const float* bq     = (const float*)d_in[6];
    const float* Wv     = (const float*)d_in[7];
    const float* bv     = (const float*)d_in[8];
    const float* Wo     = (const float*)d_in[9];
    const float* bo     = (const float*)d_in[10];
    const float* gamma  = (const float*)d_in[11];
    const float* beta   = (const float*)d_in[12];
    float* out = (float*)d_out;

    __nv_bfloat16 *xqh, *xql, *xkh, *xkl, *xvh, *xvl;
    __nv_bfloat16 *Qh, *Ql, *Kh, *Kl, *Vh, *Vl, *vth, *vtl, *ch, *cl;
    __nv_bfloat16 *wqh, *wql, *wvh, *wvl, *woh, *wol;
    float* Op;
    cudaGetSymbolAddress((void**)&xqh, g_xqh); cudaGetSymbolAddress((void**)&xql, g_xql);
    cudaGetSymbolAddress((void**)&xkh, g_xkh); cudaGetSymbolAddress((void**)&xkl, g_xkl);
    cudaGetSymbolAddress((void**)&xvh, g_xvh); cudaGetSymbolAddress((void**)&xvl, g_xvl);
    cudaGetSymbolAddress((void**)&Qh, g_Qh);   cudaGetSymbolAddress((void**)&Ql, g_Ql);
    cudaGetSymbolAddress((void**)&Kh, g_Kh);   cudaGetSymbolAddress((void**)&Kl, g_Kl);
    cudaGetSymbolAddress((void**)&Vh, g_Vh);   cudaGetSymbolAddress((void**)&Vl, g_Vl);
    cudaGetSymbolAddress((void**)&vth, g_vth); cudaGetSymbolAddress((void**)&vtl, g_vtl);
    cudaGetSymbolAddress((void**)&ch, g_ch);   cudaGetSymbolAddress((void**)&cl, g_cl);
    cudaGetSymbolAddress((void**)&wqh, g_wqh); cudaGetSymbolAddress((void**)&wql, g_wql);
    cudaGetSymbolAddress((void**)&wvh, g_wvh); cudaGetSymbolAddress((void**)&wvl, g_wvl);
    cudaGetSymbolAddress((void**)&woh, g_woh); cudaGetSymbolAddress((void**)&wol, g_wol);
    cudaGetSymbolAddress((void**)&Op, g_O);

    Split3Args sp = {};
    sp.x[0] = query;  sp.hi[0] = xqh; sp.lo[0] = xql;
    sp.x[1] = key;    sp.hi[1] = xkh; sp.lo[1] = xkl;
    sp.x[2] = values; sp.hi[2] = xvh; sp.lo[2] = xvl;
    split3<<<dim3((unsigned)(NELEM / 1024), 3), 256>>>(sp);

    TW3Args tw = {};
    tw.w[0] = Wq; tw.hi[0] = wqh; tw.lo[0] = wql;
    tw.w[1] = Wv; tw.hi[1] = wvh; tw.lo[1] = wvl;
    tw.w[2] = Wo; tw.hi[2] = woh; tw.lo[2] = wol;
    transpose_split_w3<<<dim3(32, 32, 3), dim3(32, 8)>>>(tw);

    GemmArgs qkv = {};
    qkv.Ah[0] = xqh; qkv.Al[0] = xql; qkv.Bh[0] = wqh; qkv.Bl[0] = wql;
    qkv.bias[0] = bq; qkv.Ch[0] = Qh; qkv.Cl[0] = Ql;
    qkv.Ah[1] = xkh; qkv.Al[1] = xkl; qkv.Bh[1] = wqh; qkv.Bl[1] = wql;
    qkv.bias[1] = bq; qkv.Ch[1] = Kh; qkv.Cl[1] = Kl;
    qkv.Ah[2] = xvh; qkv.Al[2] = xvl; qkv.Bh[2] = wvh; qkv.Bl[2] = wvl;
    qkv.bias[2] = bv; qkv.Ch[2] = Vh; qkv.Cl[2] = Vl;
    dim3 gq(Dsz / 128, Msz / 128, 3);
    gemm_pipe<true><<<gq, 256>>>(qkv, Msz, Dsz, Dsz);

    transpose_v<<<dim3(Ssz / 32, DKsz / 32, Bsz * Hsz), dim3(32, 8)>>>(Vh, Vl, vth, vtl);

    flash_attn_mma<<<dim3(Ssz / 128, Hsz, Bsz), 256>>>(Qh, Ql, Kh, Kl, vth, vtl,
                                                       sw, ch, cl);

    GemmArgs og = {};
    og.Ah[0] = ch; og.Al[0] = cl; og.Bh[0] = woh; og.Bl[0] = wol;
    og.bias[0] = bo; og.Cf[0] = Op;
    dim3 go(Dsz / 128, Msz / 128, 1);
    gemm_pipe<false><<<go, 256>>>(og, Msz, Dsz, Dsz);

    residual_ln<<<Msz, 256>>>(query, Op, gamma, beta, out);
}

// round 9
// speedup vs baseline: 4.4060x; 1.0155x over previous
#include <cuda_runtime.h>
#include <cuda_bf16.h>
#include <math_constants.h>
#include <cstdint>

// ---------------------------------------------------------------------------
// DTransformerLayer: B=4, S=1024, D=1024, H=16, DK=64
// R9 (= R8 resubmit; R8 died with the same container-level failure that a
// byte-identical resubmit cured in R6->R7, and the source audits clean):
// attention with cp.async pipelined K/V tiles (K double-buffered, V
// latency-hidden), ldmatrix(+trans) fragment loads from XOR-swizzled smem,
// natural-layout V (no transpose_v kernel). GEMMs unchanged from R7.
// ---------------------------------------------------------------------------

#define Bsz 4
#define Ssz 1024
#define Dsz 1024
#define Hsz 16
#define DKsz 64
#define Msz (Bsz * Ssz)            // 4096
#define NELEM ((size_t)Msz * Dsz)  // 4M
#define WELEM ((size_t)Dsz * Dsz)  // 1M

__device__ __nv_bfloat16 g_xqh[NELEM], g_xql[NELEM];
__device__ __nv_bfloat16 g_xkh[NELEM], g_xkl[NELEM];
__device__ __nv_bfloat16 g_xvh[NELEM], g_xvl[NELEM];
__device__ __nv_bfloat16 g_Qh[NELEM], g_Ql[NELEM];
__device__ __nv_bfloat16 g_Kh[NELEM], g_Kl[NELEM];
__device__ __nv_bfloat16 g_Vh[NELEM], g_Vl[NELEM];
__device__ __nv_bfloat16 g_ch[NELEM], g_cl[NELEM];
__device__ __nv_bfloat16 g_wqh[WELEM], g_wql[WELEM];
__device__ __nv_bfloat16 g_wvh[WELEM], g_wvl[WELEM];
__device__ __nv_bfloat16 g_woh[WELEM], g_wol[WELEM];
__device__ float g_O[NELEM];

__device__ __forceinline__ uint32_t pack2bf(float a, float b) {
    __nv_bfloat162 t = __floats2bfloat162_rn(a, b);
    return *(uint32_t*)&t;
}

__device__ __forceinline__ void cp_async16(uint32_t dst_sm, const void* src) {
    asm volatile("cp.async.cg.shared.global [%0], [%1], 16;\n"
                 :: "r"(dst_sm), "l"(src));
}
#define CP_COMMIT() asm volatile("cp.async.commit_group;\n" ::: "memory")
#define CP_WAIT1()  asm volatile("cp.async.wait_group 1;\n" ::: "memory")
#define CP_WAIT2()  asm volatile("cp.async.wait_group 2;\n" ::: "memory")

__device__ __forceinline__ void ldsm_x4(uint32_t& r0, uint32_t& r1,
                                        uint32_t& r2, uint32_t& r3,
                                        uint32_t addr) {
    asm volatile("ldmatrix.sync.aligned.m8n8.x4.shared.b16 {%0,%1,%2,%3}, [%4];"
                 : "=r"(r0), "=r"(r1), "=r"(r2), "=r"(r3) : "r"(addr));
}
__device__ __forceinline__ void ldsm_x4t(uint32_t& r0, uint32_t& r1,
                                         uint32_t& r2, uint32_t& r3,
                                         uint32_t addr) {
    asm volatile("ldmatrix.sync.aligned.m8n8.x4.trans.shared.b16 {%0,%1,%2,%3}, [%4];"
                 : "=r"(r0), "=r"(r1), "=r"(r2), "=r"(r3) : "r"(addr));
}

// ---------------------------------------------------------------------------
struct Split3Args {
    const float* x[3];
    __nv_bfloat16 *hi[3], *lo[3];
};

__global__ __launch_bounds__(256) void split3(Split3Args a)
{
    const int z = blockIdx.y;
    const size_t i = ((size_t)blockIdx.x * 256 + threadIdx.x) * 4;
    float4 v = *(const float4*)(a.x[z] + i);
    float vv[4] = {v.x, v.y, v.z, v.w};
    __nv_bfloat16 h[4], l[4];
#pragma unroll
    for (int u = 0; u < 4; u++) {
        h[u] = __float2bfloat16_rn(vv[u]);
        l[u] = __float2bfloat16_rn(vv[u] - __bfloat162float(h[u]));
    }
    *(uint2*)(a.hi[z] + i) = *(uint2*)h;
    *(uint2*)(a.lo[z] + i) = *(uint2*)l;
}

// ---------------------------------------------------------------------------
struct TW3Args {
    const float* w[3];
    __nv_bfloat16 *hi[3], *lo[3];
};

__global__ __launch_bounds__(256) void transpose_split_w3(TW3Args a)
{
    __shared__ float t[32][33];
    const int z = blockIdx.z;
    const float* __restrict__ w = a.w[z];
    const int bx = blockIdx.x * 32;
    const int by = blockIdx.y * 32;
    const int tx = threadIdx.x, ty = threadIdx.y;
#pragma unroll
    for (int i = 0; i < 4; i++)
        t[ty + 8 * i][tx] = w[(size_t)(by + ty + 8 * i) * Dsz + bx + tx];
    __syncthreads();
#pragma unroll
    for (int i = 0; i < 4; i++) {
        float v = t[tx][ty + 8 * i];
        __nv_bfloat16 h = __float2bfloat16_rn(v);
        __nv_bfloat16 l = __float2bfloat16_rn(v - __bfloat162float(h));
        const size_t o = (size_t)(bx + ty + 8 * i) * Dsz + by + tx;
        a.hi[z][o] = h;
        a.lo[z][o] = l;
    }
}

// ---------------------------------------------------------------------------
// Pipelined bf16x3 GEMM (unchanged from R7, passing).
// ---------------------------------------------------------------------------
#define MMA16816(d, a, b0, b1)                                              \
    asm volatile(                                                           \
        "mma.sync.aligned.m16n8k16.row.col.f32.bf16.bf16.f32 "              \
        "{%0,%1,%2,%3},{%4,%5,%6,%7},{%8,%9},{%0,%1,%2,%3};"                \
        : "+f"(d[0]), "+f"(d[1]), "+f"(d[2]), "+f"(d[3])                    \
        : "r"(a[0]), "r"(a[1]), "r"(a[2]), "r"(a[3]), "r"(b0), "r"(b1))

__device__ __forceinline__ uint32_t swz_byte(int row, int chunk) {
    return (uint32_t)(row * 32 + ((chunk ^ ((row >> 2) & 1)) << 4));
}

struct GemmArgs {
    const __nv_bfloat16 *Ah[3], *Al[3], *Bh[3], *Bl[3];
    const float* bias[3];
    float* Cf[3];
    __nv_bfloat16 *Ch[3], *Cl[3];
};

template <bool SPLIT>
__global__ __launch_bounds__(256, 2) void gemm_pipe(GemmArgs args, int M, int N, int K)
{
    __shared__ uint32_t sA[3][2][128 * 8];
    __shared__ uint32_t sB[3][2][128 * 8];

    const int z = blockIdx.z;
    const __nv_bfloat16* __restrict__ Ah = args.Ah[z];
    const __nv_bfloat16* __restrict__ Al = args.Al[z];
    const __nv_bfloat16* __restrict__ Bh = args.Bh[z];
    const __nv_bfloat16* __restrict__ Bl = args.Bl[z];
    const float* __restrict__ bias = args.bias[z];

    const int tid = threadIdx.x;
    const int bm = blockIdx.y * 128, bn = blockIdx.x * 128;
    const int w = tid >> 5, lane = tid & 31;
    const int g = lane >> 2, tg = lane & 3;
    const int wm = w >> 1, wn = w & 1;
    const int l7 = lane & 7, sel = lane >> 3;

    const int lrow = tid >> 1, lch = tid & 1;
    const uint32_t ldst = swz_byte(lrow, lch);
    const size_t gA = (size_t)(bm + lrow) * K + lch * 8;
    const size_t gB = (size_t)(bn + lrow) * K + lch * 8;

    const uint32_t baseA = (uint32_t)__cvta_generic_to_shared(&sA[0][0][0]);
    const uint32_t baseB = (uint32_t)__cvta_generic_to_shared(&sB[0][0][0]);

    float fa[2][8][4];
#pragma unroll
    for (int i = 0; i < 2; i++)
#pragma unroll
        for (int j = 0; j < 8; j++)
#pragma unroll
            for (int u = 0; u < 4; u++) fa[i][j][u] = 0.f;

    const int arow_off = l7 + ((sel & 1) << 3);
    const int achk = sel >> 1;
    const int brow_off = ((sel >> 1) << 3) + l7;
    const int bchk = sel & 1;

    auto load_stage = [&](int st, int kk) {
        const uint32_t so = (uint32_t)st * 8192;
        cp_async16(baseA + so +        ldst, Ah + gA + kk);
        cp_async16(baseA + so + 4096 + ldst, Al + gA + kk);
        cp_async16(baseB + so +        ldst, Bh + gB + kk);
        cp_async16(baseB + so + 4096 + ldst, Bl + gB + kk);
    };

    load_stage(0, 0);  CP_COMMIT();
    load_stage(1, 16); CP_COMMIT();

    int s = 0;
    for (int k0 = 0; k0 < K; k0 += 16) {
        CP_WAIT1();
        __syncthreads();
        {
            const int ns = (s + 2) % 3;
            if (k0 + 32 < K) load_stage(ns, k0 + 32);
            CP_COMMIT();
        }

        const uint32_t sAh = baseA + (uint32_t)s * 8192;
        const uint32_t sAl = sAh + 4096;
        const uint32_t sBh = baseB + (uint32_t)s * 8192;
        const uint32_t sBl = sBh + 4096;

        uint32_t a[2][2][4];
#pragma unroll
        for (int i = 0; i < 2; i++) {
            const int rb = wm * 32 + i * 16 + arow_off;
            const uint32_t off = swz_byte(rb, achk);
            ldsm_x4(a[0][i][0], a[0][i][1], a[0][i][2], a[0][i][3], sAh + off);
            ldsm_x4(a[1][i][0], a[1][i][1], a[1][i][2], a[1][i][3], sAl + off);
        }

#pragma unroll
        for (int jp = 0; jp < 4; jp++) {
            const int nb = wn * 64 + jp * 16 + brow_off;
            const uint32_t off = swz_byte(nb, bchk);
            uint32_t bh[4], bl[4];
            ldsm_x4(bh[0], bh[1], bh[2], bh[3], sBh + off);
            ldsm_x4(bl[0], bl[1], bl[2], bl[3], sBl + off);
#pragma unroll
            for (int i = 0; i < 2; i++) {
                MMA16816(fa[i][2 * jp],     a[0][i], bh[0], bh[1]);
                MMA16816(fa[i][2 * jp],     a[1][i], bh[0], bh[1]);
                MMA16816(fa[i][2 * jp],     a[0][i], bl[0], bl[1]);
                MMA16816(fa[i][2 * jp + 1], a[0][i], bh[2], bh[3]);
                MMA16816(fa[i][2 * jp + 1], a[1][i], bh[2], bh[3]);
                MMA16816(fa[i][2 * jp + 1], a[0][i], bl[2], bl[3]);
            }
        }
        s = (s + 1) % 3;
    }

#pragma unroll
    for (int i = 0; i < 2; i++) {
        const int row = bm + wm * 32 + i * 16 + g;
#pragma unroll
        for (int j = 0; j < 8; j++) {
            const int col = bn + wn * 64 + j * 8 + tg * 2;
            const float b0 = bias[col], b1 = bias[col + 1];
            float v00 = fa[i][j][0] + b0, v01 = fa[i][j][1] + b1;
            float v10 = fa[i][j][2] + b0, v11 = fa[i][j][3] + b1;
            if (SPLIT) {
                __nv_bfloat16 h00 = __float2bfloat16_rn(v00);
                __nv_bfloat16 h01 = __float2bfloat16_rn(v01);
                __nv_bfloat16 h10 = __float2bfloat16_rn(v10);
                __nv_bfloat16 h11 = __float2bfloat16_rn(v11);
                const size_t o0 = (size_t)row * N + col;
                const size_t o1 = (size_t)(row + 8) * N + col;
                *(uint32_t*)(args.Ch[z] + o0) =
                    (uint32_t)*(uint16_t*)&h00 | ((uint32_t)*(uint16_t*)&h01 << 16);
                *(uint32_t*)(args.Ch[z] + o1) =
                    (uint32_t)*(uint16_t*)&h10 | ((uint32_t)*(uint16_t*)&h11 << 16);
                *(uint32_t*)(args.Cl[z] + o0) = pack2bf(v00 - __bfloat162float(h00),
                                                        v01 - __bfloat162float(h01));
                *(uint32_t*)(args.Cl[z] + o1) = pack2bf(v10 - __bfloat162float(h10),
                                                        v11 - __bfloat162float(h11));
            } else {
                float2 a2 = {v00, v01}, b2 = {v10, v11};
                *(float2*)&args.Cf[z][(size_t)row * N + col] = a2;
                *(float2*)&args.Cf[z][(size_t)(row + 8) * N + col] = b2;
            }
        }
    }
}

// ---------------------------------------------------------------------------
// mma flash attention: cp.async pipelined tiles, ldmatrix frag loads,
// natural-layout V with ldmatrix.trans. 48KB static smem exactly.
// smem swizzle: 64-col bf16 tiles, 128B rows, chunk ^= (row & 7).
// ---------------------------------------------------------------------------
__global__ __launch_bounds__(256) void flash_attn_mma(
    const __nv_bfloat16* __restrict__ Qh, const __nv_bfloat16* __restrict__ Ql,
    const __nv_bfloat16* __restrict__ Kh, const __nv_bfloat16* __restrict__ Kl,
    const __nv_bfloat16* __restrict__ Vh, const __nv_bfloat16* __restrict__ Vl,
    const float* __restrict__ SW,
    __nv_bfloat16* __restrict__ ctx_h, __nv_bfloat16* __restrict__ ctx_l)
{
    __shared__ __nv_bfloat16 sK[2][2][64 * 64];  // [stage][hi/lo] 32 KB
    __shared__ __nv_bfloat16 sV[2][64 * 64];     // [hi/lo]        16 KB

    const int qt = blockIdx.x, h = blockIdx.y, b = blockIdx.z;
    const int tid = threadIdx.x, w = tid >> 5, lane = tid & 31;
    const int g = lane >> 2, tg = lane & 3;
    const int q0 = qt * 128, rw = q0 + w * 16;
    const float scale = 0.125f;

    // Q fragments resident in registers
    uint32_t aq[2][4][4];
    {
        const size_t base = ((size_t)b * Ssz) * Dsz + (size_t)h * DKsz;
#pragma unroll
        for (int t = 0; t < 4; t++) {
            const int col = t * 16 + tg * 2;
            const size_t r0 = base + (size_t)(rw + g) * Dsz + col;
            const size_t r1 = base + (size_t)(rw + g + 8) * Dsz + col;
            aq[0][t][0] = *(const uint32_t*)(Qh + r0);
            aq[0][t][1] = *(const uint32_t*)(Qh + r1);
            aq[0][t][2] = *(const uint32_t*)(Qh + r0 + 8);
            aq[0][t][3] = *(const uint32_t*)(Qh + r1 + 8);
            aq[1][t][0] = *(const uint32_t*)(Ql + r0);
            aq[1][t][1] = *(const uint32_t*)(Ql + r1);
            aq[1][t][2] = *(const uint32_t*)(Ql + r0 + 8);
            aq[1][t][3] = *(const uint32_t*)(Ql + r1 + 8);
        }
    }

    // cp.async store mapping: row = tid>>2 (0..63), chunks (tid&3)*2, +1
    const int lrow = tid >> 2;
    const int lc0 = (tid & 3) * 2;
    const uint32_t sd0 = (uint32_t)(lrow * 128 + (((lc0)     ^ (lrow & 7)) << 4));
    const uint32_t sd1 = (uint32_t)(lrow * 128 + (((lc0 + 1) ^ (lrow & 7)) << 4));
    const uint32_t bK = (uint32_t)__cvta_generic_to_shared(&sK[0][0][0]);
    const uint32_t bV = (uint32_t)__cvta_generic_to_shared(&sV[0][0]);
    const size_t gbase = ((size_t)b * Ssz) * Dsz + (size_t)h * DKsz;

    // ldmatrix per-lane address components
    const int r7 = lane & 7, grp = lane >> 3;
    const int krow_off = ((grp >> 1) << 3) + r7;
    const int kchk_sel = grp & 1;
    const int vrow_off = ((grp & 1) << 3) + r7;
    const int vchk_sel = grp >> 1;

    const int i0 = rw + g, i1 = rw + g + 8;
    float m0 = -CUDART_INF_F, m1 = -CUDART_INF_F, l0 = 0.f, l1 = 0.f;
    float o[8][4];
#pragma unroll
    for (int d = 0; d < 8; d++)
#pragma unroll
        for (int u = 0; u < 4; u++) o[d][u] = 0.f;

    const int nkt = 2 * qt + 2;

    // prologue: K(0) -> stage 0
    {
        const size_t gk = gbase + (size_t)lrow * Dsz + lc0 * 8;
        cp_async16(bK + sd0, Kh + gk);
        cp_async16(bK + sd1, Kh + gk + 8);
        cp_async16(bK + 8192 + sd0, Kl + gk);
        cp_async16(bK + 8192 + sd1, Kl + gk + 8);
    }
    CP_COMMIT();

    int s = 0;
    for (int kt = 0; kt < nkt; kt++) {
        const int k0 = kt * 64;
        __syncthreads();   // sV free (prev PV done); sK[s^1] free (prev S done)

        // issue V(kt) [group A]
        {
            const size_t gv = gbase + (size_t)(k0 + lrow) * Dsz + lc0 * 8;
            cp_async16(bV + sd0, Vh + gv);
            cp_async16(bV + sd1, Vh + gv + 8);
            cp_async16(bV + 8192 + sd0, Vl + gv);
            cp_async16(bV + 8192 + sd1, Vl + gv + 8);
        }
        CP_COMMIT();
        // issue K(kt+1) into other stage [group B]
        if (kt + 1 < nkt) {
            const uint32_t so = bK + (uint32_t)(s ^ 1) * 16384;
            const size_t gk = gbase + (size_t)(k0 + 64 + lrow) * Dsz + lc0 * 8;
            cp_async16(so + sd0, Kh + gk);
            cp_async16(so + sd1, Kh + gk + 8);
            cp_async16(so + 8192 + sd0, Kl + gk);
            cp_async16(so + 8192 + sd1, Kl + gk + 8);
        }
        CP_COMMIT();

        CP_WAIT2();        // K(kt) ready; {V(kt)},{K(kt+1)} may be in flight
        __syncthreads();

        const bool active = (k0 <= rw + 14);
        uint32_t ph[4][4], pl[4][4];
        float corr0 = 1.f, corr1 = 1.f;

        if (active) {
            const uint32_t sKh = bK + (uint32_t)s * 16384;
            const uint32_t sKl = sKh + 8192;

            float sf[8][4];
#pragma unroll
            for (int j = 0; j < 8; j++)
#pragma unroll
                for (int u = 0; u < 4; u++) sf[j][u] = 0.f;

#pragma unroll
            for (int t = 0; t < 4; t++) {
                const int kc = 2 * t + kchk_sel;
#pragma unroll
                for (int jp = 0; jp < 4; jp++) {
                    const int row = jp * 16 + krow_off;
                    const uint32_t off =
                        (uint32_t)(row * 128 + ((kc ^ (row & 7)) << 4));
                    uint32_t kh[4], kl[4];
                    ldsm_x4(kh[0], kh[1], kh[2], kh[3], sKh + off);
                    ldsm_x4(kl[0], kl[1], kl[2], kl[3], sKl + off);
                    MMA16816(sf[2 * jp],     aq[0][t], kh[0], kh[1]);
                    MMA16816(sf[2 * jp],     aq[1][t], kh[0], kh[1]);
                    MMA16816(sf[2 * jp],     aq[0][t], kl[0], kl[1]);
                    MMA16816(sf[2 * jp + 1], aq[0][t], kh[2], kh[3]);
                    MMA16816(sf[2 * jp + 1], aq[1][t], kh[2], kh[3]);
                    MMA16816(sf[2 * jp + 1], aq[0][t], kl[2], kl[3]);
                }
            }

            const float* sw0 = SW + ((size_t)h * Ssz + i0) * Ssz + k0;
            const float* sw1 = SW + ((size_t)h * Ssz + i1) * Ssz + k0;
            const bool needmask = (k0 + 63 >= i0);
#pragma unroll
            for (int j = 0; j < 8; j++) {
                const int c = j * 8 + tg * 2;
                const float2 w0 = *(const float2*)(sw0 + c);
                const float2 w1 = *(const float2*)(sw1 + c);
                sf[j][0] = sf[j][0] * scale + w0.x;
                sf[j][1] = sf[j][1] * scale + w0.y;
                sf[j][2] = sf[j][2] * scale + w1.x;
                sf[j][3] = sf[j][3] * scale + w1.y;
                if (needmask) {
                    const int gc = k0 + c;
                    if (gc     >= i0) sf[j][0] = -CUDART_INF_F;
                    if (gc + 1 >= i0) sf[j][1] = -CUDART_INF_F;
                    if (gc     >= i1) sf[j][2] = -CUDART_INF_F;
                    if (gc + 1 >= i1) sf[j][3] = -CUDART_INF_F;
                }
            }

            float r0m = -CUDART_INF_F, r1m = -CUDART_INF_F;
#pragma unroll
            for (int j = 0; j < 8; j++) {
                r0m = fmaxf(r0m, fmaxf(sf[j][0], sf[j][1]));
                r1m = fmaxf(r1m, fmaxf(sf[j][2], sf[j][3]));
            }
            r0m = fmaxf(r0m, __shfl_xor_sync(0xffffffffu, r0m, 1));
            r0m = fmaxf(r0m, __shfl_xor_sync(0xffffffffu, r0m, 2));
            r1m = fmaxf(r1m, __shfl_xor_sync(0xffffffffu, r1m, 1));
            r1m = fmaxf(r1m, __shfl_xor_sync(0xffffffffu, r1m, 2));

            const float mn0 = fmaxf(m0, r0m), mn1 = fmaxf(m1, r1m);
            corr0 = (mn0 == -CUDART_INF_F) ? 0.f : __expf(m0 - mn0);
            corr1 = (mn1 == -CUDART_INF_F) ? 0.f : __expf(m1 - mn1);

            float rs0 = 0.f, rs1 = 0.f;
#pragma unroll
            for (int t = 0; t < 4; t++) {
                float pv[2][4];
#pragma unroll
                for (int u = 0; u < 2; u++) {
                    const int j = 2 * t + u;
#pragma unroll
                    for (int r = 0; r < 4; r++) {
                        const float e = sf[j][r];
                        const float mm = (r < 2) ? mn0 : mn1;
                        float p = (e == -CUDART_INF_F) ? 0.f : __expf(e - mm);
                        pv[u][r] = p;
                        if (r < 2) rs0 += p; else rs1 += p;
                    }
                }
                float lo[2][4];
#pragma unroll
                for (int u = 0; u < 2; u++)
#pragma unroll
                    for (int r = 0; r < 4; r++) {
                        __nv_bfloat16 hb = __float2bfloat16_rn(pv[u][r]);
                        lo[u][r] = pv[u][r] - __bfloat162float(hb);
                    }
                ph[t][0] = pack2bf(pv[0][0], pv[0][1]);
                ph[t][1] = pack2bf(pv[0][2], pv[0][3]);
                ph[t][2] = pack2bf(pv[1][0], pv[1][1]);
                ph[t][3] = pack2bf(pv[1][2], pv[1][3]);
                pl[t][0] = pack2bf(lo[0][0], lo[0][1]);
                pl[t][1] = pack2bf(lo[0][2], lo[0][3]);
                pl[t][2] = pack2bf(lo[1][0], lo[1][1]);
                pl[t][3] = pack2bf(lo[1][2], lo[1][3]);
            }
            rs0 += __shfl_xor_sync(0xffffffffu, rs0, 1);
            rs0 += __shfl_xor_sync(0xffffffffu, rs0, 2);
            rs1 += __shfl_xor_sync(0xffffffffu, rs1, 1);
            rs1 += __shfl_xor_sync(0xffffffffu, rs1, 2);

            l0 = l0 * corr0 + rs0;
            l1 = l1 * corr1 + rs1;
            m0 = mn0; m1 = mn1;
#pragma unroll
            for (int d = 0; d < 8; d++) {
                o[d][0] *= corr0; o[d][1] *= corr0;
                o[d][2] *= corr1; o[d][3] *= corr1;
            }
        }

        CP_WAIT1();        // V(kt) ready; K(kt+1) may remain in flight
        __syncthreads();

        if (active) {
#pragma unroll
            for (int t = 0; t < 4; t++) {
                const int row = t * 16 + vrow_off;
#pragma unroll
                for (int dp = 0; dp < 4; dp++) {
                    const int vc = 2 * dp + vchk_sel;
                    const uint32_t off =
                        (uint32_t)(row * 128 + ((vc ^ (row & 7)) << 4));
                    uint32_t vh[4], vl[4];
                    ldsm_x4t(vh[0], vh[1], vh[2], vh[3], bV + off);
                    ldsm_x4t(vl[0], vl[1], vl[2], vl[3], bV + 8192 + off);
                    MMA16816(o[2 * dp],     ph[t], vh[0], vh[1]);
                    MMA16816(o[2 * dp],     pl[t], vh[0], vh[1]);
                    MMA16816(o[2 * dp],     ph[t], vl[0], vl[1]);
                    MMA16816(o[2 * dp + 1], ph[t], vh[2], vh[3]);
                    MMA16816(o[2 * dp + 1], pl[t], vh[2], vh[3]);
                    MMA16816(o[2 * dp + 1], ph[t], vl[2], vl[3]);
                }
            }
        }
        s ^= 1;
    }

    const float inv0 = (l0 > 0.f) ? (1.f / l0) : 0.f;
    const float inv1 = (l1 > 0.f) ? (1.f / l1) : 0.f;
    const size_t ob = ((size_t)b * Ssz) * Dsz + (size_t)h * DKsz;
#pragma unroll
    for (int d = 0; d < 8; d++) {
        const int col = d * 8 + tg * 2;
        float v00 = o[d][0] * inv0, v01 = o[d][1] * inv0;
        float v10 = o[d][2] * inv1, v11 = o[d][3] * inv1;
        __nv_bfloat16 h00 = __float2bfloat16_rn(v00);
        __nv_bfloat16 h01 = __float2bfloat16_rn(v01);
        __nv_bfloat16 h10 = __float2bfloat16_rn(v10);
        __nv_bfloat16 h11 = __float2bfloat16_rn(v11);
        const size_t o0 = ob + (size_t)i0 * Dsz + col;
        const size_t o1 = ob + (size_t)i1 * Dsz + col;
        *(uint32_t*)(ctx_h + o0) =
            (uint32_t)*(uint16_t*)&h00 | ((uint32_t)*(uint16_t*)&h01 << 16);
        *(uint32_t*)(ctx_h + o1) =
            (uint32_t)*(uint16_t*)&h10 | ((uint32_t)*(uint16_t*)&h11 << 16);
        *(uint32_t*)(ctx_l + o0) = pack2bf(v00 - __bfloat162float(h00),
                                           v01 - __bfloat162float(h01));
        *(uint32_t*)(ctx_l + o1) = pack2bf(v10 - __bfloat162float(h10),
                                           v11 - __bfloat162float(h11));
    }
}

// ---------------------------------------------------------------------------
__global__ __launch_bounds__(256) void residual_ln(
    const float* __restrict__ x0, const float* __restrict__ y,
    const float* __restrict__ gamma, const float* __restrict__ beta,
    float* __restrict__ out)
{
    const int row = blockIdx.x;
    const float* a = x0 + (size_t)row * Dsz;
    const float* c = y  + (size_t)row * Dsz;
    const int tid = threadIdx.x;

    float v[4];
    float sum = 0.f, sumsq = 0.f;
#pragma unroll
    for (int u = 0; u < 4; u++) {
        int idx = tid + u * 256;
        float t = a[idx] + c[idx];
        v[u] = t;
        sum += t;
        sumsq += t * t;
    }
#pragma unroll
    for (int off = 16; off; off >>= 1) {
        sum   += __shfl_xor_sync(0xffffffffu, sum, off);
        sumsq += __shfl_xor_sync(0xffffffffu, sumsq, off);
    }
    __shared__ float s1[8], s2[8];
    if ((tid & 31) == 0) { s1[tid >> 5] = sum; s2[tid >> 5] = sumsq; }
    __syncthreads();
    if (tid < 32) {
        sum   = (tid < 8) ? s1[tid] : 0.f;
        sumsq = (tid < 8) ? s2[tid] : 0.f;
#pragma unroll
        for (int off = 4; off; off >>= 1) {
            sum   += __shfl_xor_sync(0xffffffffu, sum, off);
            sumsq += __shfl_xor_sync(0xffffffffu, sumsq, off);
        }
        if (tid == 0) { s1[0] = sum; s2[0] = sumsq; }
    }
    __syncthreads();
    const float mu   = s1[0] * (1.f / Dsz);
    const float var  = s2[0] * (1.f / Dsz) - mu * mu;
    const float rstd = rsqrtf(var + 1e-5f);

    float* op = out + (size_t)row * Dsz;
#pragma unroll
    for (int u = 0; u < 4; u++) {
        int idx = tid + u * 256;
        op[idx] = (v[u] - mu) * rstd * gamma[idx] + beta[idx];
    }
}

// ---------------------------------------------------------------------------
extern "C" void kernel_launch(void* const* d_in, const int* in_sizes, int n_in,
                              void* d_out, int out_size)
{
    const float* query  = (const float*)d_in[0];
    const float* key    = (const float*)d_in[1];
    const float* values = (const float*)d_in[2];
    // d_in[3] = lens (unused by reference)
    const float* sw     = (const float*)d_in[4];
    const float* Wq     = (const float*)d_in[5];
    const float* bq     = (const float*)d_in[6];
    const float* Wv     = (const float*)d_in[7];
    const float* bv     = (const float*)d_in[8];
    const float* Wo     = (const float*)d_in[9];
    const float* bo     = (const float*)d_in[10];
    const float* gamma  = (const float*)d_in[11];
    const float* beta   = (const float*)d_in[12];
    float* out = (float*)d_out;

    __nv_bfloat16 *xqh, *xql, *xkh, *xkl, *xvh, *xvl;
    __nv_bfloat16 *Qh, *Ql, *Kh, *Kl, *Vh, *Vl, *ch, *cl;
    __nv_bfloat16 *wqh, *wql, *wvh, *wvl, *woh, *wol;
    float* Op;
    cudaGetSymbolAddress((void**)&xqh, g_xqh); cudaGetSymbolAddress((void**)&xql, g_xql);
    cudaGetSymbolAddress((void**)&xkh, g_xkh); cudaGetSymbolAddress((void**)&xkl, g_xkl);
    cudaGetSymbolAddress((void**)&xvh, g_xvh); cudaGetSymbolAddress((void**)&xvl, g_xvl);
    cudaGetSymbolAddress((void**)&Qh, g_Qh);   cudaGetSymbolAddress((void**)&Ql, g_Ql);
    cudaGetSymbolAddress((void**)&Kh, g_Kh);   cudaGetSymbolAddress((void**)&Kl, g_Kl);
    cudaGetSymbolAddress((void**)&Vh, g_Vh);   cudaGetSymbolAddress((void**)&Vl, g_Vl);
    cudaGetSymbolAddress((void**)&ch, g_ch);   cudaGetSymbolAddress((void**)&cl, g_cl);
    cudaGetSymbolAddress((void**)&wqh, g_wqh); cudaGetSymbolAddress((void**)&wql, g_wql);
    cudaGetSymbolAddress((void**)&wvh, g_wvh); cudaGetSymbolAddress((void**)&wvl, g_wvl);
    cudaGetSymbolAddress((void**)&woh, g_woh); cudaGetSymbolAddress((void**)&wol, g_wol);
    cudaGetSymbolAddress((void**)&Op, g_O);

    Split3Args sp = {};
    sp.x[0] = query;  sp.hi[0] = xqh; sp.lo[0] = xql;
    sp.x[1] = key;    sp.hi[1] = xkh; sp.lo[1] = xkl;
    sp.x[2] = values; sp.hi[2] = xvh; sp.lo[2] = xvl;
    split3<<<dim3((unsigned)(NELEM / 1024), 3), 256>>>(sp);

    TW3Args tw = {};
    tw.w[0] = Wq; tw.hi[0] = wqh; tw.lo[0] = wql;
    tw.w[1] = Wv; tw.hi[1] = wvh; tw.lo[1] = wvl;
    tw.w[2] = Wo; tw.hi[2] = woh; tw.lo[2] = wol;
    transpose_split_w3<<<dim3(32, 32, 3), dim3(32, 8)>>>(tw);

    GemmArgs qkv = {};
    qkv.Ah[0] = xqh; qkv.Al[0] = xql; qkv.Bh[0] = wqh; qkv.Bl[0] = wql;
    qkv.bias[0] = bq; qkv.Ch[0] = Qh; qkv.Cl[0] = Ql;
    qkv.Ah[1] = xkh; qkv.Al[1] = xkl; qkv.Bh[1] = wqh; qkv.Bl[1] = wql;
    qkv.bias[1] = bq; qkv.Ch[1] = Kh; qkv.Cl[1] = Kl;
    qkv.Ah[2] = xvh; qkv.Al[2] = xvl; qkv.Bh[2] = wvh; qkv.Bl[2] = wvl;
    qkv.bias[2] = bv; qkv.Ch[2] = Vh; qkv.Cl[2] = Vl;
    dim3 gq(Dsz / 128, Msz / 128, 3);
    gemm_pipe<true><<<gq, 256>>>(qkv, Msz, Dsz, Dsz);

    flash_attn_mma<<<dim3(Ssz / 128, Hsz, Bsz), 256>>>(Qh, Ql, Kh, Kl, Vh, Vl,
                                                       sw, ch, cl);

    GemmArgs og = {};
    og.Ah[0] = ch; og.Al[0] = cl; og.Bh[0] = woh; og.Bl[0] = wol;
    og.bias[0] = bo; og.Cf[0] = Op;
    dim3 go(Dsz / 128, Msz / 128, 1);
    gemm_pipe<false><<<go, 256>>>(og, Msz, Dsz, Dsz);

    residual_ln<<<Msz, 256>>>(query, Op, gamma, beta, out);
}

// round 10
// speedup vs baseline: 4.4109x; 1.0011x over previous
#include <cuda_runtime.h>
#include <cuda_bf16.h>
#include <math_constants.h>
#include <cstdint>

// ---------------------------------------------------------------------------
// DTransformerLayer: B=4, S=1024, D=1024, H=16, DK=64
// R10: attention occupancy fix — __launch_bounds__(256,2) (128-reg cap,
// 2 CTAs/SM) enabled by fusing softmax packing into the PV loop per k-chunk
// (ph/pl live range 32->8 regs). GEMMs/splits/LN unchanged from R9.
// ---------------------------------------------------------------------------

#define Bsz 4
#define Ssz 1024
#define Dsz 1024
#define Hsz 16
#define DKsz 64
#define Msz (Bsz * Ssz)            // 4096
#define NELEM ((size_t)Msz * Dsz)  // 4M
#define WELEM ((size_t)Dsz * Dsz)  // 1M

__device__ __nv_bfloat16 g_xqh[NELEM], g_xql[NELEM];
__device__ __nv_bfloat16 g_xkh[NELEM], g_xkl[NELEM];
__device__ __nv_bfloat16 g_xvh[NELEM], g_xvl[NELEM];
__device__ __nv_bfloat16 g_Qh[NELEM], g_Ql[NELEM];
__device__ __nv_bfloat16 g_Kh[NELEM], g_Kl[NELEM];
__device__ __nv_bfloat16 g_Vh[NELEM], g_Vl[NELEM];
__device__ __nv_bfloat16 g_ch[NELEM], g_cl[NELEM];
__device__ __nv_bfloat16 g_wqh[WELEM], g_wql[WELEM];
__device__ __nv_bfloat16 g_wvh[WELEM], g_wvl[WELEM];
__device__ __nv_bfloat16 g_woh[WELEM], g_wol[WELEM];
__device__ float g_O[NELEM];

__device__ __forceinline__ uint32_t pack2bf(float a, float b) {
    __nv_bfloat162 t = __floats2bfloat162_rn(a, b);
    return *(uint32_t*)&t;
}

__device__ __forceinline__ void cp_async16(uint32_t dst_sm, const void* src) {
    asm volatile("cp.async.cg.shared.global [%0], [%1], 16;\n"
                 :: "r"(dst_sm), "l"(src));
}
#define CP_COMMIT() asm volatile("cp.async.commit_group;\n" ::: "memory")
#define CP_WAIT1()  asm volatile("cp.async.wait_group 1;\n" ::: "memory")
#define CP_WAIT2()  asm volatile("cp.async.wait_group 2;\n" ::: "memory")

__device__ __forceinline__ void ldsm_x4(uint32_t& r0, uint32_t& r1,
                                        uint32_t& r2, uint32_t& r3,
                                        uint32_t addr) {
    asm volatile("ldmatrix.sync.aligned.m8n8.x4.shared.b16 {%0,%1,%2,%3}, [%4];"
                 : "=r"(r0), "=r"(r1), "=r"(r2), "=r"(r3) : "r"(addr));
}
__device__ __forceinline__ void ldsm_x4t(uint32_t& r0, uint32_t& r1,
                                         uint32_t& r2, uint32_t& r3,
                                         uint32_t addr) {
    asm volatile("ldmatrix.sync.aligned.m8n8.x4.trans.shared.b16 {%0,%1,%2,%3}, [%4];"
                 : "=r"(r0), "=r"(r1), "=r"(r2), "=r"(r3) : "r"(addr));
}

// ---------------------------------------------------------------------------
struct Split3Args {
    const float* x[3];
    __nv_bfloat16 *hi[3], *lo[3];
};

__global__ __launch_bounds__(256) void split3(Split3Args a)
{
    const int z = blockIdx.y;
    const size_t i = ((size_t)blockIdx.x * 256 + threadIdx.x) * 4;
    float4 v = *(const float4*)(a.x[z] + i);
    float vv[4] = {v.x, v.y, v.z, v.w};
    __nv_bfloat16 h[4], l[4];
#pragma unroll
    for (int u = 0; u < 4; u++) {
        h[u] = __float2bfloat16_rn(vv[u]);
        l[u] = __float2bfloat16_rn(vv[u] - __bfloat162float(h[u]));
    }
    *(uint2*)(a.hi[z] + i) = *(uint2*)h;
    *(uint2*)(a.lo[z] + i) = *(uint2*)l;
}

// ---------------------------------------------------------------------------
struct TW3Args {
    const float* w[3];
    __nv_bfloat16 *hi[3], *lo[3];
};

__global__ __launch_bounds__(256) void transpose_split_w3(TW3Args a)
{
    __shared__ float t[32][33];
    const int z = blockIdx.z;
    const float* __restrict__ w = a.w[z];
    const int bx = blockIdx.x * 32;
    const int by = blockIdx.y * 32;
    const int tx = threadIdx.x, ty = threadIdx.y;
#pragma unroll
    for (int i = 0; i < 4; i++)
        t[ty + 8 * i][tx] = w[(size_t)(by + ty + 8 * i) * Dsz + bx + tx];
    __syncthreads();
#pragma unroll
    for (int i = 0; i < 4; i++) {
        float v = t[tx][ty + 8 * i];
        __nv_bfloat16 h = __float2bfloat16_rn(v);
        __nv_bfloat16 l = __float2bfloat16_rn(v - __bfloat162float(h));
        const size_t o = (size_t)(bx + ty + 8 * i) * Dsz + by + tx;
        a.hi[z][o] = h;
        a.lo[z][o] = l;
    }
}

// ---------------------------------------------------------------------------
// Pipelined bf16x3 GEMM (unchanged, passing).
// ---------------------------------------------------------------------------
#define MMA16816(d, a, b0, b1)                                              \
    asm volatile(                                                           \
        "mma.sync.aligned.m16n8k16.row.col.f32.bf16.bf16.f32 "              \
        "{%0,%1,%2,%3},{%4,%5,%6,%7},{%8,%9},{%0,%1,%2,%3};"                \
        : "+f"(d[0]), "+f"(d[1]), "+f"(d[2]), "+f"(d[3])                    \
        : "r"(a[0]), "r"(a[1]), "r"(a[2]), "r"(a[3]), "r"(b0), "r"(b1))

__device__ __forceinline__ uint32_t swz_byte(int row, int chunk) {
    return (uint32_t)(row * 32 + ((chunk ^ ((row >> 2) & 1)) << 4));
}

struct GemmArgs {
    const __nv_bfloat16 *Ah[3], *Al[3], *Bh[3], *Bl[3];
    const float* bias[3];
    float* Cf[3];
    __nv_bfloat16 *Ch[3], *Cl[3];
};

template <bool SPLIT>
__global__ __launch_bounds__(256, 2) void gemm_pipe(GemmArgs args, int M, int N, int K)
{
    __shared__ uint32_t sA[3][2][128 * 8];
    __shared__ uint32_t sB[3][2][128 * 8];

    const int z = blockIdx.z;
    const __nv_bfloat16* __restrict__ Ah = args.Ah[z];
    const __nv_bfloat16* __restrict__ Al = args.Al[z];
    const __nv_bfloat16* __restrict__ Bh = args.Bh[z];
    const __nv_bfloat16* __restrict__ Bl = args.Bl[z];
    const float* __restrict__ bias = args.bias[z];

    const int tid = threadIdx.x;
    const int bm = blockIdx.y * 128, bn = blockIdx.x * 128;
    const int w = tid >> 5, lane = tid & 31;
    const int g = lane >> 2, tg = lane & 3;
    const int wm = w >> 1, wn = w & 1;
    const int l7 = lane & 7, sel = lane >> 3;

    const int lrow = tid >> 1, lch = tid & 1;
    const uint32_t ldst = swz_byte(lrow, lch);
    const size_t gA = (size_t)(bm + lrow) * K + lch * 8;
    const size_t gB = (size_t)(bn + lrow) * K + lch * 8;

    const uint32_t baseA = (uint32_t)__cvta_generic_to_shared(&sA[0][0][0]);
    const uint32_t baseB = (uint32_t)__cvta_generic_to_shared(&sB[0][0][0]);

    float fa[2][8][4];
#pragma unroll
    for (int i = 0; i < 2; i++)
#pragma unroll
        for (int j = 0; j < 8; j++)
#pragma unroll
            for (int u = 0; u < 4; u++) fa[i][j][u] = 0.f;

    const int arow_off = l7 + ((sel & 1) << 3);
    const int achk = sel >> 1;
    const int brow_off = ((sel >> 1) << 3) + l7;
    const int bchk = sel & 1;

    auto load_stage = [&](int st, int kk) {
        const uint32_t so = (uint32_t)st * 8192;
        cp_async16(baseA + so +        ldst, Ah + gA + kk);
        cp_async16(baseA + so + 4096 + ldst, Al + gA + kk);
        cp_async16(baseB + so +        ldst, Bh + gB + kk);
        cp_async16(baseB + so + 4096 + ldst, Bl + gB + kk);
    };

    load_stage(0, 0);  CP_COMMIT();
    load_stage(1, 16); CP_COMMIT();

    int s = 0;
    for (int k0 = 0; k0 < K; k0 += 16) {
        CP_WAIT1();
        __syncthreads();
        {
            const int ns = (s + 2) % 3;
            if (k0 + 32 < K) load_stage(ns, k0 + 32);
            CP_COMMIT();
        }

        const uint32_t sAh = baseA + (uint32_t)s * 8192;
        const uint32_t sAl = sAh + 4096;
        const uint32_t sBh = baseB + (uint32_t)s * 8192;
        const uint32_t sBl = sBh + 4096;

        uint32_t a[2][2][4];
#pragma unroll
        for (int i = 0; i < 2; i++) {
            const int rb = wm * 32 + i * 16 + arow_off;
            const uint32_t off = swz_byte(rb, achk);
            ldsm_x4(a[0][i][0], a[0][i][1], a[0][i][2], a[0][i][3], sAh + off);
            ldsm_x4(a[1][i][0], a[1][i][1], a[1][i][2], a[1][i][3], sAl + off);
        }

#pragma unroll
        for (int jp = 0; jp < 4; jp++) {
            const int nb = wn * 64 + jp * 16 + brow_off;
            const uint32_t off = swz_byte(nb, bchk);
            uint32_t bh[4], bl[4];
            ldsm_x4(bh[0], bh[1], bh[2], bh[3], sBh + off);
            ldsm_x4(bl[0], bl[1], bl[2], bl[3], sBl + off);
#pragma unroll
            for (int i = 0; i < 2; i++) {
                MMA16816(fa[i][2 * jp],     a[0][i], bh[0], bh[1]);
                MMA16816(fa[i][2 * jp],     a[1][i], bh[0], bh[1]);
                MMA16816(fa[i][2 * jp],     a[0][i], bl[0], bl[1]);
                MMA16816(fa[i][2 * jp + 1], a[0][i], bh[2], bh[3]);
                MMA16816(fa[i][2 * jp + 1], a[1][i], bh[2], bh[3]);
                MMA16816(fa[i][2 * jp + 1], a[0][i], bl[2], bl[3]);
            }
        }
        s = (s + 1) % 3;
    }

#pragma unroll
    for (int i = 0; i < 2; i++) {
        const int row = bm + wm * 32 + i * 16 + g;
#pragma unroll
        for (int j = 0; j < 8; j++) {
            const int col = bn + wn * 64 + j * 8 + tg * 2;
            const float b0 = bias[col], b1 = bias[col + 1];
            float v00 = fa[i][j][0] + b0, v01 = fa[i][j][1] + b1;
            float v10 = fa[i][j][2] + b0, v11 = fa[i][j][3] + b1;
            if (SPLIT) {
                __nv_bfloat16 h00 = __float2bfloat16_rn(v00);
                __nv_bfloat16 h01 = __float2bfloat16_rn(v01);
                __nv_bfloat16 h10 = __float2bfloat16_rn(v10);
                __nv_bfloat16 h11 = __float2bfloat16_rn(v11);
                const size_t o0 = (size_t)row * N + col;
                const size_t o1 = (size_t)(row + 8) * N + col;
                *(uint32_t*)(args.Ch[z] + o0) =
                    (uint32_t)*(uint16_t*)&h00 | ((uint32_t)*(uint16_t*)&h01 << 16);
                *(uint32_t*)(args.Ch[z] + o1) =
                    (uint32_t)*(uint16_t*)&h10 | ((uint32_t)*(uint16_t*)&h11 << 16);
                *(uint32_t*)(args.Cl[z] + o0) = pack2bf(v00 - __bfloat162float(h00),
                                                        v01 - __bfloat162float(h01));
                *(uint32_t*)(args.Cl[z] + o1) = pack2bf(v10 - __bfloat162float(h10),
                                                        v11 - __bfloat162float(h11));
            } else {
                float2 a2 = {v00, v01}, b2 = {v10, v11};
                *(float2*)&args.Cf[z][(size_t)row * N + col] = a2;
                *(float2*)&args.Cf[z][(size_t)(row + 8) * N + col] = b2;
            }
        }
    }
}

// ---------------------------------------------------------------------------
// mma flash attention, R10: 2 CTAs/SM (128-reg cap) + softmax/PV fusion
// per k-chunk. cp.async pipelined K (2-stage) / V (latency-hidden),
// ldmatrix(+trans) frag loads, XOR-swizzled smem, 48KB static.
// ---------------------------------------------------------------------------
__global__ __launch_bounds__(256, 2) void flash_attn_mma(
    const __nv_bfloat16* __restrict__ Qh, const __nv_bfloat16* __restrict__ Ql,
    const __nv_bfloat16* __restrict__ Kh, const __nv_bfloat16* __restrict__ Kl,
    const __nv_bfloat16* __restrict__ Vh, const __nv_bfloat16* __restrict__ Vl,
    const float* __restrict__ SW,
    __nv_bfloat16* __restrict__ ctx_h, __nv_bfloat16* __restrict__ ctx_l)
{
    __shared__ __nv_bfloat16 sK[2][2][64 * 64];  // [stage][hi/lo] 32 KB
    __shared__ __nv_bfloat16 sV[2][64 * 64];     // [hi/lo]        16 KB

    const int qt = blockIdx.x, h = blockIdx.y, b = blockIdx.z;
    const int tid = threadIdx.x, w = tid >> 5, lane = tid & 31;
    const int g = lane >> 2, tg = lane & 3;
    const int q0 = qt * 128, rw = q0 + w * 16;
    const float scale = 0.125f;

    // Q fragments resident in registers
    uint32_t aq[2][4][4];
    {
        const size_t base = ((size_t)b * Ssz) * Dsz + (size_t)h * DKsz;
#pragma unroll
        for (int t = 0; t < 4; t++) {
            const int col = t * 16 + tg * 2;
            const size_t r0 = base + (size_t)(rw + g) * Dsz + col;
            const size_t r1 = base + (size_t)(rw + g + 8) * Dsz + col;
            aq[0][t][0] = *(const uint32_t*)(Qh + r0);
            aq[0][t][1] = *(const uint32_t*)(Qh + r1);
            aq[0][t][2] = *(const uint32_t*)(Qh + r0 + 8);
            aq[0][t][3] = *(const uint32_t*)(Qh + r1 + 8);
            aq[1][t][0] = *(const uint32_t*)(Ql + r0);
            aq[1][t][1] = *(const uint32_t*)(Ql + r1);
            aq[1][t][2] = *(const uint32_t*)(Ql + r0 + 8);
            aq[1][t][3] = *(const uint32_t*)(Ql + r1 + 8);
        }
    }

    const int lrow = tid >> 2;
    const int lc0 = (tid & 3) * 2;
    const uint32_t sd0 = (uint32_t)(lrow * 128 + (((lc0)     ^ (lrow & 7)) << 4));
    const uint32_t sd1 = (uint32_t)(lrow * 128 + (((lc0 + 1) ^ (lrow & 7)) << 4));
    const uint32_t bK = (uint32_t)__cvta_generic_to_shared(&sK[0][0][0]);
    const uint32_t bV = (uint32_t)__cvta_generic_to_shared(&sV[0][0]);
    const size_t gbase = ((size_t)b * Ssz) * Dsz + (size_t)h * DKsz;

    const int r7 = lane & 7, grp = lane >> 3;
    const int krow_off = ((grp >> 1) << 3) + r7;
    const int kchk_sel = grp & 1;
    const int vrow_off = ((grp & 1) << 3) + r7;
    const int vchk_sel = grp >> 1;

    const int i0 = rw + g, i1 = rw + g + 8;
    float m0 = -CUDART_INF_F, m1 = -CUDART_INF_F, l0 = 0.f, l1 = 0.f;
    float o[8][4];
#pragma unroll
    for (int d = 0; d < 8; d++)
#pragma unroll
        for (int u = 0; u < 4; u++) o[d][u] = 0.f;

    const int nkt = 2 * qt + 2;

    // prologue: K(0) -> stage 0
    {
        const size_t gk = gbase + (size_t)lrow * Dsz + lc0 * 8;
        cp_async16(bK + sd0, Kh + gk);
        cp_async16(bK + sd1, Kh + gk + 8);
        cp_async16(bK + 8192 + sd0, Kl + gk);
        cp_async16(bK + 8192 + sd1, Kl + gk + 8);
    }
    CP_COMMIT();

    int s = 0;
    for (int kt = 0; kt < nkt; kt++) {
        const int k0 = kt * 64;
        __syncthreads();   // sV free (prev PV done); sK[s^1] free (prev S done)

        // issue V(kt) [group A]
        {
            const size_t gv = gbase + (size_t)(k0 + lrow) * Dsz + lc0 * 8;
            cp_async16(bV + sd0, Vh + gv);
            cp_async16(bV + sd1, Vh + gv + 8);
            cp_async16(bV + 8192 + sd0, Vl + gv);
            cp_async16(bV + 8192 + sd1, Vl + gv + 8);
        }
        CP_COMMIT();
        // issue K(kt+1) into other stage [group B]
        if (kt + 1 < nkt) {
            const uint32_t so = bK + (uint32_t)(s ^ 1) * 16384;
            const size_t gk = gbase + (size_t)(k0 + 64 + lrow) * Dsz + lc0 * 8;
            cp_async16(so + sd0, Kh + gk);
            cp_async16(so + sd1, Kh + gk + 8);
            cp_async16(so + 8192 + sd0, Kl + gk);
            cp_async16(so + 8192 + sd1, Kl + gk + 8);
        }
        CP_COMMIT();

        CP_WAIT2();        // K(kt) ready
        __syncthreads();

        const bool active = (k0 <= rw + 14);
        float sf[8][4];
        float mn0 = m0, mn1 = m1, corr0 = 1.f, corr1 = 1.f;

        if (active) {
            const uint32_t sKh = bK + (uint32_t)s * 16384;
            const uint32_t sKl = sKh + 8192;

#pragma unroll
            for (int j = 0; j < 8; j++)
#pragma unroll
                for (int u = 0; u < 4; u++) sf[j][u] = 0.f;

#pragma unroll
            for (int t = 0; t < 4; t++) {
                const int kc = 2 * t + kchk_sel;
#pragma unroll
                for (int jp = 0; jp < 4; jp++) {
                    const int row = jp * 16 + krow_off;
                    const uint32_t off =
                        (uint32_t)(row * 128 + ((kc ^ (row & 7)) << 4));
                    uint32_t kh[4], kl[4];
                    ldsm_x4(kh[0], kh[1], kh[2], kh[3], sKh + off);
                    ldsm_x4(kl[0], kl[1], kl[2], kl[3], sKl + off);
                    MMA16816(sf[2 * jp],     aq[0][t], kh[0], kh[1]);
                    MMA16816(sf[2 * jp],     aq[1][t], kh[0], kh[1]);
                    MMA16816(sf[2 * jp],     aq[0][t], kl[0], kl[1]);
                    MMA16816(sf[2 * jp + 1], aq[0][t], kh[2], kh[3]);
                    MMA16816(sf[2 * jp + 1], aq[1][t], kh[2], kh[3]);
                    MMA16816(sf[2 * jp + 1], aq[0][t], kl[2], kl[3]);
                }
            }

            const float* sw0 = SW + ((size_t)h * Ssz + i0) * Ssz + k0;
            const float* sw1 = SW + ((size_t)h * Ssz + i1) * Ssz + k0;
            const bool needmask = (k0 + 63 >= i0);
#pragma unroll
            for (int j = 0; j < 8; j++) {
                const int c = j * 8 + tg * 2;
                const float2 w0 = *(const float2*)(sw0 + c);
                const float2 w1 = *(const float2*)(sw1 + c);
                sf[j][0] = sf[j][0] * scale + w0.x;
                sf[j][1] = sf[j][1] * scale + w0.y;
                sf[j][2] = sf[j][2] * scale + w1.x;
                sf[j][3] = sf[j][3] * scale + w1.y;
                if (needmask) {
                    const int gc = k0 + c;
                    if (gc     >= i0) sf[j][0] = -CUDART_INF_F;
                    if (gc + 1 >= i0) sf[j][1] = -CUDART_INF_F;
                    if (gc     >= i1) sf[j][2] = -CUDART_INF_F;
                    if (gc + 1 >= i1) sf[j][3] = -CUDART_INF_F;
                }
            }

            float r0m = -CUDART_INF_F, r1m = -CUDART_INF_F;
#pragma unroll
            for (int j = 0; j < 8; j++) {
                r0m = fmaxf(r0m, fmaxf(sf[j][0], sf[j][1]));
                r1m = fmaxf(r1m, fmaxf(sf[j][2], sf[j][3]));
            }
            r0m = fmaxf(r0m, __shfl_xor_sync(0xffffffffu, r0m, 1));
            r0m = fmaxf(r0m, __shfl_xor_sync(0xffffffffu, r0m, 2));
            r1m = fmaxf(r1m, __shfl_xor_sync(0xffffffffu, r1m, 1));
            r1m = fmaxf(r1m, __shfl_xor_sync(0xffffffffu, r1m, 2));

            mn0 = fmaxf(m0, r0m); mn1 = fmaxf(m1, r1m);
            corr0 = (mn0 == -CUDART_INF_F) ? 0.f : __expf(m0 - mn0);
            corr1 = (mn1 == -CUDART_INF_F) ? 0.f : __expf(m1 - mn1);
#pragma unroll
            for (int d = 0; d < 8; d++) {
                o[d][0] *= corr0; o[d][1] *= corr0;
                o[d][2] *= corr1; o[d][3] *= corr1;
            }
        }

        CP_WAIT1();        // V(kt) ready; K(kt+1) may remain in flight
        __syncthreads();

        if (active) {
            float rs0 = 0.f, rs1 = 0.f;
            // fused: per k-chunk t -> exp+pack (8 regs) then PV mmas
#pragma unroll
            for (int t = 0; t < 4; t++) {
                float pv[2][4];
#pragma unroll
                for (int u = 0; u < 2; u++) {
                    const int j = 2 * t + u;
#pragma unroll
                    for (int r = 0; r < 4; r++) {
                        const float e = sf[j][r];
                        const float mm = (r < 2) ? mn0 : mn1;
                        float p = (e == -CUDART_INF_F) ? 0.f : __expf(e - mm);
                        pv[u][r] = p;
                        if (r < 2) rs0 += p; else rs1 += p;
                    }
                }
                uint32_t ph4[4], pl4[4];
                {
                    float lo[2][4];
#pragma unroll
                    for (int u = 0; u < 2; u++)
#pragma unroll
                        for (int r = 0; r < 4; r++) {
                            __nv_bfloat16 hb = __float2bfloat16_rn(pv[u][r]);
                            lo[u][r] = pv[u][r] - __bfloat162float(hb);
                        }
                    ph4[0] = pack2bf(pv[0][0], pv[0][1]);
                    ph4[1] = pack2bf(pv[0][2], pv[0][3]);
                    ph4[2] = pack2bf(pv[1][0], pv[1][1]);
                    ph4[3] = pack2bf(pv[1][2], pv[1][3]);
                    pl4[0] = pack2bf(lo[0][0], lo[0][1]);
                    pl4[1] = pack2bf(lo[0][2], lo[0][3]);
                    pl4[2] = pack2bf(lo[1][0], lo[1][1]);
                    pl4[3] = pack2bf(lo[1][2], lo[1][3]);
                }
                const int row = t * 16 + vrow_off;
#pragma unroll
                for (int dp = 0; dp < 4; dp++) {
                    const int vc = 2 * dp + vchk_sel;
                    const uint32_t off =
                        (uint32_t)(row * 128 + ((vc ^ (row & 7)) << 4));
                    uint32_t vh[4], vl[4];
                    ldsm_x4t(vh[0], vh[1], vh[2], vh[3], bV + off);
                    ldsm_x4t(vl[0], vl[1], vl[2], vl[3], bV + 8192 + off);
                    MMA16816(o[2 * dp],     ph4, vh[0], vh[1]);
                    MMA16816(o[2 * dp],     pl4, vh[0], vh[1]);
                    MMA16816(o[2 * dp],     ph4, vl[0], vl[1]);
                    MMA16816(o[2 * dp + 1], ph4, vh[2], vh[3]);
                    MMA16816(o[2 * dp + 1], pl4, vh[2], vh[3]);
                    MMA16816(o[2 * dp + 1], ph4, vl[2], vl[3]);
                }
            }
            rs0 += __shfl_xor_sync(0xffffffffu, rs0, 1);
            rs0 += __shfl_xor_sync(0xffffffffu, rs0, 2);
            rs1 += __shfl_xor_sync(0xffffffffu, rs1, 1);
            rs1 += __shfl_xor_sync(0xffffffffu, rs1, 2);
            l0 = l0 * corr0 + rs0;
            l1 = l1 * corr1 + rs1;
            m0 = mn0; m1 = mn1;
        }
        s ^= 1;
    }

    const float inv0 = (l0 > 0.f) ? (1.f / l0) : 0.f;
    const float inv1 = (l1 > 0.f) ? (1.f / l1) : 0.f;
    const size_t ob = ((size_t)b * Ssz) * Dsz + (size_t)h * DKsz;
#pragma unroll
    for (int d = 0; d < 8; d++) {
        const int col = d * 8 + tg * 2;
        float v00 = o[d][0] * inv0, v01 = o[d][1] * inv0;
        float v10 = o[d][2] * inv1, v11 = o[d][3] * inv1;
        __nv_bfloat16 h00 = __float2bfloat16_rn(v00);
        __nv_bfloat16 h01 = __float2bfloat16_rn(v01);
        __nv_bfloat16 h10 = __float2bfloat16_rn(v10);
        __nv_bfloat16 h11 = __float2bfloat16_rn(v11);
        const size_t o0 = ob + (size_t)i0 * Dsz + col;
        const size_t o1 = ob + (size_t)i1 * Dsz + col;
        *(uint32_t*)(ctx_h + o0) =
            (uint32_t)*(uint16_t*)&h00 | ((uint32_t)*(uint16_t*)&h01 << 16);
        *(uint32_t*)(ctx_h + o1) =
            (uint32_t)*(uint16_t*)&h10 | ((uint32_t)*(uint16_t*)&h11 << 16);
        *(uint32_t*)(ctx_l + o0) = pack2bf(v00 - __bfloat162float(h00),
                                           v01 - __bfloat162float(h01));
        *(uint32_t*)(ctx_l + o1) = pack2bf(v10 - __bfloat162float(h10),
                                           v11 - __bfloat162float(h11));
    }
}

// ---------------------------------------------------------------------------
__global__ __launch_bounds__(256) void residual_ln(
    const float* __restrict__ x0, const float* __restrict__ y,
    const float* __restrict__ gamma, const float* __restrict__ beta,
    float* __restrict__ out)
{
    const int row = blockIdx.x;
    const float* a = x0 + (size_t)row * Dsz;
    const float* c = y  + (size_t)row * Dsz;
    const int tid = threadIdx.x;

    float v[4];
    float sum = 0.f, sumsq = 0.f;
#pragma unroll
    for (int u = 0; u < 4; u++) {
        int idx = tid + u * 256;
        float t = a[idx] + c[idx];
        v[u] = t;
        sum += t;
        sumsq += t * t;
    }
#pragma unroll
    for (int off = 16; off; off >>= 1) {
        sum   += __shfl_xor_sync(0xffffffffu, sum, off);
        sumsq += __shfl_xor_sync(0xffffffffu, sumsq, off);
    }
    __shared__ float s1[8], s2[8];
    if ((tid & 31) == 0) { s1[tid >> 5] = sum; s2[tid >> 5] = sumsq; }
    __syncthreads();
    if (tid < 32) {
        sum   = (tid < 8) ? s1[tid] : 0.f;
        sumsq = (tid < 8) ? s2[tid] : 0.f;
#pragma unroll
        for (int off = 4; off; off >>= 1) {
            sum   += __shfl_xor_sync(0xffffffffu, sum, off);
            sumsq += __shfl_xor_sync(0xffffffffu, sumsq, off);
        }
        if (tid == 0) { s1[0] = sum; s2[0] = sumsq; }
    }
    __syncthreads();
    const float mu   = s1[0] * (1.f / Dsz);
    const float var  = s2[0] * (1.f / Dsz) - mu * mu;
    const float rstd = rsqrtf(var + 1e-5f);

    float* op = out + (size_t)row * Dsz;
#pragma unroll
    for (int u = 0; u < 4; u++) {
        int idx = tid + u * 256;
        op[idx] = (v[u] - mu) * rstd * gamma[idx] + beta[idx];
    }
}

// ---------------------------------------------------------------------------
extern "C" void kernel_launch(void* const* d_in, const int* in_sizes, int n_in,
                              void* d_out, int out_size)
{
    const float* query  = (const float*)d_in[0];
    const float* key    = (const float*)d_in[1];
    const float* values = (const float*)d_in[2];
    // d_in[3] = lens (unused by reference)
    const float* sw     = (const float*)d_in[4];
    const float* Wq     = (const float*)d_in[5];
    const float* bq     = (const float*)d_in[6];
    const float* Wv     = (const float*)d_in[7];
    const float* bv     = (const float*)d_in[8];
    const float* Wo     = (const float*)d_in[9];
    const float* bo     = (const float*)d_in[10];
    const float* gamma  = (const float*)d_in[11];
    const float* beta   = (const float*)d_in[12];
    float* out = (float*)d_out;

    __nv_bfloat16 *xqh, *xql, *xkh, *xkl, *xvh, *xvl;
    __nv_bfloat16 *Qh, *Ql, *Kh, *Kl, *Vh, *Vl, *ch, *cl;
    __nv_bfloat16 *wqh, *wql, *wvh, *wvl, *woh, *wol;
    float* Op;
    cudaGetSymbolAddress((void**)&xqh, g_xqh); cudaGetSymbolAddress((void**)&xql, g_xql);
    cudaGetSymbolAddress((void**)&xkh, g_xkh); cudaGetSymbolAddress((void**)&xkl, g_xkl);
    cudaGetSymbolAddress((void**)&xvh, g_xvh); cudaGetSymbolAddress((void**)&xvl, g_xvl);
    cudaGetSymbolAddress((void**)&Qh, g_Qh);   cudaGetSymbolAddress((void**)&Ql, g_Ql);
    cudaGetSymbolAddress((void**)&Kh, g_Kh);   cudaGetSymbolAddress((void**)&Kl, g_Kl);
    cudaGetSymbolAddress((void**)&Vh, g_Vh);   cudaGetSymbolAddress((void**)&Vl, g_Vl);
    cudaGetSymbolAddress((void**)&ch, g_ch);   cudaGetSymbolAddress((void**)&cl, g_cl);
    cudaGetSymbolAddress((void**)&wqh, g_wqh); cudaGetSymbolAddress((void**)&wql, g_wql);
    cudaGetSymbolAddress((void**)&wvh, g_wvh); cudaGetSymbolAddress((void**)&wvl, g_wvl);
    cudaGetSymbolAddress((void**)&woh, g_woh); cudaGetSymbolAddress((void**)&wol, g_wol);
    cudaGetSymbolAddress((void**)&Op, g_O);

    Split3Args sp = {};
    sp.x[0] = query;  sp.hi[0] = xqh; sp.lo[0] = xql;
    sp.x[1] = key;    sp.hi[1] = xkh; sp.lo[1] = xkl;
    sp.x[2] = values; sp.hi[2] = xvh; sp.lo[2] = xvl;
    split3<<<dim3((unsigned)(NELEM / 1024), 3), 256>>>(sp);

    TW3Args tw = {};
    tw.w[0] = Wq; tw.hi[0] = wqh; tw.lo[0] = wql;
    tw.w[1] = Wv; tw.hi[1] = wvh; tw.lo[1] = wvl;
    tw.w[2] = Wo; tw.hi[2] = woh; tw.lo[2] = wol;
    transpose_split_w3<<<dim3(32, 32, 3), dim3(32, 8)>>>(tw);

    GemmArgs qkv = {};
    qkv.Ah[0] = xqh; qkv.Al[0] = xql; qkv.Bh[0] = wqh; qkv.Bl[0] = wql;
    qkv.bias[0] = bq; qkv.Ch[0] = Qh; qkv.Cl[0] = Ql;
    qkv.Ah[1] = xkh; qkv.Al[1] = xkl; qkv.Bh[1] = wqh; qkv.Bl[1] = wql;
    qkv.bias[1] = bq; qkv.Ch[1] = Kh; qkv.Cl[1] = Kl;
    qkv.Ah[2] = xvh; qkv.Al[2] = xvl; qkv.Bh[2] = wvh; qkv.Bl[2] = wvl;
    qkv.bias[2] = bv; qkv.Ch[2] = Vh; qkv.Cl[2] = Vl;
    dim3 gq(Dsz / 128, Msz / 128, 3);
    gemm_pipe<true><<<gq, 256>>>(qkv, Msz, Dsz, Dsz);

    flash_attn_mma<<<dim3(Ssz / 128, Hsz, Bsz), 256>>>(Qh, Ql, Kh, Kl, Vh, Vl,
                                                       sw, ch, cl);

    GemmArgs og = {};
    og.Ah[0] = ch; og.Al[0] = cl; og.Bh[0] = woh; og.Bl[0] = wol;
    og.bias[0] = bo; og.Cf[0] = Op;
    dim3 go(Dsz / 128, Msz / 128, 1);
    gemm_pipe<false><<<go, 256>>>(og, Msz, Dsz, Dsz);

    residual_ln<<<Msz, 256>>>(query, Op, gamma, beta, out);
}

// round 11
// speedup vs baseline: 4.4377x; 1.0061x over previous
#include <cuda_runtime.h>
#include <cuda_bf16.h>
#include <math_constants.h>
#include <cstdint>

// ---------------------------------------------------------------------------
// DTransformerLayer: B=4, S=1024, D=1024, H=16, DK=64
// R11: attention restructured to 64-row q-tiles, 128 threads, 4 CTAs/SM
// (4 independent barrier domains -> cross-CTA phase overlap). Compute path
// unchanged. GEMMs/splits/LN unchanged from R10.
// ---------------------------------------------------------------------------

#define Bsz 4
#define Ssz 1024
#define Dsz 1024
#define Hsz 16
#define DKsz 64
#define Msz (Bsz * Ssz)            // 4096
#define NELEM ((size_t)Msz * Dsz)  // 4M
#define WELEM ((size_t)Dsz * Dsz)  // 1M

__device__ __nv_bfloat16 g_xqh[NELEM], g_xql[NELEM];
__device__ __nv_bfloat16 g_xkh[NELEM], g_xkl[NELEM];
__device__ __nv_bfloat16 g_xvh[NELEM], g_xvl[NELEM];
__device__ __nv_bfloat16 g_Qh[NELEM], g_Ql[NELEM];
__device__ __nv_bfloat16 g_Kh[NELEM], g_Kl[NELEM];
__device__ __nv_bfloat16 g_Vh[NELEM], g_Vl[NELEM];
__device__ __nv_bfloat16 g_ch[NELEM], g_cl[NELEM];
__device__ __nv_bfloat16 g_wqh[WELEM], g_wql[WELEM];
__device__ __nv_bfloat16 g_wvh[WELEM], g_wvl[WELEM];
__device__ __nv_bfloat16 g_woh[WELEM], g_wol[WELEM];
__device__ float g_O[NELEM];

__device__ __forceinline__ uint32_t pack2bf(float a, float b) {
    __nv_bfloat162 t = __floats2bfloat162_rn(a, b);
    return *(uint32_t*)&t;
}

__device__ __forceinline__ void cp_async16(uint32_t dst_sm, const void* src) {
    asm volatile("cp.async.cg.shared.global [%0], [%1], 16;\n"
                 :: "r"(dst_sm), "l"(src));
}
#define CP_COMMIT() asm volatile("cp.async.commit_group;\n" ::: "memory")
#define CP_WAIT1()  asm volatile("cp.async.wait_group 1;\n" ::: "memory")
#define CP_WAIT2()  asm volatile("cp.async.wait_group 2;\n" ::: "memory")

__device__ __forceinline__ void ldsm_x4(uint32_t& r0, uint32_t& r1,
                                        uint32_t& r2, uint32_t& r3,
                                        uint32_t addr) {
    asm volatile("ldmatrix.sync.aligned.m8n8.x4.shared.b16 {%0,%1,%2,%3}, [%4];"
                 : "=r"(r0), "=r"(r1), "=r"(r2), "=r"(r3) : "r"(addr));
}
__device__ __forceinline__ void ldsm_x4t(uint32_t& r0, uint32_t& r1,
                                         uint32_t& r2, uint32_t& r3,
                                         uint32_t addr) {
    asm volatile("ldmatrix.sync.aligned.m8n8.x4.trans.shared.b16 {%0,%1,%2,%3}, [%4];"
                 : "=r"(r0), "=r"(r1), "=r"(r2), "=r"(r3) : "r"(addr));
}

// ---------------------------------------------------------------------------
struct Split3Args {
    const float* x[3];
    __nv_bfloat16 *hi[3], *lo[3];
};

__global__ __launch_bounds__(256) void split3(Split3Args a)
{
    const int z = blockIdx.y;
    const size_t i = ((size_t)blockIdx.x * 256 + threadIdx.x) * 4;
    float4 v = *(const float4*)(a.x[z] + i);
    float vv[4] = {v.x, v.y, v.z, v.w};
    __nv_bfloat16 h[4], l[4];
#pragma unroll
    for (int u = 0; u < 4; u++) {
        h[u] = __float2bfloat16_rn(vv[u]);
        l[u] = __float2bfloat16_rn(vv[u] - __bfloat162float(h[u]));
    }
    *(uint2*)(a.hi[z] + i) = *(uint2*)h;
    *(uint2*)(a.lo[z] + i) = *(uint2*)l;
}

// ---------------------------------------------------------------------------
struct TW3Args {
    const float* w[3];
    __nv_bfloat16 *hi[3], *lo[3];
};

__global__ __launch_bounds__(256) void transpose_split_w3(TW3Args a)
{
    __shared__ float t[32][33];
    const int z = blockIdx.z;
    const float* __restrict__ w = a.w[z];
    const int bx = blockIdx.x * 32;
    const int by = blockIdx.y * 32;
    const int tx = threadIdx.x, ty = threadIdx.y;
#pragma unroll
    for (int i = 0; i < 4; i++)
        t[ty + 8 * i][tx] = w[(size_t)(by + ty + 8 * i) * Dsz + bx + tx];
    __syncthreads();
#pragma unroll
    for (int i = 0; i < 4; i++) {
        float v = t[tx][ty + 8 * i];
        __nv_bfloat16 h = __float2bfloat16_rn(v);
        __nv_bfloat16 l = __float2bfloat16_rn(v - __bfloat162float(h));
        const size_t o = (size_t)(bx + ty + 8 * i) * Dsz + by + tx;
        a.hi[z][o] = h;
        a.lo[z][o] = l;
    }
}

// ---------------------------------------------------------------------------
// Pipelined bf16x3 GEMM (unchanged, passing).
// ---------------------------------------------------------------------------
#define MMA16816(d, a, b0, b1)                                              \
    asm volatile(                                                           \
        "mma.sync.aligned.m16n8k16.row.col.f32.bf16.bf16.f32 "              \
        "{%0,%1,%2,%3},{%4,%5,%6,%7},{%8,%9},{%0,%1,%2,%3};"                \
        : "+f"(d[0]), "+f"(d[1]), "+f"(d[2]), "+f"(d[3])                    \
        : "r"(a[0]), "r"(a[1]), "r"(a[2]), "r"(a[3]), "r"(b0), "r"(b1))

__device__ __forceinline__ uint32_t swz_byte(int row, int chunk) {
    return (uint32_t)(row * 32 + ((chunk ^ ((row >> 2) & 1)) << 4));
}

struct GemmArgs {
    const __nv_bfloat16 *Ah[3], *Al[3], *Bh[3], *Bl[3];
    const float* bias[3];
    float* Cf[3];
    __nv_bfloat16 *Ch[3], *Cl[3];
};

template <bool SPLIT>
__global__ __launch_bounds__(256, 2) void gemm_pipe(GemmArgs args, int M, int N, int K)
{
    __shared__ uint32_t sA[3][2][128 * 8];
    __shared__ uint32_t sB[3][2][128 * 8];

    const int z = blockIdx.z;
    const __nv_bfloat16* __restrict__ Ah = args.Ah[z];
    const __nv_bfloat16* __restrict__ Al = args.Al[z];
    const __nv_bfloat16* __restrict__ Bh = args.Bh[z];
    const __nv_bfloat16* __restrict__ Bl = args.Bl[z];
    const float* __restrict__ bias = args.bias[z];

    const int tid = threadIdx.x;
    const int bm = blockIdx.y * 128, bn = blockIdx.x * 128;
    const int w = tid >> 5, lane = tid & 31;
    const int g = lane >> 2, tg = lane & 3;
    const int wm = w >> 1, wn = w & 1;
    const int l7 = lane & 7, sel = lane >> 3;

    const int lrow = tid >> 1, lch = tid & 1;
    const uint32_t ldst = swz_byte(lrow, lch);
    const size_t gA = (size_t)(bm + lrow) * K + lch * 8;
    const size_t gB = (size_t)(bn + lrow) * K + lch * 8;

    const uint32_t baseA = (uint32_t)__cvta_generic_to_shared(&sA[0][0][0]);
    const uint32_t baseB = (uint32_t)__cvta_generic_to_shared(&sB[0][0][0]);

    float fa[2][8][4];
#pragma unroll
    for (int i = 0; i < 2; i++)
#pragma unroll
        for (int j = 0; j < 8; j++)
#pragma unroll
            for (int u = 0; u < 4; u++) fa[i][j][u] = 0.f;

    const int arow_off = l7 + ((sel & 1) << 3);
    const int achk = sel >> 1;
    const int brow_off = ((sel >> 1) << 3) + l7;
    const int bchk = sel & 1;

    auto load_stage = [&](int st, int kk) {
        const uint32_t so = (uint32_t)st * 8192;
        cp_async16(baseA + so +        ldst, Ah + gA + kk);
        cp_async16(baseA + so + 4096 + ldst, Al + gA + kk);
        cp_async16(baseB + so +        ldst, Bh + gB + kk);
        cp_async16(baseB + so + 4096 + ldst, Bl + gB + kk);
    };

    load_stage(0, 0);  CP_COMMIT();
    load_stage(1, 16); CP_COMMIT();

    int s = 0;
    for (int k0 = 0; k0 < K; k0 += 16) {
        CP_WAIT1();
        __syncthreads();
        {
            const int ns = (s + 2) % 3;
            if (k0 + 32 < K) load_stage(ns, k0 + 32);
            CP_COMMIT();
        }

        const uint32_t sAh = baseA + (uint32_t)s * 8192;
        const uint32_t sAl = sAh + 4096;
        const uint32_t sBh = baseB + (uint32_t)s * 8192;
        const uint32_t sBl = sBh + 4096;

        uint32_t a[2][2][4];
#pragma unroll
        for (int i = 0; i < 2; i++) {
            const int rb = wm * 32 + i * 16 + arow_off;
            const uint32_t off = swz_byte(rb, achk);
            ldsm_x4(a[0][i][0], a[0][i][1], a[0][i][2], a[0][i][3], sAh + off);
            ldsm_x4(a[1][i][0], a[1][i][1], a[1][i][2], a[1][i][3], sAl + off);
        }

#pragma unroll
        for (int jp = 0; jp < 4; jp++) {
            const int nb = wn * 64 + jp * 16 + brow_off;
            const uint32_t off = swz_byte(nb, bchk);
            uint32_t bh[4], bl[4];
            ldsm_x4(bh[0], bh[1], bh[2], bh[3], sBh + off);
            ldsm_x4(bl[0], bl[1], bl[2], bl[3], sBl + off);
#pragma unroll
            for (int i = 0; i < 2; i++) {
                MMA16816(fa[i][2 * jp],     a[0][i], bh[0], bh[1]);
                MMA16816(fa[i][2 * jp],     a[1][i], bh[0], bh[1]);
                MMA16816(fa[i][2 * jp],     a[0][i], bl[0], bl[1]);
                MMA16816(fa[i][2 * jp + 1], a[0][i], bh[2], bh[3]);
                MMA16816(fa[i][2 * jp + 1], a[1][i], bh[2], bh[3]);
                MMA16816(fa[i][2 * jp + 1], a[0][i], bl[2], bl[3]);
            }
        }
        s = (s + 1) % 3;
    }

#pragma unroll
    for (int i = 0; i < 2; i++) {
        const int row = bm + wm * 32 + i * 16 + g;
#pragma unroll
        for (int j = 0; j < 8; j++) {
            const int col = bn + wn * 64 + j * 8 + tg * 2;
            const float b0 = bias[col], b1 = bias[col + 1];
            float v00 = fa[i][j][0] + b0, v01 = fa[i][j][1] + b1;
            float v10 = fa[i][j][2] + b0, v11 = fa[i][j][3] + b1;
            if (SPLIT) {
                __nv_bfloat16 h00 = __float2bfloat16_rn(v00);
                __nv_bfloat16 h01 = __float2bfloat16_rn(v01);
                __nv_bfloat16 h10 = __float2bfloat16_rn(v10);
                __nv_bfloat16 h11 = __float2bfloat16_rn(v11);
                const size_t o0 = (size_t)row * N + col;
                const size_t o1 = (size_t)(row + 8) * N + col;
                *(uint32_t*)(args.Ch[z] + o0) =
                    (uint32_t)*(uint16_t*)&h00 | ((uint32_t)*(uint16_t*)&h01 << 16);
                *(uint32_t*)(args.Ch[z] + o1) =
                    (uint32_t)*(uint16_t*)&h10 | ((uint32_t)*(uint16_t*)&h11 << 16);
                *(uint32_t*)(args.Cl[z] + o0) = pack2bf(v00 - __bfloat162float(h00),
                                                        v01 - __bfloat162float(h01));
                *(uint32_t*)(args.Cl[z] + o1) = pack2bf(v10 - __bfloat162float(h10),
                                                        v11 - __bfloat162float(h11));
            } else {
                float2 a2 = {v00, v01}, b2 = {v10, v11};
                *(float2*)&args.Cf[z][(size_t)row * N + col] = a2;
                *(float2*)&args.Cf[z][(size_t)(row + 8) * N + col] = b2;
            }
        }
    }
}

// ---------------------------------------------------------------------------
// mma flash attention, R11: 64-row q-tiles, 128 threads, 4 warps,
// __launch_bounds__(128,4) -> 4 CTAs/SM, 4 independent barrier domains.
// cp.async pipelined K (2-stage) / V, ldmatrix(+trans) frag loads,
// XOR-swizzled smem, 48KB static.
// ---------------------------------------------------------------------------
__global__ __launch_bounds__(128, 4) void flash_attn_mma(
    const __nv_bfloat16* __restrict__ Qh, const __nv_bfloat16* __restrict__ Ql,
    const __nv_bfloat16* __restrict__ Kh, const __nv_bfloat16* __restrict__ Kl,
    const __nv_bfloat16* __restrict__ Vh, const __nv_bfloat16* __restrict__ Vl,
    const float* __restrict__ SW,
    __nv_bfloat16* __restrict__ ctx_h, __nv_bfloat16* __restrict__ ctx_l)
{
    __shared__ __nv_bfloat16 sK[2][2][64 * 64];  // [stage][hi/lo] 32 KB
    __shared__ __nv_bfloat16 sV[2][64 * 64];     // [hi/lo]        16 KB

    const int qt = blockIdx.x, h = blockIdx.y, b = blockIdx.z;
    const int tid = threadIdx.x, w = tid >> 5, lane = tid & 31;
    const int g = lane >> 2, tg = lane & 3;
    const int q0 = qt * 64, rw = q0 + w * 16;
    const float scale = 0.125f;

    // Q fragments resident in registers
    uint32_t aq[2][4][4];
    {
        const size_t base = ((size_t)b * Ssz) * Dsz + (size_t)h * DKsz;
#pragma unroll
        for (int t = 0; t < 4; t++) {
            const int col = t * 16 + tg * 2;
            const size_t r0 = base + (size_t)(rw + g) * Dsz + col;
            const size_t r1 = base + (size_t)(rw + g + 8) * Dsz + col;
            aq[0][t][0] = *(const uint32_t*)(Qh + r0);
            aq[0][t][1] = *(const uint32_t*)(Qh + r1);
            aq[0][t][2] = *(const uint32_t*)(Qh + r0 + 8);
            aq[0][t][3] = *(const uint32_t*)(Qh + r1 + 8);
            aq[1][t][0] = *(const uint32_t*)(Ql + r0);
            aq[1][t][1] = *(const uint32_t*)(Ql + r1);
            aq[1][t][2] = *(const uint32_t*)(Ql + r0 + 8);
            aq[1][t][3] = *(const uint32_t*)(Ql + r1 + 8);
        }
    }

    // cp.async store mapping: 128 threads fill 64 rows x 8 chunks (hi+lo):
    // row = tid>>1, chunks (tid&1)*4 .. +3 -> 4 cp16 per array per buffer
    const int lrow = tid >> 1;
    const int lc0 = (tid & 1) * 4;
    uint32_t sd[4];
#pragma unroll
    for (int c = 0; c < 4; c++)
        sd[c] = (uint32_t)(lrow * 128 + (((lc0 + c) ^ (lrow & 7)) << 4));
    const uint32_t bK = (uint32_t)__cvta_generic_to_shared(&sK[0][0][0]);
    const uint32_t bV = (uint32_t)__cvta_generic_to_shared(&sV[0][0]);
    const size_t gbase = ((size_t)b * Ssz) * Dsz + (size_t)h * DKsz;

    // ldmatrix per-lane address components
    const int r7 = lane & 7, grp = lane >> 3;
    const int krow_off = ((grp >> 1) << 3) + r7;
    const int kchk_sel = grp & 1;
    const int vrow_off = ((grp & 1) << 3) + r7;
    const int vchk_sel = grp >> 1;

    const int i0 = rw + g, i1 = rw + g + 8;
    float m0 = -CUDART_INF_F, m1 = -CUDART_INF_F, l0 = 0.f, l1 = 0.f;
    float o[8][4];
#pragma unroll
    for (int d = 0; d < 8; d++)
#pragma unroll
        for (int u = 0; u < 4; u++) o[d][u] = 0.f;

    const int nkt = qt + 1;

    // prologue: K(0) -> stage 0
    {
        const size_t gk = gbase + (size_t)lrow * Dsz + lc0 * 8;
#pragma unroll
        for (int c = 0; c < 4; c++) {
            cp_async16(bK + sd[c], Kh + gk + c * 8);
            cp_async16(bK + 8192 + sd[c], Kl + gk + c * 8);
        }
    }
    CP_COMMIT();

    int s = 0;
    for (int kt = 0; kt < nkt; kt++) {
        const int k0 = kt * 64;
        __syncthreads();   // sV free (prev PV done); sK[s^1] free (prev S done)

        // issue V(kt) [group A]
        {
            const size_t gv = gbase + (size_t)(k0 + lrow) * Dsz + lc0 * 8;
#pragma unroll
            for (int c = 0; c < 4; c++) {
                cp_async16(bV + sd[c], Vh + gv + c * 8);
                cp_async16(bV + 8192 + sd[c], Vl + gv + c * 8);
            }
        }
        CP_COMMIT();
        // issue K(kt+1) into other stage [group B]
        if (kt + 1 < nkt) {
            const uint32_t so = bK + (uint32_t)(s ^ 1) * 16384;
            const size_t gk = gbase + (size_t)(k0 + 64 + lrow) * Dsz + lc0 * 8;
#pragma unroll
            for (int c = 0; c < 4; c++) {
                cp_async16(so + sd[c], Kh + gk + c * 8);
                cp_async16(so + 8192 + sd[c], Kl + gk + c * 8);
            }
        }
        CP_COMMIT();

        CP_WAIT2();        // K(kt) ready
        __syncthreads();

        const bool active = (k0 <= rw + 14);
        float sf[8][4];
        float mn0 = m0, mn1 = m1, corr0 = 1.f, corr1 = 1.f;

        if (active) {
            const uint32_t sKh = bK + (uint32_t)s * 16384;
            const uint32_t sKl = sKh + 8192;

#pragma unroll
            for (int j = 0; j < 8; j++)
#pragma unroll
                for (int u = 0; u < 4; u++) sf[j][u] = 0.f;

#pragma unroll
            for (int t = 0; t < 4; t++) {
                const int kc = 2 * t + kchk_sel;
#pragma unroll
                for (int jp = 0; jp < 4; jp++) {
                    const int row = jp * 16 + krow_off;
                    const uint32_t off =
                        (uint32_t)(row * 128 + ((kc ^ (row & 7)) << 4));
                    uint32_t kh[4], kl[4];
                    ldsm_x4(kh[0], kh[1], kh[2], kh[3], sKh + off);
                    ldsm_x4(kl[0], kl[1], kl[2], kl[3], sKl + off);
                    MMA16816(sf[2 * jp],     aq[0][t], kh[0], kh[1]);
                    MMA16816(sf[2 * jp],     aq[1][t], kh[0], kh[1]);
                    MMA16816(sf[2 * jp],     aq[0][t], kl[0], kl[1]);
                    MMA16816(sf[2 * jp + 1], aq[0][t], kh[2], kh[3]);
                    MMA16816(sf[2 * jp + 1], aq[1][t], kh[2], kh[3]);
                    MMA16816(sf[2 * jp + 1], aq[0][t], kl[2], kl[3]);
                }
            }

            const float* sw0 = SW + ((size_t)h * Ssz + i0) * Ssz + k0;
            const float* sw1 = SW + ((size_t)h * Ssz + i1) * Ssz + k0;
            const bool needmask = (k0 + 63 >= i0);
#pragma unroll
            for (int j = 0; j < 8; j++) {
                const int c = j * 8 + tg * 2;
                const float2 w0 = *(const float2*)(sw0 + c);
                const float2 w1 = *(const float2*)(sw1 + c);
                sf[j][0] = sf[j][0] * scale + w0.x;
                sf[j][1] = sf[j][1] * scale + w0.y;
                sf[j][2] = sf[j][2] * scale + w1.x;
                sf[j][3] = sf[j][3] * scale + w1.y;
                if (needmask) {
                    const int gc = k0 + c;
                    if (gc     >= i0) sf[j][0] = -CUDART_INF_F;
                    if (gc + 1 >= i0) sf[j][1] = -CUDART_INF_F;
                    if (gc     >= i1) sf[j][2] = -CUDART_INF_F;
                    if (gc + 1 >= i1) sf[j][3] = -CUDART_INF_F;
                }
            }

            float r0m = -CUDART_INF_F, r1m = -CUDART_INF_F;
#pragma unroll
            for (int j = 0; j < 8; j++) {
                r0m = fmaxf(r0m, fmaxf(sf[j][0], sf[j][1]));
                r1m = fmaxf(r1m, fmaxf(sf[j][2], sf[j][3]));
            }
            r0m = fmaxf(r0m, __shfl_xor_sync(0xffffffffu, r0m, 1));
            r0m = fmaxf(r0m, __shfl_xor_sync(0xffffffffu, r0m, 2));
            r1m = fmaxf(r1m, __shfl_xor_sync(0xffffffffu, r1m, 1));
            r1m = fmaxf(r1m, __shfl_xor_sync(0xffffffffu, r1m, 2));

            mn0 = fmaxf(m0, r0m); mn1 = fmaxf(m1, r1m);
            corr0 = (mn0 == -CUDART_INF_F) ? 0.f : __expf(m0 - mn0);
            corr1 = (mn1 == -CUDART_INF_F) ? 0.f : __expf(m1 - mn1);
#pragma unroll
            for (int d = 0; d < 8; d++) {
                o[d][0] *= corr0; o[d][1] *= corr0;
                o[d][2] *= corr1; o[d][3] *= corr1;
            }
        }

        CP_WAIT1();        // V(kt) ready; K(kt+1) may remain in flight
        __syncthreads();

        if (active) {
            float rs0 = 0.f, rs1 = 0.f;
#pragma unroll
            for (int t = 0; t < 4; t++) {
                float pv[2][4];
#pragma unroll
                for (int u = 0; u < 2; u++) {
                    const int j = 2 * t + u;
#pragma unroll
                    for (int r = 0; r < 4; r++) {
                        const float e = sf[j][r];
                        const float mm = (r < 2) ? mn0 : mn1;
                        float p = (e == -CUDART_INF_F) ? 0.f : __expf(e - mm);
                        pv[u][r] = p;
                        if (r < 2) rs0 += p; else rs1 += p;
                    }
                }
                uint32_t ph4[4], pl4[4];
                {
                    float lo[2][4];
#pragma unroll
                    for (int u = 0; u < 2; u++)
#pragma unroll
                        for (int r = 0; r < 4; r++) {
                            __nv_bfloat16 hb = __float2bfloat16_rn(pv[u][r]);
                            lo[u][r] = pv[u][r] - __bfloat162float(hb);
                        }
                    ph4[0] = pack2bf(pv[0][0], pv[0][1]);
                    ph4[1] = pack2bf(pv[0][2], pv[0][3]);
                    ph4[2] = pack2bf(pv[1][0], pv[1][1]);
                    ph4[3] = pack2bf(pv[1][2], pv[1][3]);
                    pl4[0] = pack2bf(lo[0][0], lo[0][1]);
                    pl4[1] = pack2bf(lo[0][2], lo[0][3]);
                    pl4[2] = pack2bf(lo[1][0], lo[1][1]);
                    pl4[3] = pack2bf(lo[1][2], lo[1][3]);
                }
                const int row = t * 16 + vrow_off;
#pragma unroll
                for (int dp = 0; dp < 4; dp++) {
                    const int vc = 2 * dp + vchk_sel;
                    const uint32_t off =
                        (uint32_t)(row * 128 + ((vc ^ (row & 7)) << 4));
                    uint32_t vh[4], vl[4];
                    ldsm_x4t(vh[0], vh[1], vh[2], vh[3], bV + off);
                    ldsm_x4t(vl[0], vl[1], vl[2], vl[3], bV + 8192 + off);
                    MMA16816(o[2 * dp],     ph4, vh[0], vh[1]);
                    MMA16816(o[2 * dp],     pl4, vh[0], vh[1]);
                    MMA16816(o[2 * dp],     ph4, vl[0], vl[1]);
                    MMA16816(o[2 * dp + 1], ph4, vh[2], vh[3]);
                    MMA16816(o[2 * dp + 1], pl4, vh[2], vh[3]);
                    MMA16816(o[2 * dp + 1], ph4, vl[2], vl[3]);
                }
            }
            rs0 += __shfl_xor_sync(0xffffffffu, rs0, 1);
            rs0 += __shfl_xor_sync(0xffffffffu, rs0, 2);
            rs1 += __shfl_xor_sync(0xffffffffu, rs1, 1);
            rs1 += __shfl_xor_sync(0xffffffffu, rs1, 2);
            l0 = l0 * corr0 + rs0;
            l1 = l1 * corr1 + rs1;
            m0 = mn0; m1 = mn1;
        }
        s ^= 1;
    }

    const float inv0 = (l0 > 0.f) ? (1.f / l0) : 0.f;
    const float inv1 = (l1 > 0.f) ? (1.f / l1) : 0.f;
    const size_t ob = ((size_t)b * Ssz) * Dsz + (size_t)h * DKsz;
#pragma unroll
    for (int d = 0; d < 8; d++) {
        const int col = d * 8 + tg * 2;
        float v00 = o[d][0] * inv0, v01 = o[d][1] * inv0;
        float v10 = o[d][2] * inv1, v11 = o[d][3] * inv1;
        __nv_bfloat16 h00 = __float2bfloat16_rn(v00);
        __nv_bfloat16 h01 = __float2bfloat16_rn(v01);
        __nv_bfloat16 h10 = __float2bfloat16_rn(v10);
        __nv_bfloat16 h11 = __float2bfloat16_rn(v11);
        const size_t o0 = ob + (size_t)i0 * Dsz + col;
        const size_t o1 = ob + (size_t)i1 * Dsz + col;
        *(uint32_t*)(ctx_h + o0) =
            (uint32_t)*(uint16_t*)&h00 | ((uint32_t)*(uint16_t*)&h01 << 16);
        *(uint32_t*)(ctx_h + o1) =
            (uint32_t)*(uint16_t*)&h10 | ((uint32_t)*(uint16_t*)&h11 << 16);
        *(uint32_t*)(ctx_l + o0) = pack2bf(v00 - __bfloat162float(h00),
                                           v01 - __bfloat162float(h01));
        *(uint32_t*)(ctx_l + o1) = pack2bf(v10 - __bfloat162float(h10),
                                           v11 - __bfloat162float(h11));
    }
}

// ---------------------------------------------------------------------------
__global__ __launch_bounds__(256) void residual_ln(
    const float* __restrict__ x0, const float* __restrict__ y,
    const float* __restrict__ gamma, const float* __restrict__ beta,
    float* __restrict__ out)
{
    const int row = blockIdx.x;
    const float* a = x0 + (size_t)row * Dsz;
    const float* c = y  + (size_t)row * Dsz;
    const int tid = threadIdx.x;

    float v[4];
    float sum = 0.f, sumsq = 0.f;
#pragma unroll
    for (int u = 0; u < 4; u++) {
        int idx = tid + u * 256;
        float t = a[idx] + c[idx];
        v[u] = t;
        sum += t;
        sumsq += t * t;
    }
#pragma unroll
    for (int off = 16; off; off >>= 1) {
        sum   += __shfl_xor_sync(0xffffffffu, sum, off);
        sumsq += __shfl_xor_sync(0xffffffffu, sumsq, off);
    }
    __shared__ float s1[8], s2[8];
    if ((tid & 31) == 0) { s1[tid >> 5] = sum; s2[tid >> 5] = sumsq; }
    __syncthreads();
    if (tid < 32) {
        sum   = (tid < 8) ? s1[tid] : 0.f;
        sumsq = (tid < 8) ? s2[tid] : 0.f;
#pragma unroll
        for (int off = 4; off; off >>= 1) {
            sum   += __shfl_xor_sync(0xffffffffu, sum, off);
            sumsq += __shfl_xor_sync(0xffffffffu, sumsq, off);
        }
        if (tid == 0) { s1[0] = sum; s2[0] = sumsq; }
    }
    __syncthreads();
    const float mu   = s1[0] * (1.f / Dsz);
    const float var  = s2[0] * (1.f / Dsz) - mu * mu;
    const float rstd = rsqrtf(var + 1e-5f);

    float* op = out + (size_t)row * Dsz;
#pragma unroll
    for (int u = 0; u < 4; u++) {
        int idx = tid + u * 256;
        op[idx] = (v[u] - mu) * rstd * gamma[idx] + beta[idx];
    }
}

// ---------------------------------------------------------------------------
extern "C" void kernel_launch(void* const* d_in, const int* in_sizes, int n_in,
                              void* d_out, int out_size)
{
    const float* query  = (const float*)d_in[0];
    const float* key    = (const float*)d_in[1];
    const float* values = (const float*)d_in[2];
    // d_in[3] = lens (unused by reference)
    const float* sw     = (const float*)d_in[4];
    const float* Wq     = (const float*)d_in[5];
    const float* bq     = (const float*)d_in[6];
    const float* Wv     = (const float*)d_in[7];
    const float* bv     = (const float*)d_in[8];
    const float* Wo     = (const float*)d_in[9];
    const float* bo     = (const float*)d_in[10];
    const float* gamma  = (const float*)d_in[11];
    const float* beta   = (const float*)d_in[12];
    float* out = (float*)d_out;

    __nv_bfloat16 *xqh, *xql, *xkh, *xkl, *xvh, *xvl;
    __nv_bfloat16 *Qh, *Ql, *Kh, *Kl, *Vh, *Vl, *ch, *cl;
    __nv_bfloat16 *wqh, *wql, *wvh, *wvl, *woh, *wol;
    float* Op;
    cudaGetSymbolAddress((void**)&xqh, g_xqh); cudaGetSymbolAddress((void**)&xql, g_xql);
    cudaGetSymbolAddress((void**)&xkh, g_xkh); cudaGetSymbolAddress((void**)&xkl, g_xkl);
    cudaGetSymbolAddress((void**)&xvh, g_xvh); cudaGetSymbolAddress((void**)&xvl, g_xvl);
    cudaGetSymbolAddress((void**)&Qh, g_Qh);   cudaGetSymbolAddress((void**)&Ql, g_Ql);
    cudaGetSymbolAddress((void**)&Kh, g_Kh);   cudaGetSymbolAddress((void**)&Kl, g_Kl);
    cudaGetSymbolAddress((void**)&Vh, g_Vh);   cudaGetSymbolAddress((void**)&Vl, g_Vl);
    cudaGetSymbolAddress((void**)&ch, g_ch);   cudaGetSymbolAddress((void**)&cl, g_cl);
    cudaGetSymbolAddress((void**)&wqh, g_wqh); cudaGetSymbolAddress((void**)&wql, g_wql);
    cudaGetSymbolAddress((void**)&wvh, g_wvh); cudaGetSymbolAddress((void**)&wvl, g_wvl);
    cudaGetSymbolAddress((void**)&woh, g_woh); cudaGetSymbolAddress((void**)&wol, g_wol);
    cudaGetSymbolAddress((void**)&Op, g_O);

    Split3Args sp = {};
    sp.x[0] = query;  sp.hi[0] = xqh; sp.lo[0] = xql;
    sp.x[1] = key;    sp.hi[1] = xkh; sp.lo[1] = xkl;
    sp.x[2] = values; sp.hi[2] = xvh; sp.lo[2] = xvl;
    split3<<<dim3((unsigned)(NELEM / 1024), 3), 256>>>(sp);

    TW3Args tw = {};
    tw.w[0] = Wq; tw.hi[0] = wqh; tw.lo[0] = wql;
    tw.w[1] = Wv; tw.hi[1] = wvh; tw.lo[1] = wvl;
    tw.w[2] = Wo; tw.hi[2] = woh; tw.lo[2] = wol;
    transpose_split_w3<<<dim3(32, 32, 3), dim3(32, 8)>>>(tw);

    GemmArgs qkv = {};
    qkv.Ah[0] = xqh; qkv.Al[0] = xql; qkv.Bh[0] = wqh; qkv.Bl[0] = wql;
    qkv.bias[0] = bq; qkv.Ch[0] = Qh; qkv.Cl[0] = Ql;
    qkv.Ah[1] = xkh; qkv.Al[1] = xkl; qkv.Bh[1] = wqh; qkv.Bl[1] = wql;
    qkv.bias[1] = bq; qkv.Ch[1] = Kh; qkv.Cl[1] = Kl;
    qkv.Ah[2] = xvh; qkv.Al[2] = xvl; qkv.Bh[2] = wvh; qkv.Bl[2] = wvl;
    qkv.bias[2] = bv; qkv.Ch[2] = Vh; qkv.Cl[2] = Vl;
    dim3 gq(Dsz / 128, Msz / 128, 3);
    gemm_pipe<true><<<gq, 256>>>(qkv, Msz, Dsz, Dsz);

    flash_attn_mma<<<dim3(Ssz / 64, Hsz, Bsz), 128>>>(Qh, Ql, Kh, Kl, Vh, Vl,
                                                      sw, ch, cl);

    GemmArgs og = {};
    og.Ah[0] = ch; og.Al[0] = cl; og.Bh[0] = woh; og.Bl[0] = wol;
    og.bias[0] = bo; og.Cf[0] = Op;
    dim3 go(Dsz / 128, Msz / 128, 1);
    gemm_pipe<false><<<go, 256>>>(og, Msz, Dsz, Dsz);

    residual_ln<<<Msz, 256>>>(query, Op, gamma, beta, out);
}